// round 8
// baseline (speedup 1.0000x reference)
#include <cuda_runtime.h>
#include <cstdint>

#define NBATCH 4
#define SEQ    4096
#define DIM    128
#define MTOT   (NBATCH*SEQ)
#define QT     64
#define KT     192
#define CK     48

// pre-split packed bf16x2 operands (hi/lo) in global memory
__device__ uint32_t g_xh[MTOT*64], g_xl[MTOT*64];          // x, A-layout [row][kp]
__device__ uint32_t g_qh[MTOT*64], g_ql[MTOT*64];          // q
__device__ uint32_t g_kh[MTOT*64], g_kl[MTOT*64];          // k
__device__ float    g_v [MTOT*DIM];                        // v fp32 (for vsum+repack)
__device__ uint32_t g_vh[(MTOT/2)*DIM], g_vl[(MTOT/2)*DIM];// v, B-layout [keypair][dim]
__device__ uint32_t g_ah[MTOT*64], g_al[MTOT*64];          // agg, A-layout
__device__ uint32_t g_wbh[(3*64+128)*DIM], g_wbl[(3*64+128)*DIM]; // Wq|Wk|Wv|Wu, B-layout [kp][n]
__device__ float g_vsum[NBATCH*DIM];
__device__ float g_vsum_p[NBATCH*16*DIM];

// ---------------------------------------------------------------------------
__device__ __forceinline__ uint32_t bfpack(float x0, float x1) {
    uint32_t r;
    asm("cvt.rn.bf16x2.f32 %0, %1, %2;" : "=r"(r) : "f"(x1), "f"(x0));
    return r;
}
__device__ __forceinline__ void bfsplit2(float x0, float x1, uint32_t& h, uint32_t& l) {
    h = bfpack(x0, x1);
    float h0 = __uint_as_float(h << 16);
    float h1 = __uint_as_float(h & 0xffff0000u);
    l = bfpack(x0 - h0, x1 - h1);
}
__device__ __forceinline__ void mma_bf16(float* c, const uint32_t* a,
                                         uint32_t b0, uint32_t b1) {
    asm volatile(
        "mma.sync.aligned.m16n8k16.row.col.f32.bf16.bf16.f32 "
        "{%0,%1,%2,%3}, {%4,%5,%6,%7}, {%8,%9}, {%0,%1,%2,%3};"
        : "+f"(c[0]), "+f"(c[1]), "+f"(c[2]), "+f"(c[3])
        : "r"(a[0]), "r"(a[1]), "r"(a[2]), "r"(a[3]), "r"(b0), "r"(b1));
}

// ---------------------------------------------------------------------------
// Prep: split x (A-layout) and all weights (B-layout) once.
// ---------------------------------------------------------------------------
__global__ __launch_bounds__(256)
void prep_split(const float* __restrict__ x,  const float* __restrict__ Wq,
                const float* __restrict__ Wk, const float* __restrict__ Wv,
                const float* __restrict__ Wu)
{
    const int bid = blockIdx.x, tid = threadIdx.x;
    if (bid < 4096) {
        int idx = bid*256 + tid;               // row*64 + kp
        int row = idx >> 6, kp = idx & 63;
        float2 v = *(const float2*)(x + (size_t)row*DIM + 2*kp);
        uint32_t h, l; bfsplit2(v.x, v.y, h, l);
        g_xh[idx] = h; g_xl[idx] = l;
    } else {
        int o = (bid - 4096)*256 + tid;        // 0..40959
        const float* W; int ofs, oo;
        if (o < 8192)        { W = Wq; ofs = 0;        oo = o; }
        else if (o < 16384)  { W = Wk; ofs = 64*128;   oo = o - 8192; }
        else if (o < 24576)  { W = Wv; ofs = 128*128;  oo = o - 16384; }
        else                 { W = Wu; ofs = 192*128;  oo = o - 24576; }
        int kp = oo >> 7, n = oo & 127;
        uint32_t h, l;
        bfsplit2(W[(size_t)(2*kp)*DIM + n], W[(size_t)(2*kp+1)*DIM + n], h, l);
        g_wbh[ofs + kp*128 + n] = h; g_wbl[ofs + kp*128 + n] = l;
    }
}

// ---------------------------------------------------------------------------
// GEMM core: 128x128 tile, K in 32-kp chunks, pure-copy staging.
// ---------------------------------------------------------------------------
#define GA_STR 36
#define GB_STR 136
#define GEMM_SMEM ((2*128*GA_STR + 2*32*GB_STR)*4)   // 71680 B

struct GemmB {
    uint32_t *Ah, *Al, *Bh, *Bl;

    __device__ void stage_A(const uint32_t* __restrict__ sh, const uint32_t* __restrict__ sl,
                            int m0, int kcp, int tid) {
#pragma unroll
        for (int t = 0; t < 4; ++t) {
            int idx = tid + t*256;
            int row = idx >> 3, q4 = (idx & 7)*4;
            *(uint4*)&Ah[row*GA_STR + q4] = *(const uint4*)&sh[(size_t)(m0+row)*64 + kcp + q4];
            *(uint4*)&Al[row*GA_STR + q4] = *(const uint4*)&sl[(size_t)(m0+row)*64 + kcp + q4];
        }
    }
    __device__ void stage_B(int kpo, int tid) {
#pragma unroll
        for (int t = 0; t < 4; ++t) {
            int idx = tid + t*256;
            int kp = idx >> 5, c4 = (idx & 31)*4;
            *(uint4*)&Bh[kp*GB_STR + c4] = *(const uint4*)&g_wbh[(size_t)(kpo+kp)*128 + c4];
            *(uint4*)&Bl[kp*GB_STR + c4] = *(const uint4*)&g_wbl[(size_t)(kpo+kp)*128 + c4];
        }
    }
    __device__ void run(float c[2][8][4], int tid) {
        const int lane = tid & 31, wid = tid >> 5;
        const int grp = lane >> 2, qd = lane & 3;
        const int wm = (wid >> 1) * 32, wn = (wid & 1) * 64;
#pragma unroll
        for (int t = 0; t < 4; ++t) {
            int kp0 = 8*t;
            uint32_t ah[2][4], al[2][4];
#pragma unroll
            for (int mi = 0; mi < 2; ++mi) {
                int r = (wm + mi*16 + grp)*GA_STR;
                ah[mi][0] = Ah[r + kp0+qd];   ah[mi][1] = Ah[r + 8*GA_STR + kp0+qd];
                ah[mi][2] = Ah[r + kp0+qd+4]; ah[mi][3] = Ah[r + 8*GA_STR + kp0+qd+4];
                al[mi][0] = Al[r + kp0+qd];   al[mi][1] = Al[r + 8*GA_STR + kp0+qd];
                al[mi][2] = Al[r + kp0+qd+4]; al[mi][3] = Al[r + 8*GA_STR + kp0+qd+4];
            }
#pragma unroll
            for (int ni = 0; ni < 8; ++ni) {
                int col = wn + ni*8 + grp;
                uint32_t bh0 = Bh[(kp0+qd)*GB_STR + col];
                uint32_t bh1 = Bh[(kp0+qd+4)*GB_STR + col];
                uint32_t bl0 = Bl[(kp0+qd)*GB_STR + col];
                uint32_t bl1 = Bl[(kp0+qd+4)*GB_STR + col];
#pragma unroll
                for (int mi = 0; mi < 2; ++mi) {
                    mma_bf16(c[mi][ni], ah[mi], bh0, bh1);
                    mma_bf16(c[mi][ni], al[mi], bh0, bh1);
                    mma_bf16(c[mi][ni], ah[mi], bl0, bl1);
                }
            }
        }
    }
};

// ---------------------------------------------------------------------------
// QKV: grid (128, 3). q/k written pre-split; v written fp32.
// ---------------------------------------------------------------------------
__global__ __launch_bounds__(256, 2)
void qkv_mma()
{
    extern __shared__ uint32_t smu[];
    GemmB g;
    g.Ah = smu;                 g.Al = g.Ah + 128*GA_STR;
    g.Bh = g.Al + 128*GA_STR;   g.Bl = g.Bh + 32*GB_STR;

    const int tid = threadIdx.x;
    const int m0 = blockIdx.x * 128;
    const int wsel = blockIdx.y;
    const int wofs_kp = wsel * 64;

    float c[2][8][4];
#pragma unroll
    for (int mi = 0; mi < 2; ++mi)
#pragma unroll
        for (int ni = 0; ni < 8; ++ni)
#pragma unroll
            for (int e = 0; e < 4; ++e) c[mi][ni][e] = 0.f;

#pragma unroll 1
    for (int kcp = 0; kcp < 64; kcp += 32) {
        g.stage_A(g_xh, g_xl, m0, kcp, tid);
        g.stage_B(wofs_kp + kcp, tid);
        __syncthreads();
        g.run(c, tid);
        if (kcp == 0) __syncthreads();
    }

    const int lane = tid & 31, wid = tid >> 5;
    const int grp = lane >> 2, qd = lane & 3;
    const int wm = (wid >> 1) * 32, wn = (wid & 1) * 64;

    if (wsel < 2) {
        uint32_t* oh = (wsel == 0) ? g_qh : g_kh;
        uint32_t* ol = (wsel == 0) ? g_ql : g_kl;
#pragma unroll
        for (int mi = 0; mi < 2; ++mi)
#pragma unroll
            for (int ni = 0; ni < 8; ++ni) {
                size_t r0 = (size_t)(m0 + wm + mi*16 + grp);
                int cp = (wn >> 1) + ni*4 + qd;
                uint32_t h, l;
                bfsplit2(c[mi][ni][0], c[mi][ni][1], h, l);
                oh[r0*64 + cp] = h; ol[r0*64 + cp] = l;
                bfsplit2(c[mi][ni][2], c[mi][ni][3], h, l);
                oh[(r0+8)*64 + cp] = h; ol[(r0+8)*64 + cp] = l;
            }
    } else {
#pragma unroll
        for (int mi = 0; mi < 2; ++mi)
#pragma unroll
            for (int ni = 0; ni < 8; ++ni) {
                size_t r0 = (size_t)(m0 + wm + mi*16 + grp);
                int col = wn + ni*8 + 2*qd;
                *(float2*)(g_v + r0*DIM + col)     = make_float2(c[mi][ni][0], c[mi][ni][1]);
                *(float2*)(g_v + (r0+8)*DIM + col) = make_float2(c[mi][ni][2], c[mi][ni][3]);
            }
    }
}

// ---------------------------------------------------------------------------
// vsum partials + V repack into pre-split pair-major layout.
// ---------------------------------------------------------------------------
__global__ __launch_bounds__(128)
void vsum_part()
{
    const int b = blockIdx.x, c = blockIdx.y;
    const int d = threadIdx.x;
    const size_t base = (size_t)b*SEQ + c*256;
    const float* vp = g_v + base*DIM + d;
    float s0 = 0.f, s1 = 0.f;
    for (int m = 0; m < 256; m += 2) {
        float a = vp[(size_t)m*DIM];
        float e = vp[(size_t)(m+1)*DIM];
        s0 += a; s1 += e;
        uint32_t h, l; bfsplit2(a, e, h, l);
        size_t pj = (base + m) >> 1;
        g_vh[pj*DIM + d] = h;
        g_vl[pj*DIM + d] = l;
    }
    g_vsum_p[(b*16 + c)*DIM + d] = s0 + s1;
}
__global__ __launch_bounds__(128)
void vsum_red()
{
    const int b = blockIdx.x, d = threadIdx.x;
    float s = 0.f;
#pragma unroll
    for (int c = 0; c < 16; ++c) s += g_vsum_p[(b*16+c)*DIM + d];
    g_vsum[b*DIM + d] = s;
}

// ---------------------------------------------------------------------------
// Attention: pure-copy staging of pre-split Q/K/V, band-skip in S phase.
// ---------------------------------------------------------------------------
#define AQ_STR 68
#define AK_STR 68
#define AV_STR 136
#define AP_STR 196
#define Q_WORDS  (QT*AQ_STR)
#define KV_WORDS (2*CK*AK_STR)
#define P_WORDS  (QT*AP_STR)
#define ATTN_SMEM ((2*Q_WORDS + KV_WORDS + P_WORDS)*4 + (KT+QT)*4)

__global__ __launch_bounds__(256, 2)
void attn_mma(const int* __restrict__ mask)
{
    extern __shared__ uint32_t smu[];
    uint32_t* Qh = smu;
    uint32_t* Ql = Qh + Q_WORDS;
    uint32_t* KV = Ql + Q_WORDS;
    float*    Ps = (float*)(KV + KV_WORDS);
    int*     msk = (int*)(Ps + P_WORDS);
    int*     qmk = msk + KT;

    uint32_t* Kh = KV;  uint32_t* Kl = KV + CK*AK_STR;
    uint32_t* Vh = KV;  uint32_t* Vl = KV + 24*AV_STR;

    const int tid = threadIdx.x;
    const int b  = blockIdx.y;
    const int q0 = blockIdx.x * QT;
    const int kbase = q0 - 64;

    if (tid < KT) {
        int j = kbase + tid;
        msk[tid] = (j >= 0 && j < SEQ) ? mask[b*SEQ + j] : 0;
    }
    if (tid < QT) qmk[tid] = mask[b*SEQ + q0 + tid];

    // stage Q (pure copy)
#pragma unroll
    for (int t = 0; t < 4; ++t) {
        int idx = tid + t*256;
        int row = idx >> 4, q4 = (idx & 15)*4;
        *(uint4*)&Qh[row*AQ_STR + q4] = *(const uint4*)&g_qh[((size_t)b*SEQ + q0 + row)*64 + q4];
        *(uint4*)&Ql[row*AQ_STR + q4] = *(const uint4*)&g_ql[((size_t)b*SEQ + q0 + row)*64 + q4];
    }
    // stage K chunk 0
#pragma unroll
    for (int t = 0; t < 3; ++t) {
        int idx = tid + t*256;
        int row = idx >> 4, q4 = (idx & 15)*4;
        int j = kbase + row;
        uint4 h = make_uint4(0,0,0,0), l = make_uint4(0,0,0,0);
        if (j >= 0 && j < SEQ) {
            h = *(const uint4*)&g_kh[((size_t)b*SEQ + j)*64 + q4];
            l = *(const uint4*)&g_kl[((size_t)b*SEQ + j)*64 + q4];
        }
        *(uint4*)&Kh[row*AK_STR + q4] = h;
        *(uint4*)&Kl[row*AK_STR + q4] = l;
    }
    __syncthreads();

    const int lane = tid & 31, wid = tid >> 5;
    const int grp = lane >> 2, qd = lane & 3;
    const float scale = 0.08838834764831845f;

    // ---- S = Q K^T, 4 chunks of 48 keys; warps 4(m) x 2(n), band skip ----
    {
        const int wm = (wid & 3) * 16;
        const int wn = (wid >> 2) * 24;
#pragma unroll 1
        for (int c = 0; c < 4; ++c) {
            float cs[3][4];
#pragma unroll
            for (int ni = 0; ni < 3; ++ni)
#pragma unroll
                for (int e = 0; e < 4; ++e) cs[ni][e] = 0.f;

            bool skip = (c*CK + wn + 24 <= wm) || (c*CK + wn > wm + 143);
            if (!skip) {
#pragma unroll
                for (int t = 0; t < 8; ++t) {
                    int kp0 = 8*t;
                    uint32_t ah[4], al[4];
                    int r = (wm + grp)*AQ_STR;
                    ah[0] = Qh[r + kp0+qd];   ah[1] = Qh[r + 8*AQ_STR + kp0+qd];
                    ah[2] = Qh[r + kp0+qd+4]; ah[3] = Qh[r + 8*AQ_STR + kp0+qd+4];
                    al[0] = Ql[r + kp0+qd];   al[1] = Ql[r + 8*AQ_STR + kp0+qd];
                    al[2] = Ql[r + kp0+qd+4]; al[3] = Ql[r + 8*AQ_STR + kp0+qd+4];
#pragma unroll
                    for (int ni = 0; ni < 3; ++ni) {
                        int col = (wn + ni*8 + grp)*AK_STR;
                        uint32_t bh0 = Kh[col + kp0+qd],  bh1 = Kh[col + kp0+qd+4];
                        uint32_t bl0 = Kl[col + kp0+qd],  bl1 = Kl[col + kp0+qd+4];
                        mma_bf16(cs[ni], ah, bh0, bh1);
                        mma_bf16(cs[ni], al, bh0, bh1);
                        mma_bf16(cs[ni], ah, bl0, bl1);
                    }
                }
            }
#pragma unroll
            for (int ni = 0; ni < 3; ++ni) {
#pragma unroll
                for (int e = 0; e < 4; ++e) {
                    int qi = wm + grp + (e >> 1)*8;
                    int jg = c*CK + wn + ni*8 + 2*qd + (e & 1);
                    bool valid = msk[jg] && (jg >= qi) && (jg <= qi + 128);
                    Ps[qi*AP_STR + jg] = valid ? cs[ni][e]*scale : -1e9f;
                }
            }
            __syncthreads();
            if (c < 3) {
#pragma unroll
                for (int t = 0; t < 3; ++t) {
                    int idx = tid + t*256;
                    int row = idx >> 4, q4 = (idx & 15)*4;
                    int j = kbase + (c+1)*CK + row;
                    uint4 h = make_uint4(0,0,0,0), l = make_uint4(0,0,0,0);
                    if (j >= 0 && j < SEQ) {
                        h = *(const uint4*)&g_kh[((size_t)b*SEQ + j)*64 + q4];
                        l = *(const uint4*)&g_kl[((size_t)b*SEQ + j)*64 + q4];
                    }
                    *(uint4*)&Kh[row*AK_STR + q4] = h;
                    *(uint4*)&Kl[row*AK_STR + q4] = l;
                }
                __syncthreads();
            }
        }
    }

    // stage V chunk 0 (pure copy into K's buffer)
#pragma unroll
    for (int t = 0; t < 3; ++t) {
        int idx = tid + t*256;
        int kp = idx >> 5, c4 = (idx & 31)*4;
        int j0 = kbase + 2*kp;
        uint4 h = make_uint4(0,0,0,0), l = make_uint4(0,0,0,0);
        if (j0 >= 0 && j0 < SEQ) {
            size_t pj = ((size_t)b*SEQ + j0) >> 1;
            h = *(const uint4*)&g_vh[pj*DIM + c4];
            l = *(const uint4*)&g_vl[pj*DIM + c4];
        }
        *(uint4*)&Vh[kp*AV_STR + c4] = h;
        *(uint4*)&Vl[kp*AV_STR + c4] = l;
    }

    // softmax: 4 threads per row
    {
        int qi = tid >> 2, lg = tid & 3;
        float mx = -3.4e38f;
        for (int j = lg; j < KT; j += 4) mx = fmaxf(mx, Ps[qi*AP_STR + j]);
        mx = fmaxf(mx, __shfl_xor_sync(0xffffffffu, mx, 1));
        mx = fmaxf(mx, __shfl_xor_sync(0xffffffffu, mx, 2));
        float s = 0.f;
        for (int j = lg; j < KT; j += 4) {
            float e = __expf(Ps[qi*AP_STR + j] - mx);
            Ps[qi*AP_STR + j] = e;
            s += e;
        }
        s += __shfl_xor_sync(0xffffffffu, s, 1);
        s += __shfl_xor_sync(0xffffffffu, s, 2);
        float inv = 1.f / s;
        for (int j = lg; j < KT; j += 4) Ps[qi*AP_STR + j] *= inv;
    }
    __syncthreads();

    // ---- agg = P V, 4 chunks of 24 key-pairs; warps 2(m) x 4(n) ----
    {
        const int wm = (wid & 1) * 32;
        const int wn = (wid >> 1) * 32;
        float co[2][4][4];
#pragma unroll
        for (int mi = 0; mi < 2; ++mi)
#pragma unroll
            for (int ni = 0; ni < 4; ++ni)
#pragma unroll
                for (int e = 0; e < 4; ++e) co[mi][ni][e] = 0.f;

#pragma unroll 1
        for (int c = 0; c < 4; ++c) {
#pragma unroll
            for (int t = 0; t < 3; ++t) {
                int ksub = 8*t;
                uint32_t ah[2][4], al[2][4];
#pragma unroll
                for (int mi = 0; mi < 2; ++mi) {
                    const float* ap = &Ps[(wm + mi*16 + grp)*AP_STR + 2*(c*24 + ksub + qd)];
                    float2 p0 = *(const float2*)(ap);
                    float2 p1 = *(const float2*)(ap + 8*AP_STR);
                    float2 p2 = *(const float2*)(ap + 8);
                    float2 p3 = *(const float2*)(ap + 8*AP_STR + 8);
                    bfsplit2(p0.x, p0.y, ah[mi][0], al[mi][0]);
                    bfsplit2(p1.x, p1.y, ah[mi][1], al[mi][1]);
                    bfsplit2(p2.x, p2.y, ah[mi][2], al[mi][2]);
                    bfsplit2(p3.x, p3.y, ah[mi][3], al[mi][3]);
                }
#pragma unroll
                for (int ni = 0; ni < 4; ++ni) {
                    int col = wn + ni*8 + grp;
                    uint32_t bh0 = Vh[(ksub+qd)*AV_STR + col];
                    uint32_t bh1 = Vh[(ksub+qd+4)*AV_STR + col];
                    uint32_t bl0 = Vl[(ksub+qd)*AV_STR + col];
                    uint32_t bl1 = Vl[(ksub+qd+4)*AV_STR + col];
#pragma unroll
                    for (int mi = 0; mi < 2; ++mi) {
                        mma_bf16(co[mi][ni], ah[mi], bh0, bh1);
                        mma_bf16(co[mi][ni], al[mi], bh0, bh1);
                        mma_bf16(co[mi][ni], ah[mi], bl0, bl1);
                    }
                }
            }
            if (c < 3) {
                __syncthreads();
#pragma unroll
                for (int t = 0; t < 3; ++t) {
                    int idx = tid + t*256;
                    int kp = idx >> 5, c4 = (idx & 31)*4;
                    int j0 = kbase + (c+1)*CK + 2*kp;
                    uint4 h = make_uint4(0,0,0,0), l = make_uint4(0,0,0,0);
                    if (j0 >= 0 && j0 < SEQ) {
                        size_t pj = ((size_t)b*SEQ + j0) >> 1;
                        h = *(const uint4*)&g_vh[pj*DIM + c4];
                        l = *(const uint4*)&g_vl[pj*DIM + c4];
                    }
                    *(uint4*)&Vh[kp*AV_STR + c4] = h;
                    *(uint4*)&Vl[kp*AV_STR + c4] = l;
                }
                __syncthreads();
            }
        }

        // epilogue: write agg pre-split; masked rows -> vsum/SEQ
#pragma unroll
        for (int mi = 0; mi < 2; ++mi)
#pragma unroll
            for (int ni = 0; ni < 4; ++ni) {
                int r0 = wm + mi*16 + grp;
                int col = wn + ni*8 + 2*qd;
#pragma unroll
                for (int half = 0; half < 2; ++half) {
                    int qi = r0 + half*8;
                    float v0 = co[mi][ni][half*2], v1 = co[mi][ni][half*2+1];
                    if (!qmk[qi]) {
                        v0 = g_vsum[b*DIM + col]     * (1.f/(float)SEQ);
                        v1 = g_vsum[b*DIM + col + 1] * (1.f/(float)SEQ);
                    }
                    uint32_t h, l; bfsplit2(v0, v1, h, l);
                    size_t row = (size_t)b*SEQ + q0 + qi;
                    g_ah[row*64 + (col>>1)] = h;
                    g_al[row*64 + (col>>1)] = l;
                }
            }
    }
}

// ---------------------------------------------------------------------------
// MLP (K=256, 4 chunks) + fused bias/ReLU/residual/LN. Pure-copy staging.
// ---------------------------------------------------------------------------
__global__ __launch_bounds__(256, 2)
void mlp_mma(const float* __restrict__ x, const float* __restrict__ bu,
             const float* __restrict__ gamma, const float* __restrict__ beta,
             float* __restrict__ out)
{
    extern __shared__ uint32_t smu[];
    GemmB g;
    g.Ah = smu;                 g.Al = g.Ah + 128*GA_STR;
    g.Bh = g.Al + 128*GA_STR;   g.Bl = g.Bh + 32*GB_STR;

    const int tid = threadIdx.x;
    const int m0 = blockIdx.x * 128;

    float c[2][8][4];
#pragma unroll
    for (int mi = 0; mi < 2; ++mi)
#pragma unroll
        for (int ni = 0; ni < 8; ++ni)
#pragma unroll
            for (int e = 0; e < 4; ++e) c[mi][ni][e] = 0.f;

#pragma unroll 1
    for (int ph = 0; ph < 2; ++ph) {
        const uint32_t* sh = ph ? g_ah : g_xh;
        const uint32_t* sl = ph ? g_al : g_xl;
#pragma unroll 1
        for (int kcp = 0; kcp < 64; kcp += 32) {
            g.stage_A(sh, sl, m0, kcp, tid);
            g.stage_B(192 + ph*64 + kcp, tid);
            __syncthreads();
            g.run(c, tid);
            __syncthreads();
        }
    }

    float* Ys = (float*)smu;  // [128][132]
    const int lane = tid & 31, wid = tid >> 5;
    const int grp = lane >> 2, qd = lane & 3;
    const int wm = (wid >> 1) * 32, wn = (wid & 1) * 64;
#pragma unroll
    for (int mi = 0; mi < 2; ++mi)
#pragma unroll
        for (int ni = 0; ni < 8; ++ni) {
            int r0 = wm + mi*16 + grp;
            int col = wn + ni*8 + 2*qd;
            float b0 = __ldg(bu + col), b1 = __ldg(bu + col + 1);
            Ys[r0*132 + col]         = fmaxf(c[mi][ni][0] + b0, 0.f);
            Ys[r0*132 + col + 1]     = fmaxf(c[mi][ni][1] + b1, 0.f);
            Ys[(r0+8)*132 + col]     = fmaxf(c[mi][ni][2] + b0, 0.f);
            Ys[(r0+8)*132 + col + 1] = fmaxf(c[mi][ni][3] + b1, 0.f);
        }
    __syncthreads();

#pragma unroll
    for (int pass = 0; pass < 2; ++pass) {
        int row = (tid >> 2) + pass*64;
        int part = tid & 3;
        const float* xr = x + (size_t)(m0 + row)*DIM + part*32;
        const float* yr = Ys + row*132 + part*32;
        float vals[32];
        float sum = 0.f, sq = 0.f;
#pragma unroll
        for (int j = 0; j < 8; ++j) {
            float4 xv = *(const float4*)(xr + j*4);
            float4 yv = *(const float4*)(yr + j*4);
            float v0 = yv.x+xv.x, v1 = yv.y+xv.y, v2 = yv.z+xv.z, v3 = yv.w+xv.w;
            vals[j*4+0]=v0; vals[j*4+1]=v1; vals[j*4+2]=v2; vals[j*4+3]=v3;
            sum += (v0+v1)+(v2+v3);
            sq  += (v0*v0+v1*v1)+(v2*v2+v3*v3);
        }
        sum += __shfl_xor_sync(0xffffffffu, sum, 1);
        sq  += __shfl_xor_sync(0xffffffffu, sq, 1);
        sum += __shfl_xor_sync(0xffffffffu, sum, 2);
        sq  += __shfl_xor_sync(0xffffffffu, sq, 2);
        float mu   = sum * (1.f/128.f);
        float var  = sq * (1.f/128.f) - mu*mu;
        float rstd = rsqrtf(var + 1e-5f);
        float* op = out + (size_t)(m0 + row)*DIM + part*32;
        const float* gp = gamma + part*32;
        const float* bp = beta + part*32;
#pragma unroll
        for (int j = 0; j < 8; ++j) {
            float4 gv = *(const float4*)(gp + j*4);
            float4 bv = *(const float4*)(bp + j*4);
            float4 o;
            o.x = gv.x*((vals[j*4+0]-mu)*rstd) + bv.x;
            o.y = gv.y*((vals[j*4+1]-mu)*rstd) + bv.y;
            o.z = gv.z*((vals[j*4+2]-mu)*rstd) + bv.z;
            o.w = gv.w*((vals[j*4+3]-mu)*rstd) + bv.w;
            *(float4*)(op + j*4) = o;
        }
    }
}

// ---------------------------------------------------------------------------
extern "C" void kernel_launch(void* const* d_in, const int* in_sizes, int n_in,
                              void* d_out, int out_size)
{
    const float* x    = (const float*)d_in[0];
    const int*   mask = (const int*)d_in[2];
    const float* Wq   = (const float*)d_in[3];
    const float* Wk   = (const float*)d_in[4];
    const float* Wv   = (const float*)d_in[5];
    const float* Wu   = (const float*)d_in[6];
    const float* bu   = (const float*)d_in[7];
    const float* gm   = (const float*)d_in[8];
    const float* bt   = (const float*)d_in[9];
    float* out = (float*)d_out;

    cudaFuncSetAttribute(qkv_mma, cudaFuncAttributeMaxDynamicSharedMemorySize, GEMM_SMEM);
    cudaFuncSetAttribute(mlp_mma, cudaFuncAttributeMaxDynamicSharedMemorySize, GEMM_SMEM);
    cudaFuncSetAttribute(attn_mma, cudaFuncAttributeMaxDynamicSharedMemorySize, ATTN_SMEM);

    prep_split<<<4096 + 160, 256>>>(x, Wq, Wk, Wv, Wu);
    qkv_mma<<<dim3(MTOT/128, 3), 256, GEMM_SMEM>>>();
    vsum_part<<<dim3(NBATCH, 16), 128>>>();
    vsum_red<<<NBATCH, 128>>>();
    attn_mma<<<dim3(SEQ/QT, NBATCH), 256, ATTN_SMEM>>>(mask);
    mlp_mma<<<MTOT/128, 256, GEMM_SMEM>>>(x, bu, gm, bt, out);
}

// round 9
// speedup vs baseline: 1.4084x; 1.4084x over previous
#include <cuda_runtime.h>
#include <cstdint>

#define NBATCH 4
#define SEQ    4096
#define DIM    128
#define MTOT   (NBATCH*SEQ)
#define QT     64
#define KT     192
#define CK     48

__device__ float g_q[MTOT*DIM];
__device__ float g_k[MTOT*DIM];
__device__ float g_v[MTOT*DIM];
__device__ float g_agg[MTOT*DIM];
__device__ float g_vsum[NBATCH*DIM];
__device__ float g_vsum_p[NBATCH*64*DIM];
__device__ uint32_t g_wbh[(3*64+128)*DIM], g_wbl[(3*64+128)*DIM]; // Wq|Wk|Wv|Wu, B-layout [kp][n]

// ---------------------------------------------------------------------------
__device__ __forceinline__ uint32_t bfpack(float x0, float x1) {
    uint32_t r;
    asm("cvt.rn.bf16x2.f32 %0, %1, %2;" : "=r"(r) : "f"(x1), "f"(x0));
    return r;
}
__device__ __forceinline__ void bfsplit2(float x0, float x1, uint32_t& h, uint32_t& l) {
    h = bfpack(x0, x1);
    float h0 = __uint_as_float(h << 16);
    float h1 = __uint_as_float(h & 0xffff0000u);
    l = bfpack(x0 - h0, x1 - h1);
}
__device__ __forceinline__ void mma_bf16(float* c, const uint32_t* a,
                                         uint32_t b0, uint32_t b1) {
    asm volatile(
        "mma.sync.aligned.m16n8k16.row.col.f32.bf16.bf16.f32 "
        "{%0,%1,%2,%3}, {%4,%5,%6,%7}, {%8,%9}, {%0,%1,%2,%3};"
        : "+f"(c[0]), "+f"(c[1]), "+f"(c[2]), "+f"(c[3])
        : "r"(a[0]), "r"(a[1]), "r"(a[2]), "r"(a[3]), "r"(b0), "r"(b1));
}

// ---------------------------------------------------------------------------
// Prep: split the 4 weight matrices once into B-layout [kp][n] hi/lo.
// 320 kp total (Wq 64 | Wk 64 | Wv 64 | Wu 128), 128 n each... n = 0..127.
// ---------------------------------------------------------------------------
__global__ __launch_bounds__(256)
void prep_w(const float* __restrict__ Wq, const float* __restrict__ Wk,
            const float* __restrict__ Wv, const float* __restrict__ Wu)
{
    int o = blockIdx.x*256 + threadIdx.x;    // 0..40959
    const float* W; int ofs, oo;
    if (o < 8192)        { W = Wq; ofs = 0;        oo = o; }
    else if (o < 16384)  { W = Wk; ofs = 64*128;   oo = o - 8192; }
    else if (o < 24576)  { W = Wv; ofs = 128*128;  oo = o - 16384; }
    else                 { W = Wu; ofs = 192*128;  oo = o - 24576; }
    int kp = oo >> 7, n = oo & 127;
    uint32_t h, l;
    bfsplit2(W[(size_t)(2*kp)*DIM + n], W[(size_t)(2*kp+1)*DIM + n], h, l);
    g_wbh[ofs + kp*128 + n] = h; g_wbl[ofs + kp*128 + n] = l;
}

// ---------------------------------------------------------------------------
// GEMM core: 128x128 tile, K in 64-elem chunks; A split at staging,
// B staged by pure copy from pre-split weights.
// ---------------------------------------------------------------------------
#define GA_STR 36
#define GB_STR 136
#define GEMM_SMEM ((2*128*GA_STR + 2*32*GB_STR)*4)   // 71680 B

struct GemmB {
    uint32_t *Ah, *Al, *Bh, *Bl;

    __device__ void stage_A(const float* __restrict__ src, int m0, int kc, int tid) {
#pragma unroll
        for (int t = 0; t < 16; ++t) {
            int idx = tid + t*256;
            int row = idx >> 5, kp = idx & 31;
            float2 v = *(const float2*)(src + (size_t)(m0+row)*DIM + kc + 2*kp);
            uint32_t h, l; bfsplit2(v.x, v.y, h, l);
            Ah[row*GA_STR + kp] = h; Al[row*GA_STR + kp] = l;
        }
    }
    __device__ void stage_B(int kpo, int tid) {
#pragma unroll
        for (int t = 0; t < 4; ++t) {
            int idx = tid + t*256;
            int kp = idx >> 5, c4 = (idx & 31)*4;
            *(uint4*)&Bh[kp*GB_STR + c4] = *(const uint4*)&g_wbh[(size_t)(kpo+kp)*128 + c4];
            *(uint4*)&Bl[kp*GB_STR + c4] = *(const uint4*)&g_wbl[(size_t)(kpo+kp)*128 + c4];
        }
    }
    __device__ void run(float c[2][8][4], int tid) {
        const int lane = tid & 31, wid = tid >> 5;
        const int grp = lane >> 2, qd = lane & 3;
        const int wm = (wid >> 1) * 32, wn = (wid & 1) * 64;
#pragma unroll
        for (int t = 0; t < 4; ++t) {
            int kp0 = 8*t;
            uint32_t ah[2][4], al[2][4];
#pragma unroll
            for (int mi = 0; mi < 2; ++mi) {
                int r = (wm + mi*16 + grp)*GA_STR;
                ah[mi][0] = Ah[r + kp0+qd];   ah[mi][1] = Ah[r + 8*GA_STR + kp0+qd];
                ah[mi][2] = Ah[r + kp0+qd+4]; ah[mi][3] = Ah[r + 8*GA_STR + kp0+qd+4];
                al[mi][0] = Al[r + kp0+qd];   al[mi][1] = Al[r + 8*GA_STR + kp0+qd];
                al[mi][2] = Al[r + kp0+qd+4]; al[mi][3] = Al[r + 8*GA_STR + kp0+qd+4];
            }
#pragma unroll
            for (int ni = 0; ni < 8; ++ni) {
                int col = wn + ni*8 + grp;
                uint32_t bh0 = Bh[(kp0+qd)*GB_STR + col];
                uint32_t bh1 = Bh[(kp0+qd+4)*GB_STR + col];
                uint32_t bl0 = Bl[(kp0+qd)*GB_STR + col];
                uint32_t bl1 = Bl[(kp0+qd+4)*GB_STR + col];
#pragma unroll
                for (int mi = 0; mi < 2; ++mi) {
                    mma_bf16(c[mi][ni], ah[mi], bh0, bh1);
                    mma_bf16(c[mi][ni], al[mi], bh0, bh1);
                    mma_bf16(c[mi][ni], ah[mi], bl0, bl1);
                }
            }
        }
    }
};

// ---------------------------------------------------------------------------
__global__ __launch_bounds__(256, 2)
void qkv_mma(const float* __restrict__ x)
{
    extern __shared__ uint32_t smu[];
    GemmB g;
    g.Ah = smu;                 g.Al = g.Ah + 128*GA_STR;
    g.Bh = g.Al + 128*GA_STR;   g.Bl = g.Bh + 32*GB_STR;

    const int tid = threadIdx.x;
    const int m0 = blockIdx.x * 128;
    const int wsel = blockIdx.y;
    float* outp = (wsel == 0) ? g_q : (wsel == 1) ? g_k : g_v;

    float c[2][8][4];
#pragma unroll
    for (int mi = 0; mi < 2; ++mi)
#pragma unroll
        for (int ni = 0; ni < 8; ++ni)
#pragma unroll
            for (int e = 0; e < 4; ++e) c[mi][ni][e] = 0.f;

#pragma unroll 1
    for (int kc = 0; kc < 128; kc += 64) {
        g.stage_A(x, m0, kc, tid);
        g.stage_B(wsel*64 + (kc >> 1), tid);
        __syncthreads();
        g.run(c, tid);
        if (kc == 0) __syncthreads();
    }

    const int lane = tid & 31, wid = tid >> 5;
    const int grp = lane >> 2, qd = lane & 3;
    const int wm = (wid >> 1) * 32, wn = (wid & 1) * 64;
#pragma unroll
    for (int mi = 0; mi < 2; ++mi)
#pragma unroll
        for (int ni = 0; ni < 8; ++ni) {
            size_t r0 = (size_t)(m0 + wm + mi*16 + grp);
            int col = wn + ni*8 + 2*qd;
            *(float2*)(outp + r0*DIM + col)     = make_float2(c[mi][ni][0], c[mi][ni][1]);
            *(float2*)(outp + (r0+8)*DIM + col) = make_float2(c[mi][ni][2], c[mi][ni][3]);
        }
}

// ---------------------------------------------------------------------------
__global__ __launch_bounds__(128)
void vsum_part()
{
    const int b = blockIdx.x, c = blockIdx.y;
    const int d = threadIdx.x;
    const float* vp = g_v + ((size_t)b*SEQ + c*64)*DIM + d;
    float s0=0.f,s1=0.f,s2=0.f,s3=0.f;
    for (int m = 0; m < 64; m += 4) {
        s0 += vp[(size_t)(m+0)*DIM]; s1 += vp[(size_t)(m+1)*DIM];
        s2 += vp[(size_t)(m+2)*DIM]; s3 += vp[(size_t)(m+3)*DIM];
    }
    g_vsum_p[(b*64+c)*DIM + d] = (s0+s1)+(s2+s3);
}
__global__ __launch_bounds__(128)
void vsum_red()
{
    const int b = blockIdx.x, d = threadIdx.x;
    float s = 0.f;
#pragma unroll
    for (int c = 0; c < 64; ++c) s += g_vsum_p[(b*64+c)*DIM + d];
    g_vsum[b*DIM + d] = s;
}

// ---------------------------------------------------------------------------
// Attention: bf16 hi/lo mma, 64-query tile, 192-key window in 4x48 chunks,
// split-at-staging (round-7 scheme) + band skip.
// ---------------------------------------------------------------------------
#define AQ_STR 68
#define AK_STR 68
#define AV_STR 136
#define AP_STR 196
#define Q_WORDS  (QT*AQ_STR)
#define KV_WORDS (2*CK*AK_STR)
#define P_WORDS  (QT*AP_STR)
#define ATTN_SMEM ((2*Q_WORDS + KV_WORDS + P_WORDS)*4 + (KT+QT)*4)

__global__ __launch_bounds__(256, 2)
void attn_mma(const int* __restrict__ mask)
{
    extern __shared__ uint32_t smu[];
    uint32_t* Qh = smu;
    uint32_t* Ql = Qh + Q_WORDS;
    uint32_t* KV = Ql + Q_WORDS;
    float*    Ps = (float*)(KV + KV_WORDS);
    int*     msk = (int*)(Ps + P_WORDS);
    int*     qmk = msk + KT;

    uint32_t* Kh = KV;  uint32_t* Kl = KV + CK*AK_STR;
    uint32_t* Vh = KV;  uint32_t* Vl = KV + 24*AV_STR;

    const int tid = threadIdx.x;
    const int b  = blockIdx.y;
    const int q0 = blockIdx.x * QT;
    const int kbase = q0 - 64;

    if (tid < KT) {
        int j = kbase + tid;
        msk[tid] = (j >= 0 && j < SEQ) ? mask[b*SEQ + j] : 0;
    }
    if (tid < QT) qmk[tid] = mask[b*SEQ + q0 + tid];

    // stage Q (split at staging)
#pragma unroll
    for (int t = 0; t < 16; ++t) {
        int idx = tid + t*256;
        int row = idx >> 6, kp = idx & 63;
        float2 v = *(const float2*)(g_q + ((size_t)b*SEQ + q0 + row)*DIM + 2*kp);
        uint32_t h, l; bfsplit2(v.x, v.y, h, l);
        Qh[row*AQ_STR + kp] = h; Ql[row*AQ_STR + kp] = l;
    }
    // stage K chunk 0
#pragma unroll
    for (int t = 0; t < 12; ++t) {
        int idx = tid + t*256;
        int row = idx >> 6, kp = idx & 63;
        int j = kbase + row;
        uint32_t h = 0, l = 0;
        if (j >= 0 && j < SEQ) {
            float2 v = *(const float2*)(g_k + ((size_t)b*SEQ + j)*DIM + 2*kp);
            bfsplit2(v.x, v.y, h, l);
        }
        Kh[row*AK_STR + kp] = h; Kl[row*AK_STR + kp] = l;
    }
    __syncthreads();

    const int lane = tid & 31, wid = tid >> 5;
    const int grp = lane >> 2, qd = lane & 3;
    const float scale = 0.08838834764831845f;

    // ---- S = Q K^T, 4 chunks of 48 keys; warps 4(m) x 2(n), band skip ----
    {
        const int wm = (wid & 3) * 16;
        const int wn = (wid >> 2) * 24;
#pragma unroll 1
        for (int c = 0; c < 4; ++c) {
            float cs[3][4];
#pragma unroll
            for (int ni = 0; ni < 3; ++ni)
#pragma unroll
                for (int e = 0; e < 4; ++e) cs[ni][e] = 0.f;

            bool skip = (c*CK + wn + 24 <= wm) || (c*CK + wn > wm + 143);
            if (!skip) {
#pragma unroll
                for (int t = 0; t < 8; ++t) {
                    int kp0 = 8*t;
                    uint32_t ah[4], al[4];
                    int r = (wm + grp)*AQ_STR;
                    ah[0] = Qh[r + kp0+qd];   ah[1] = Qh[r + 8*AQ_STR + kp0+qd];
                    ah[2] = Qh[r + kp0+qd+4]; ah[3] = Qh[r + 8*AQ_STR + kp0+qd+4];
                    al[0] = Ql[r + kp0+qd];   al[1] = Ql[r + 8*AQ_STR + kp0+qd];
                    al[2] = Ql[r + kp0+qd+4]; al[3] = Ql[r + 8*AQ_STR + kp0+qd+4];
#pragma unroll
                    for (int ni = 0; ni < 3; ++ni) {
                        int col = (wn + ni*8 + grp)*AK_STR;
                        uint32_t bh0 = Kh[col + kp0+qd],  bh1 = Kh[col + kp0+qd+4];
                        uint32_t bl0 = Kl[col + kp0+qd],  bl1 = Kl[col + kp0+qd+4];
                        mma_bf16(cs[ni], ah, bh0, bh1);
                        mma_bf16(cs[ni], al, bh0, bh1);
                        mma_bf16(cs[ni], ah, bl0, bl1);
                    }
                }
            }
#pragma unroll
            for (int ni = 0; ni < 3; ++ni) {
#pragma unroll
                for (int e = 0; e < 4; ++e) {
                    int qi = wm + grp + (e >> 1)*8;
                    int jg = c*CK + wn + ni*8 + 2*qd + (e & 1);
                    bool valid = msk[jg] && (jg >= qi) && (jg <= qi + 128);
                    Ps[qi*AP_STR + jg] = valid ? cs[ni][e]*scale : -1e9f;
                }
            }
            __syncthreads();
            if (c < 3) {
#pragma unroll
                for (int t = 0; t < 12; ++t) {
                    int idx = tid + t*256;
                    int row = idx >> 6, kp = idx & 63;
                    int j = kbase + (c+1)*CK + row;
                    uint32_t h = 0, l = 0;
                    if (j >= 0 && j < SEQ) {
                        float2 v = *(const float2*)(g_k + ((size_t)b*SEQ + j)*DIM + 2*kp);
                        bfsplit2(v.x, v.y, h, l);
                    }
                    Kh[row*AK_STR + kp] = h; Kl[row*AK_STR + kp] = l;
                }
                __syncthreads();
            }
        }
    }

    // stage V chunk 0
#pragma unroll
    for (int t = 0; t < 3; ++t) {
        int idx = tid + t*256;
        int kp = idx >> 5, c4 = idx & 31;
        int j0 = kbase + 2*kp, j1 = j0 + 1;
        float4 v0 = make_float4(0,0,0,0), v1 = make_float4(0,0,0,0);
        if (j0 >= 0 && j0 < SEQ) v0 = *(const float4*)(g_v + ((size_t)b*SEQ + j0)*DIM + 4*c4);
        if (j1 >= 0 && j1 < SEQ) v1 = *(const float4*)(g_v + ((size_t)b*SEQ + j1)*DIM + 4*c4);
        uint32_t h0,l0,h1,l1,h2,l2,h3,l3;
        bfsplit2(v0.x, v1.x, h0, l0); bfsplit2(v0.y, v1.y, h1, l1);
        bfsplit2(v0.z, v1.z, h2, l2); bfsplit2(v0.w, v1.w, h3, l3);
        *(uint4*)(&Vh[kp*AV_STR + 4*c4]) = make_uint4(h0,h1,h2,h3);
        *(uint4*)(&Vl[kp*AV_STR + 4*c4]) = make_uint4(l0,l1,l2,l3);
    }

    // softmax: 4 threads per row
    {
        int qi = tid >> 2, lg = tid & 3;
        float mx = -3.4e38f;
        for (int j = lg; j < KT; j += 4) mx = fmaxf(mx, Ps[qi*AP_STR + j]);
        mx = fmaxf(mx, __shfl_xor_sync(0xffffffffu, mx, 1));
        mx = fmaxf(mx, __shfl_xor_sync(0xffffffffu, mx, 2));
        float s = 0.f;
        for (int j = lg; j < KT; j += 4) {
            float e = __expf(Ps[qi*AP_STR + j] - mx);
            Ps[qi*AP_STR + j] = e;
            s += e;
        }
        s += __shfl_xor_sync(0xffffffffu, s, 1);
        s += __shfl_xor_sync(0xffffffffu, s, 2);
        float inv = 1.f / s;
        for (int j = lg; j < KT; j += 4) Ps[qi*AP_STR + j] *= inv;
    }
    __syncthreads();

    // ---- agg = P V, 4 chunks of 24 key-pairs; warps 2(m) x 4(n) ----
    {
        const int wm = (wid & 1) * 32;
        const int wn = (wid >> 1) * 32;
        float co[2][4][4];
#pragma unroll
        for (int mi = 0; mi < 2; ++mi)
#pragma unroll
            for (int ni = 0; ni < 4; ++ni)
#pragma unroll
                for (int e = 0; e < 4; ++e) co[mi][ni][e] = 0.f;

#pragma unroll 1
        for (int c = 0; c < 4; ++c) {
#pragma unroll
            for (int t = 0; t < 3; ++t) {
                int ksub = 8*t;
                uint32_t ah[2][4], al[2][4];
#pragma unroll
                for (int mi = 0; mi < 2; ++mi) {
                    const float* ap = &Ps[(wm + mi*16 + grp)*AP_STR + 2*(c*24 + ksub + qd)];
                    float2 p0 = *(const float2*)(ap);
                    float2 p1 = *(const float2*)(ap + 8*AP_STR);
                    float2 p2 = *(const float2*)(ap + 8);
                    float2 p3 = *(const float2*)(ap + 8*AP_STR + 8);
                    bfsplit2(p0.x, p0.y, ah[mi][0], al[mi][0]);
                    bfsplit2(p1.x, p1.y, ah[mi][1], al[mi][1]);
                    bfsplit2(p2.x, p2.y, ah[mi][2], al[mi][2]);
                    bfsplit2(p3.x, p3.y, ah[mi][3], al[mi][3]);
                }
#pragma unroll
                for (int ni = 0; ni < 4; ++ni) {
                    int col = wn + ni*8 + grp;
                    uint32_t bh0 = Vh[(ksub+qd)*AV_STR + col];
                    uint32_t bh1 = Vh[(ksub+qd+4)*AV_STR + col];
                    uint32_t bl0 = Vl[(ksub+qd)*AV_STR + col];
                    uint32_t bl1 = Vl[(ksub+qd+4)*AV_STR + col];
#pragma unroll
                    for (int mi = 0; mi < 2; ++mi) {
                        mma_bf16(co[mi][ni], ah[mi], bh0, bh1);
                        mma_bf16(co[mi][ni], al[mi], bh0, bh1);
                        mma_bf16(co[mi][ni], ah[mi], bl0, bl1);
                    }
                }
            }
            if (c < 3) {
                __syncthreads();
#pragma unroll
                for (int t = 0; t < 3; ++t) {
                    int idx = tid + t*256;
                    int kp = idx >> 5, c4 = idx & 31;
                    int j0 = kbase + (c+1)*CK + 2*kp, j1 = j0 + 1;
                    float4 v0 = make_float4(0,0,0,0), v1 = make_float4(0,0,0,0);
                    if (j0 >= 0 && j0 < SEQ) v0 = *(const float4*)(g_v + ((size_t)b*SEQ + j0)*DIM + 4*c4);
                    if (j1 >= 0 && j1 < SEQ) v1 = *(const float4*)(g_v + ((size_t)b*SEQ + j1)*DIM + 4*c4);
                    uint32_t h0,l0,h1,l1,h2,l2,h3,l3;
                    bfsplit2(v0.x, v1.x, h0, l0); bfsplit2(v0.y, v1.y, h1, l1);
                    bfsplit2(v0.z, v1.z, h2, l2); bfsplit2(v0.w, v1.w, h3, l3);
                    *(uint4*)(&Vh[kp*AV_STR + 4*c4]) = make_uint4(h0,h1,h2,h3);
                    *(uint4*)(&Vl[kp*AV_STR + 4*c4]) = make_uint4(l0,l1,l2,l3);
                }
                __syncthreads();
            }
        }

#pragma unroll
        for (int mi = 0; mi < 2; ++mi)
#pragma unroll
            for (int ni = 0; ni < 4; ++ni) {
                int r0 = wm + mi*16 + grp;
                int col = wn + ni*8 + 2*qd;
#pragma unroll
                for (int half = 0; half < 2; ++half) {
                    int qi = r0 + half*8;
                    float v0 = co[mi][ni][half*2], v1 = co[mi][ni][half*2+1];
                    if (!qmk[qi]) {
                        v0 = g_vsum[b*DIM + col]     * (1.f/(float)SEQ);
                        v1 = g_vsum[b*DIM + col + 1] * (1.f/(float)SEQ);
                    }
                    size_t row = (size_t)b*SEQ + q0 + qi;
                    *(float2*)(g_agg + row*DIM + col) = make_float2(v0, v1);
                }
            }
    }
}

// ---------------------------------------------------------------------------
// MLP (K=256, 4 chunks) + fused bias/ReLU/residual/LN.
// ---------------------------------------------------------------------------
__global__ __launch_bounds__(256, 2)
void mlp_mma(const float* __restrict__ x, const float* __restrict__ bu,
             const float* __restrict__ gamma, const float* __restrict__ beta,
             float* __restrict__ out)
{
    extern __shared__ uint32_t smu[];
    GemmB g;
    g.Ah = smu;                 g.Al = g.Ah + 128*GA_STR;
    g.Bh = g.Al + 128*GA_STR;   g.Bl = g.Bh + 32*GB_STR;

    const int tid = threadIdx.x;
    const int m0 = blockIdx.x * 128;

    float c[2][8][4];
#pragma unroll
    for (int mi = 0; mi < 2; ++mi)
#pragma unroll
        for (int ni = 0; ni < 8; ++ni)
#pragma unroll
            for (int e = 0; e < 4; ++e) c[mi][ni][e] = 0.f;

#pragma unroll 1
    for (int ph = 0; ph < 2; ++ph) {
        const float* Asrc = (ph == 0) ? x : (const float*)g_agg;
#pragma unroll 1
        for (int kc = 0; kc < 128; kc += 64) {
            g.stage_A(Asrc, m0, kc, tid);
            g.stage_B(192 + ph*64 + (kc >> 1), tid);
            __syncthreads();
            g.run(c, tid);
            __syncthreads();
        }
    }

    float* Ys = (float*)smu;  // [128][132]
    const int lane = tid & 31, wid = tid >> 5;
    const int grp = lane >> 2, qd = lane & 3;
    const int wm = (wid >> 1) * 32, wn = (wid & 1) * 64;
#pragma unroll
    for (int mi = 0; mi < 2; ++mi)
#pragma unroll
        for (int ni = 0; ni < 8; ++ni) {
            int r0 = wm + mi*16 + grp;
            int col = wn + ni*8 + 2*qd;
            float b0 = __ldg(bu + col), b1 = __ldg(bu + col + 1);
            Ys[r0*132 + col]         = fmaxf(c[mi][ni][0] + b0, 0.f);
            Ys[r0*132 + col + 1]     = fmaxf(c[mi][ni][1] + b1, 0.f);
            Ys[(r0+8)*132 + col]     = fmaxf(c[mi][ni][2] + b0, 0.f);
            Ys[(r0+8)*132 + col + 1] = fmaxf(c[mi][ni][3] + b1, 0.f);
        }
    __syncthreads();

#pragma unroll
    for (int pass = 0; pass < 2; ++pass) {
        int row = (tid >> 2) + pass*64;
        int part = tid & 3;
        const float* xr = x + (size_t)(m0 + row)*DIM + part*32;
        const float* yr = Ys + row*132 + part*32;
        float vals[32];
        float sum = 0.f, sq = 0.f;
#pragma unroll
        for (int j = 0; j < 8; ++j) {
            float4 xv = *(const float4*)(xr + j*4);
            float4 yv = *(const float4*)(yr + j*4);
            float v0 = yv.x+xv.x, v1 = yv.y+xv.y, v2 = yv.z+xv.z, v3 = yv.w+xv.w;
            vals[j*4+0]=v0; vals[j*4+1]=v1; vals[j*4+2]=v2; vals[j*4+3]=v3;
            sum += (v0+v1)+(v2+v3);
            sq  += (v0*v0+v1*v1)+(v2*v2+v3*v3);
        }
        sum += __shfl_xor_sync(0xffffffffu, sum, 1);
        sq  += __shfl_xor_sync(0xffffffffu, sq, 1);
        sum += __shfl_xor_sync(0xffffffffu, sum, 2);
        sq  += __shfl_xor_sync(0xffffffffu, sq, 2);
        float mu   = sum * (1.f/128.f);
        float var  = sq * (1.f/128.f) - mu*mu;
        float rstd = rsqrtf(var + 1e-5f);
        float* op = out + (size_t)(m0 + row)*DIM + part*32;
        const float* gp = gamma + part*32;
        const float* bp = beta + part*32;
#pragma unroll
        for (int j = 0; j < 8; ++j) {
            float4 gv = *(const float4*)(gp + j*4);
            float4 bv = *(const float4*)(bp + j*4);
            float4 o;
            o.x = gv.x*((vals[j*4+0]-mu)*rstd) + bv.x;
            o.y = gv.y*((vals[j*4+1]-mu)*rstd) + bv.y;
            o.z = gv.z*((vals[j*4+2]-mu)*rstd) + bv.z;
            o.w = gv.w*((vals[j*4+3]-mu)*rstd) + bv.w;
            *(float4*)(op + j*4) = o;
        }
    }
}

// ---------------------------------------------------------------------------
extern "C" void kernel_launch(void* const* d_in, const int* in_sizes, int n_in,
                              void* d_out, int out_size)
{
    const float* x    = (const float*)d_in[0];
    const int*   mask = (const int*)d_in[2];
    const float* Wq   = (const float*)d_in[3];
    const float* Wk   = (const float*)d_in[4];
    const float* Wv   = (const float*)d_in[5];
    const float* Wu   = (const float*)d_in[6];
    const float* bu   = (const float*)d_in[7];
    const float* gm   = (const float*)d_in[8];
    const float* bt   = (const float*)d_in[9];
    float* out = (float*)d_out;

    cudaFuncSetAttribute(qkv_mma, cudaFuncAttributeMaxDynamicSharedMemorySize, GEMM_SMEM);
    cudaFuncSetAttribute(mlp_mma, cudaFuncAttributeMaxDynamicSharedMemorySize, GEMM_SMEM);
    cudaFuncSetAttribute(attn_mma, cudaFuncAttributeMaxDynamicSharedMemorySize, ATTN_SMEM);

    prep_w<<<160, 256>>>(Wq, Wk, Wv, Wu);
    qkv_mma<<<dim3(MTOT/128, 3), 256, GEMM_SMEM>>>(x);
    vsum_part<<<dim3(NBATCH, 64), 128>>>();
    vsum_red<<<NBATCH, 128>>>();
    attn_mma<<<dim3(SEQ/QT, NBATCH), 256, ATTN_SMEM>>>(mask);
    mlp_mma<<<MTOT/128, 256, GEMM_SMEM>>>(x, bu, gm, bt, out);
}

// round 10
// speedup vs baseline: 1.6958x; 1.2040x over previous
#include <cuda_runtime.h>
#include <cstdint>

#define NBATCH 4
#define SEQ    4096
#define DIM    128
#define MTOT   (NBATCH*SEQ)
#define QT     64
#define KT     192
#define CKA    96

__device__ float g_q[MTOT*DIM];
__device__ float g_k[MTOT*DIM];
__device__ float g_v[MTOT*DIM];
__device__ float g_agg[MTOT*DIM];
__device__ float g_vsum[NBATCH*DIM];
__device__ float g_vsum_p[NBATCH*64*DIM];
__device__ uint32_t g_wh[(3*64+128)*DIM];   // Wq|Wk|Wv|Wu, B-layout [kp][n], fp16x2 packed

// ---------------------------------------------------------------------------
// fp16 helpers: pack (x0 lo-half, x1 hi-half); split A operands into hi+lo
// ---------------------------------------------------------------------------
__device__ __forceinline__ uint32_t hpack(float x0, float x1) {
    uint32_t r;
    asm("cvt.rn.f16x2.f32 %0, %1, %2;" : "=r"(r) : "f"(x1), "f"(x0));
    return r;
}
__device__ __forceinline__ float2 hunpack(uint32_t h) {
    float f0, f1;
    asm("{.reg .b16 lo,hi; mov.b32 {lo,hi}, %2; cvt.f32.f16 %0, lo; cvt.f32.f16 %1, hi;}"
        : "=f"(f0), "=f"(f1) : "r"(h));
    return make_float2(f0, f1);
}
__device__ __forceinline__ void hsplit2(float x0, float x1, uint32_t& h, uint32_t& l) {
    h = hpack(x0, x1);
    float2 hf = hunpack(h);
    l = hpack(x0 - hf.x, x1 - hf.y);
}
__device__ __forceinline__ void mma_f16(float* c, const uint32_t* a,
                                        uint32_t b0, uint32_t b1) {
    asm volatile(
        "mma.sync.aligned.m16n8k16.row.col.f32.f16.f16.f32 "
        "{%0,%1,%2,%3}, {%4,%5,%6,%7}, {%8,%9}, {%0,%1,%2,%3};"
        : "+f"(c[0]), "+f"(c[1]), "+f"(c[2]), "+f"(c[3])
        : "r"(a[0]), "r"(a[1]), "r"(a[2]), "r"(a[3]), "r"(b0), "r"(b1));
}

// ---------------------------------------------------------------------------
// Prep: round the 4 weight matrices once into B-layout [kp][n] fp16x2.
// ---------------------------------------------------------------------------
__global__ __launch_bounds__(256)
void prep_w(const float* __restrict__ Wq, const float* __restrict__ Wk,
            const float* __restrict__ Wv, const float* __restrict__ Wu)
{
    int o = blockIdx.x*256 + threadIdx.x;    // 0..40959
    const float* W; int ofs, oo;
    if (o < 8192)        { W = Wq; ofs = 0;        oo = o; }
    else if (o < 16384)  { W = Wk; ofs = 64*128;   oo = o - 8192; }
    else if (o < 24576)  { W = Wv; ofs = 128*128;  oo = o - 16384; }
    else                 { W = Wu; ofs = 192*128;  oo = o - 24576; }
    int kp = oo >> 7, n = oo & 127;
    g_wh[ofs + kp*128 + n] = hpack(W[(size_t)(2*kp)*DIM + n], W[(size_t)(2*kp+1)*DIM + n]);
}

// ---------------------------------------------------------------------------
// GEMM core: 128x128 tile, FULL K=128 staged at once (no chunk loop).
// A split hi/lo fp16 [128][68]; B single fp16 [64 kp][136].
// 8 warps (4m x 2n); per warp 2 m-frags x 8 n-frags; 2 MMAs per k16 step.
// ---------------------------------------------------------------------------
#define GA_STR 68
#define GB_STR 136
#define GEMM_SMEM ((2*128*GA_STR + 64*GB_STR)*4)   // 104448 B -> 2 CTAs/SM

struct GemmH {
    uint32_t *Ah, *Al, *Bh;

    __device__ void stage_A(const float* __restrict__ src, int m0, int tid) {
#pragma unroll
        for (int t = 0; t < 32; ++t) {
            int idx = tid + t*256;
            int row = idx >> 6, kp = idx & 63;
            float2 v = *(const float2*)(src + (size_t)(m0+row)*DIM + 2*kp);
            uint32_t h, l; hsplit2(v.x, v.y, h, l);
            Ah[row*GA_STR + kp] = h; Al[row*GA_STR + kp] = l;
        }
    }
    __device__ void stage_B(int kpo, int tid) {
#pragma unroll
        for (int t = 0; t < 8; ++t) {
            int idx = tid + t*256;
            int kp = idx >> 5, c4 = (idx & 31)*4;
            *(uint4*)&Bh[kp*GB_STR + c4] = *(const uint4*)&g_wh[(size_t)(kpo+kp)*128 + c4];
        }
    }
    __device__ void run(float c[2][8][4], int tid) {
        const int lane = tid & 31, wid = tid >> 5;
        const int grp = lane >> 2, qd = lane & 3;
        const int wm = (wid >> 1) * 32, wn = (wid & 1) * 64;
#pragma unroll
        for (int t = 0; t < 8; ++t) {
            int kp0 = 8*t;
            uint32_t ah[2][4], al[2][4];
#pragma unroll
            for (int mi = 0; mi < 2; ++mi) {
                int r = (wm + mi*16 + grp)*GA_STR;
                ah[mi][0] = Ah[r + kp0+qd];   ah[mi][1] = Ah[r + 8*GA_STR + kp0+qd];
                ah[mi][2] = Ah[r + kp0+qd+4]; ah[mi][3] = Ah[r + 8*GA_STR + kp0+qd+4];
                al[mi][0] = Al[r + kp0+qd];   al[mi][1] = Al[r + 8*GA_STR + kp0+qd];
                al[mi][2] = Al[r + kp0+qd+4]; al[mi][3] = Al[r + 8*GA_STR + kp0+qd+4];
            }
#pragma unroll
            for (int ni = 0; ni < 8; ++ni) {
                int col = wn + ni*8 + grp;
                uint32_t bh0 = Bh[(kp0+qd)*GB_STR + col];
                uint32_t bh1 = Bh[(kp0+qd+4)*GB_STR + col];
#pragma unroll
                for (int mi = 0; mi < 2; ++mi) {
                    mma_f16(c[mi][ni], ah[mi], bh0, bh1);
                    mma_f16(c[mi][ni], al[mi], bh0, bh1);
                }
            }
        }
    }
};

// ---------------------------------------------------------------------------
__global__ __launch_bounds__(256, 2)
void qkv_mma(const float* __restrict__ x)
{
    extern __shared__ uint32_t smu[];
    GemmH g;
    g.Ah = smu;               g.Al = g.Ah + 128*GA_STR;
    g.Bh = g.Al + 128*GA_STR;

    const int tid = threadIdx.x;
    const int m0 = blockIdx.x * 128;
    const int wsel = blockIdx.y;
    float* outp = (wsel == 0) ? g_q : (wsel == 1) ? g_k : g_v;

    float c[2][8][4];
#pragma unroll
    for (int mi = 0; mi < 2; ++mi)
#pragma unroll
        for (int ni = 0; ni < 8; ++ni)
#pragma unroll
            for (int e = 0; e < 4; ++e) c[mi][ni][e] = 0.f;

    g.stage_A(x, m0, tid);
    g.stage_B(wsel*64, tid);
    __syncthreads();
    g.run(c, tid);

    const int lane = tid & 31, wid = tid >> 5;
    const int grp = lane >> 2, qd = lane & 3;
    const int wm = (wid >> 1) * 32, wn = (wid & 1) * 64;
#pragma unroll
    for (int mi = 0; mi < 2; ++mi)
#pragma unroll
        for (int ni = 0; ni < 8; ++ni) {
            size_t r0 = (size_t)(m0 + wm + mi*16 + grp);
            int col = wn + ni*8 + 2*qd;
            *(float2*)(outp + r0*DIM + col)     = make_float2(c[mi][ni][0], c[mi][ni][1]);
            *(float2*)(outp + (r0+8)*DIM + col) = make_float2(c[mi][ni][2], c[mi][ni][3]);
        }
}

// ---------------------------------------------------------------------------
__global__ __launch_bounds__(128)
void vsum_part()
{
    const int b = blockIdx.x, c = blockIdx.y;
    const int d = threadIdx.x;
    const float* vp = g_v + ((size_t)b*SEQ + c*64)*DIM + d;
    float s0=0.f,s1=0.f,s2=0.f,s3=0.f;
    for (int m = 0; m < 64; m += 4) {
        s0 += vp[(size_t)(m+0)*DIM]; s1 += vp[(size_t)(m+1)*DIM];
        s2 += vp[(size_t)(m+2)*DIM]; s3 += vp[(size_t)(m+3)*DIM];
    }
    g_vsum_p[(b*64+c)*DIM + d] = (s0+s1)+(s2+s3);
}
__global__ __launch_bounds__(512)
void vsum_red()
{
    __shared__ float ps[4][128];
    const int b = blockIdx.x;
    const int c = threadIdx.x >> 7, d = threadIdx.x & 127;
    float s = 0.f;
#pragma unroll
    for (int k = 0; k < 16; ++k) s += g_vsum_p[(b*64 + c*16 + k)*DIM + d];
    ps[c][d] = s;
    __syncthreads();
    if (threadIdx.x < 128)
        g_vsum[b*DIM + threadIdx.x] =
            (ps[0][threadIdx.x] + ps[1][threadIdx.x]) +
            (ps[2][threadIdx.x] + ps[3][threadIdx.x]);
}

// ---------------------------------------------------------------------------
// Attention: fp16 2-term, 64-query tile, 192-key window in 2x96 chunks.
// Q split hi/lo; K,V single fp16. P fp32, split on the fly for PV.
// ---------------------------------------------------------------------------
#define AQ_STR 68
#define AK_STR 68
#define AV_STR 136
#define AP_STR 196
#define Q_WORDS  (QT*AQ_STR)        // 4352 per array
#define KV_WORDS (CKA*AK_STR)       // 6528 (== 48*136)
#define P_WORDS  (QT*AP_STR)        // 12544
#define ATTN_SMEM ((2*Q_WORDS + KV_WORDS + P_WORDS)*4 + (KT+QT)*4)   // 112128

__global__ __launch_bounds__(256, 2)
void attn_mma(const int* __restrict__ mask)
{
    extern __shared__ uint32_t smu[];
    uint32_t* Qh = smu;
    uint32_t* Ql = Qh + Q_WORDS;
    uint32_t* KV = Ql + Q_WORDS;            // K chunk [96][68] or V chunk [48kp][136]
    float*    Ps = (float*)(KV + KV_WORDS);
    int*     msk = (int*)(Ps + P_WORDS);
    int*     qmk = msk + KT;

    uint32_t* Ks = KV;
    uint32_t* Vs = KV;

    const int tid = threadIdx.x;
    const int b  = blockIdx.y;
    const int q0 = blockIdx.x * QT;
    const int kbase = q0 - 64;

    if (tid < KT) {
        int j = kbase + tid;
        msk[tid] = (j >= 0 && j < SEQ) ? mask[b*SEQ + j] : 0;
    }
    if (tid < QT) qmk[tid] = mask[b*SEQ + q0 + tid];

    // stage Q (split hi/lo)
#pragma unroll
    for (int t = 0; t < 16; ++t) {
        int idx = tid + t*256;
        int row = idx >> 6, kp = idx & 63;
        float2 v = *(const float2*)(g_q + ((size_t)b*SEQ + q0 + row)*DIM + 2*kp);
        uint32_t h, l; hsplit2(v.x, v.y, h, l);
        Qh[row*AQ_STR + kp] = h; Ql[row*AQ_STR + kp] = l;
    }
    // stage K chunk 0 (96 rows, single fp16)
#pragma unroll
    for (int t = 0; t < 24; ++t) {
        int idx = tid + t*256;
        int row = idx >> 6, kp = idx & 63;
        int j = kbase + row;
        uint32_t h = 0;
        if (j >= 0 && j < SEQ) {
            float2 v = *(const float2*)(g_k + ((size_t)b*SEQ + j)*DIM + 2*kp);
            h = hpack(v.x, v.y);
        }
        Ks[row*AK_STR + kp] = h;
    }
    __syncthreads();

    const int lane = tid & 31, wid = tid >> 5;
    const int grp = lane >> 2, qd = lane & 3;
    const float scale = 0.08838834764831845f;   // 1/sqrt(128)

    // ---- S = Q K^T, 2 chunks of 96 keys; warps 4(m) x 2(n) ----
    {
        const int wm = (wid & 3) * 16;
        const int wn = (wid >> 2) * 48;
#pragma unroll 1
        for (int c = 0; c < 2; ++c) {
            float cs[6][4];
#pragma unroll
            for (int ni = 0; ni < 6; ++ni)
#pragma unroll
                for (int e = 0; e < 4; ++e) cs[ni][e] = 0.f;

            int cb = c*CKA + wn;
            bool skip = (cb + 47 < wm) || (cb > wm + 143);
            if (!skip) {
#pragma unroll
                for (int t = 0; t < 8; ++t) {
                    int kp0 = 8*t;
                    uint32_t ah[4], al[4];
                    int r = (wm + grp)*AQ_STR;
                    ah[0] = Qh[r + kp0+qd];   ah[1] = Qh[r + 8*AQ_STR + kp0+qd];
                    ah[2] = Qh[r + kp0+qd+4]; ah[3] = Qh[r + 8*AQ_STR + kp0+qd+4];
                    al[0] = Ql[r + kp0+qd];   al[1] = Ql[r + 8*AQ_STR + kp0+qd];
                    al[2] = Ql[r + kp0+qd+4]; al[3] = Ql[r + 8*AQ_STR + kp0+qd+4];
#pragma unroll
                    for (int ni = 0; ni < 6; ++ni) {
                        int col = (wn + ni*8 + grp)*AK_STR;
                        uint32_t bh0 = Ks[col + kp0+qd];
                        uint32_t bh1 = Ks[col + kp0+qd+4];
                        mma_f16(cs[ni], ah, bh0, bh1);
                        mma_f16(cs[ni], al, bh0, bh1);
                    }
                }
            }
#pragma unroll
            for (int ni = 0; ni < 6; ++ni) {
#pragma unroll
                for (int e = 0; e < 4; ++e) {
                    int qi = wm + grp + (e >> 1)*8;
                    int jg = cb + ni*8 + 2*qd + (e & 1);
                    bool valid = msk[jg] && (jg >= qi) && (jg <= qi + 128);
                    Ps[qi*AP_STR + jg] = valid ? cs[ni][e]*scale : -1e9f;
                }
            }
            __syncthreads();
            if (c == 0) {
#pragma unroll
                for (int t = 0; t < 24; ++t) {
                    int idx = tid + t*256;
                    int row = idx >> 6, kp = idx & 63;
                    int j = kbase + CKA + row;
                    uint32_t h = 0;
                    if (j >= 0 && j < SEQ) {
                        float2 v = *(const float2*)(g_k + ((size_t)b*SEQ + j)*DIM + 2*kp);
                        h = hpack(v.x, v.y);
                    }
                    Ks[row*AK_STR + kp] = h;
                }
                __syncthreads();
            }
        }
    }

    // stage V chunk 0 (48 key-pairs, single fp16; K buffer free after S sync)
#pragma unroll
    for (int t = 0; t < 6; ++t) {
        int idx = tid + t*256;
        int kp = idx >> 5, c4 = (idx & 31)*4;
        int j0 = kbase + 2*kp, j1 = j0 + 1;
        float4 v0 = make_float4(0,0,0,0), v1 = make_float4(0,0,0,0);
        if (j0 >= 0 && j0 < SEQ) v0 = *(const float4*)(g_v + ((size_t)b*SEQ + j0)*DIM + c4);
        if (j1 >= 0 && j1 < SEQ) v1 = *(const float4*)(g_v + ((size_t)b*SEQ + j1)*DIM + c4);
        *(uint4*)&Vs[kp*AV_STR + c4] = make_uint4(
            hpack(v0.x, v1.x), hpack(v0.y, v1.y), hpack(v0.z, v1.z), hpack(v0.w, v1.w));
    }

    // softmax: 4 threads per row
    {
        int qi = tid >> 2, lg = tid & 3;
        float mx = -3.4e38f;
        for (int j = lg; j < KT; j += 4) mx = fmaxf(mx, Ps[qi*AP_STR + j]);
        mx = fmaxf(mx, __shfl_xor_sync(0xffffffffu, mx, 1));
        mx = fmaxf(mx, __shfl_xor_sync(0xffffffffu, mx, 2));
        float s = 0.f;
        for (int j = lg; j < KT; j += 4) {
            float e = __expf(Ps[qi*AP_STR + j] - mx);
            Ps[qi*AP_STR + j] = e;
            s += e;
        }
        s += __shfl_xor_sync(0xffffffffu, s, 1);
        s += __shfl_xor_sync(0xffffffffu, s, 2);
        float inv = 1.f / s;
        for (int j = lg; j < KT; j += 4) Ps[qi*AP_STR + j] *= inv;
    }
    __syncthreads();

    // ---- agg = P V, 2 chunks of 48 key-pairs; warps 2(m) x 4(n) ----
    {
        const int wm = (wid & 1) * 32;
        const int wn = (wid >> 1) * 32;
        float co[2][4][4];
#pragma unroll
        for (int mi = 0; mi < 2; ++mi)
#pragma unroll
            for (int ni = 0; ni < 4; ++ni)
#pragma unroll
                for (int e = 0; e < 4; ++e) co[mi][ni][e] = 0.f;

#pragma unroll 1
        for (int c = 0; c < 2; ++c) {
#pragma unroll
            for (int t = 0; t < 6; ++t) {
                int ck = c*48 + t*8;          // global key-pair base for this step
                uint32_t ah[2][4], al[2][4];
#pragma unroll
                for (int mi = 0; mi < 2; ++mi) {
                    const float* ap = &Ps[(wm + mi*16 + grp)*AP_STR + 2*(ck + qd)];
                    float2 p0 = *(const float2*)(ap);
                    float2 p1 = *(const float2*)(ap + 8*AP_STR);
                    float2 p2 = *(const float2*)(ap + 8);
                    float2 p3 = *(const float2*)(ap + 8*AP_STR + 8);
                    hsplit2(p0.x, p0.y, ah[mi][0], al[mi][0]);
                    hsplit2(p1.x, p1.y, ah[mi][1], al[mi][1]);
                    hsplit2(p2.x, p2.y, ah[mi][2], al[mi][2]);
                    hsplit2(p3.x, p3.y, ah[mi][3], al[mi][3]);
                }
#pragma unroll
                for (int ni = 0; ni < 4; ++ni) {
                    int col = wn + ni*8 + grp;
                    uint32_t bh0 = Vs[(t*8+qd)*AV_STR + col];
                    uint32_t bh1 = Vs[(t*8+qd+4)*AV_STR + col];
#pragma unroll
                    for (int mi = 0; mi < 2; ++mi) {
                        mma_f16(co[mi][ni], ah[mi], bh0, bh1);
                        mma_f16(co[mi][ni], al[mi], bh0, bh1);
                    }
                }
            }
            if (c == 0) {
                __syncthreads();
#pragma unroll
                for (int t = 0; t < 6; ++t) {
                    int idx = tid + t*256;
                    int kp = idx >> 5, c4 = (idx & 31)*4;
                    int j0 = kbase + CKA + 2*kp, j1 = j0 + 1;
                    float4 v0 = make_float4(0,0,0,0), v1 = make_float4(0,0,0,0);
                    if (j0 >= 0 && j0 < SEQ) v0 = *(const float4*)(g_v + ((size_t)b*SEQ + j0)*DIM + c4);
                    if (j1 >= 0 && j1 < SEQ) v1 = *(const float4*)(g_v + ((size_t)b*SEQ + j1)*DIM + c4);
                    *(uint4*)&Vs[kp*AV_STR + c4] = make_uint4(
                        hpack(v0.x, v1.x), hpack(v0.y, v1.y), hpack(v0.z, v1.z), hpack(v0.w, v1.w));
                }
                __syncthreads();
            }
        }

        // epilogue: write agg; masked query rows get uniform mean of v
#pragma unroll
        for (int mi = 0; mi < 2; ++mi)
#pragma unroll
            for (int ni = 0; ni < 4; ++ni) {
                int r0 = wm + mi*16 + grp;
                int col = wn + ni*8 + 2*qd;
#pragma unroll
                for (int half = 0; half < 2; ++half) {
                    int qi = r0 + half*8;
                    float v0 = co[mi][ni][half*2], v1 = co[mi][ni][half*2+1];
                    if (!qmk[qi]) {
                        v0 = g_vsum[b*DIM + col]     * (1.f/(float)SEQ);
                        v1 = g_vsum[b*DIM + col + 1] * (1.f/(float)SEQ);
                    }
                    size_t row = (size_t)b*SEQ + q0 + qi;
                    *(float2*)(g_agg + row*DIM + col) = make_float2(v0, v1);
                }
            }
    }
}

// ---------------------------------------------------------------------------
// MLP (K=256 via 2 full-128 phases) + fused bias/ReLU/residual/LN.
// ---------------------------------------------------------------------------
__global__ __launch_bounds__(256, 2)
void mlp_mma(const float* __restrict__ x, const float* __restrict__ bu,
             const float* __restrict__ gamma, const float* __restrict__ beta,
             float* __restrict__ out)
{
    extern __shared__ uint32_t smu[];
    GemmH g;
    g.Ah = smu;               g.Al = g.Ah + 128*GA_STR;
    g.Bh = g.Al + 128*GA_STR;

    const int tid = threadIdx.x;
    const int m0 = blockIdx.x * 128;

    float c[2][8][4];
#pragma unroll
    for (int mi = 0; mi < 2; ++mi)
#pragma unroll
        for (int ni = 0; ni < 8; ++ni)
#pragma unroll
            for (int e = 0; e < 4; ++e) c[mi][ni][e] = 0.f;

#pragma unroll 1
    for (int ph = 0; ph < 2; ++ph) {
        const float* Asrc = (ph == 0) ? x : (const float*)g_agg;
        g.stage_A(Asrc, m0, tid);
        g.stage_B(192 + ph*64, tid);
        __syncthreads();
        g.run(c, tid);
        __syncthreads();
    }

    float* Ys = (float*)smu;  // [128][132]
    const int lane = tid & 31, wid = tid >> 5;
    const int grp = lane >> 2, qd = lane & 3;
    const int wm = (wid >> 1) * 32, wn = (wid & 1) * 64;
#pragma unroll
    for (int mi = 0; mi < 2; ++mi)
#pragma unroll
        for (int ni = 0; ni < 8; ++ni) {
            int r0 = wm + mi*16 + grp;
            int col = wn + ni*8 + 2*qd;
            float b0 = __ldg(bu + col), b1 = __ldg(bu + col + 1);
            Ys[r0*132 + col]         = fmaxf(c[mi][ni][0] + b0, 0.f);
            Ys[r0*132 + col + 1]     = fmaxf(c[mi][ni][1] + b1, 0.f);
            Ys[(r0+8)*132 + col]     = fmaxf(c[mi][ni][2] + b0, 0.f);
            Ys[(r0+8)*132 + col + 1] = fmaxf(c[mi][ni][3] + b1, 0.f);
        }
    __syncthreads();

#pragma unroll
    for (int pass = 0; pass < 2; ++pass) {
        int row = (tid >> 2) + pass*64;
        int part = tid & 3;
        const float* xr = x + (size_t)(m0 + row)*DIM + part*32;
        const float* yr = Ys + row*132 + part*32;
        float vals[32];
        float sum = 0.f, sq = 0.f;
#pragma unroll
        for (int j = 0; j < 8; ++j) {
            float4 xv = *(const float4*)(xr + j*4);
            float4 yv = *(const float4*)(yr + j*4);
            float v0 = yv.x+xv.x, v1 = yv.y+xv.y, v2 = yv.z+xv.z, v3 = yv.w+xv.w;
            vals[j*4+0]=v0; vals[j*4+1]=v1; vals[j*4+2]=v2; vals[j*4+3]=v3;
            sum += (v0+v1)+(v2+v3);
            sq  += (v0*v0+v1*v1)+(v2*v2+v3*v3);
        }
        sum += __shfl_xor_sync(0xffffffffu, sum, 1);
        sq  += __shfl_xor_sync(0xffffffffu, sq, 1);
        sum += __shfl_xor_sync(0xffffffffu, sum, 2);
        sq  += __shfl_xor_sync(0xffffffffu, sq, 2);
        float mu   = sum * (1.f/128.f);
        float var  = sq * (1.f/128.f) - mu*mu;
        float rstd = rsqrtf(var + 1e-5f);
        float* op = out + (size_t)(m0 + row)*DIM + part*32;
        const float* gp = gamma + part*32;
        const float* bp = beta + part*32;
#pragma unroll
        for (int j = 0; j < 8; ++j) {
            float4 gv = *(const float4*)(gp + j*4);
            float4 bv = *(const float4*)(bp + j*4);
            float4 o;
            o.x = gv.x*((vals[j*4+0]-mu)*rstd) + bv.x;
            o.y = gv.y*((vals[j*4+1]-mu)*rstd) + bv.y;
            o.z = gv.z*((vals[j*4+2]-mu)*rstd) + bv.z;
            o.w = gv.w*((vals[j*4+3]-mu)*rstd) + bv.w;
            *(float4*)(op + j*4) = o;
        }
    }
}

// ---------------------------------------------------------------------------
extern "C" void kernel_launch(void* const* d_in, const int* in_sizes, int n_in,
                              void* d_out, int out_size)
{
    const float* x    = (const float*)d_in[0];
    const int*   mask = (const int*)d_in[2];
    const float* Wq   = (const float*)d_in[3];
    const float* Wk   = (const float*)d_in[4];
    const float* Wv   = (const float*)d_in[5];
    const float* Wu   = (const float*)d_in[6];
    const float* bu   = (const float*)d_in[7];
    const float* gm   = (const float*)d_in[8];
    const float* bt   = (const float*)d_in[9];
    float* out = (float*)d_out;

    cudaFuncSetAttribute(qkv_mma, cudaFuncAttributeMaxDynamicSharedMemorySize, GEMM_SMEM);
    cudaFuncSetAttribute(mlp_mma, cudaFuncAttributeMaxDynamicSharedMemorySize, GEMM_SMEM);
    cudaFuncSetAttribute(attn_mma, cudaFuncAttributeMaxDynamicSharedMemorySize, ATTN_SMEM);

    prep_w<<<160, 256>>>(Wq, Wk, Wv, Wu);
    qkv_mma<<<dim3(MTOT/128, 3), 256, GEMM_SMEM>>>(x);
    vsum_part<<<dim3(NBATCH, 64), 128>>>();
    vsum_red<<<NBATCH, 512>>>();
    attn_mma<<<dim3(SEQ/QT, NBATCH), 256, ATTN_SMEM>>>(mask);
    mlp_mma<<<MTOT/128, 256, GEMM_SMEM>>>(x, bu, gm, bt, out);
}

// round 11
// speedup vs baseline: 1.8564x; 1.0947x over previous
#include <cuda_runtime.h>
#include <cstdint>

#define NBATCH 4
#define SEQ    4096
#define DIM    128
#define MTOT   (NBATCH*SEQ)
#define QT     64
#define KT     192
#define CKA    96

__device__ float g_q[MTOT*DIM];
__device__ float g_k[MTOT*DIM];
__device__ float g_v[MTOT*DIM];
__device__ float g_agg[MTOT*DIM];
__device__ float g_vsum[NBATCH*DIM];
__device__ float g_vsum_p[NBATCH*32*DIM];
__device__ uint32_t g_wh[(3*64+128)*DIM];   // Wq|Wk|Wv|Wu, B-layout [kp][n], fp16x2

// ---------------------------------------------------------------------------
__device__ __forceinline__ uint32_t hpack(float x0, float x1) {
    uint32_t r;
    asm("cvt.rn.f16x2.f32 %0, %1, %2;" : "=r"(r) : "f"(x1), "f"(x0));
    return r;
}
__device__ __forceinline__ float2 hunpack(uint32_t h) {
    float f0, f1;
    asm("{.reg .b16 lo,hi; mov.b32 {lo,hi}, %2; cvt.f32.f16 %0, lo; cvt.f32.f16 %1, hi;}"
        : "=f"(f0), "=f"(f1) : "r"(h));
    return make_float2(f0, f1);
}
__device__ __forceinline__ void hsplit2(float x0, float x1, uint32_t& h, uint32_t& l) {
    h = hpack(x0, x1);
    float2 hf = hunpack(h);
    l = hpack(x0 - hf.x, x1 - hf.y);
}
__device__ __forceinline__ void mma_f16(float* c, const uint32_t* a,
                                        uint32_t b0, uint32_t b1) {
    asm volatile(
        "mma.sync.aligned.m16n8k16.row.col.f32.f16.f16.f32 "
        "{%0,%1,%2,%3}, {%4,%5,%6,%7}, {%8,%9}, {%0,%1,%2,%3};"
        : "+f"(c[0]), "+f"(c[1]), "+f"(c[2]), "+f"(c[3])
        : "r"(a[0]), "r"(a[1]), "r"(a[2]), "r"(a[3]), "r"(b0), "r"(b1));
}

// ---------------------------------------------------------------------------
__global__ __launch_bounds__(256)
void prep_w(const float* __restrict__ Wq, const float* __restrict__ Wk,
            const float* __restrict__ Wv, const float* __restrict__ Wu)
{
    int o = blockIdx.x*256 + threadIdx.x;
    const float* W; int ofs, oo;
    if (o < 8192)        { W = Wq; ofs = 0;        oo = o; }
    else if (o < 16384)  { W = Wk; ofs = 64*128;   oo = o - 8192; }
    else if (o < 24576)  { W = Wv; ofs = 128*128;  oo = o - 16384; }
    else                 { W = Wu; ofs = 192*128;  oo = o - 24576; }
    int kp = oo >> 7, n = oo & 127;
    g_wh[ofs + kp*128 + n] = hpack(W[(size_t)(2*kp)*DIM + n], W[(size_t)(2*kp+1)*DIM + n]);
}

// ---------------------------------------------------------------------------
// GEMM core: 128x128 tile, full K=128; A split hi/lo fp16, B single fp16.
// ---------------------------------------------------------------------------
#define GA_STR 68
#define GB_STR 136
#define GEMM_SMEM ((2*128*GA_STR + 64*GB_STR)*4)   // 104448 B

struct GemmH {
    uint32_t *Ah, *Al, *Bh;

    __device__ void stage_A(const float* __restrict__ src, int m0, int tid) {
#pragma unroll
        for (int t = 0; t < 32; ++t) {
            int idx = tid + t*256;
            int row = idx >> 6, kp = idx & 63;
            float2 v = *(const float2*)(src + (size_t)(m0+row)*DIM + 2*kp);
            uint32_t h, l; hsplit2(v.x, v.y, h, l);
            Ah[row*GA_STR + kp] = h; Al[row*GA_STR + kp] = l;
        }
    }
    __device__ void stage_B(int kpo, int tid) {
#pragma unroll
        for (int t = 0; t < 8; ++t) {
            int idx = tid + t*256;
            int kp = idx >> 5, c4 = (idx & 31)*4;
            *(uint4*)&Bh[kp*GB_STR + c4] = *(const uint4*)&g_wh[(size_t)(kpo+kp)*128 + c4];
        }
    }
    __device__ void run(float c[2][8][4], int tid) {
        const int lane = tid & 31, wid = tid >> 5;
        const int grp = lane >> 2, qd = lane & 3;
        const int wm = (wid >> 1) * 32, wn = (wid & 1) * 64;
#pragma unroll
        for (int t = 0; t < 8; ++t) {
            int kp0 = 8*t;
            uint32_t ah[2][4], al[2][4];
#pragma unroll
            for (int mi = 0; mi < 2; ++mi) {
                int r = (wm + mi*16 + grp)*GA_STR;
                ah[mi][0] = Ah[r + kp0+qd];   ah[mi][1] = Ah[r + 8*GA_STR + kp0+qd];
                ah[mi][2] = Ah[r + kp0+qd+4]; ah[mi][3] = Ah[r + 8*GA_STR + kp0+qd+4];
                al[mi][0] = Al[r + kp0+qd];   al[mi][1] = Al[r + 8*GA_STR + kp0+qd];
                al[mi][2] = Al[r + kp0+qd+4]; al[mi][3] = Al[r + 8*GA_STR + kp0+qd+4];
            }
#pragma unroll
            for (int ni = 0; ni < 8; ++ni) {
                int col = wn + ni*8 + grp;
                uint32_t bh0 = Bh[(kp0+qd)*GB_STR + col];
                uint32_t bh1 = Bh[(kp0+qd+4)*GB_STR + col];
#pragma unroll
                for (int mi = 0; mi < 2; ++mi) {
                    mma_f16(c[mi][ni], ah[mi], bh0, bh1);
                    mma_f16(c[mi][ni], al[mi], bh0, bh1);
                }
            }
        }
    }
};

// ---------------------------------------------------------------------------
// QKV fused: one CTA stages x once, loops over Wq/Wk/Wv. V phase also emits
// per-tile column sums (vsum partials) via smem reduce.
// ---------------------------------------------------------------------------
__global__ __launch_bounds__(256, 2)
void qkv3_mma(const float* __restrict__ x)
{
    extern __shared__ uint32_t smu[];
    GemmH g;
    g.Ah = smu;               g.Al = g.Ah + 128*GA_STR;
    g.Bh = g.Al + 128*GA_STR;

    const int tid = threadIdx.x;
    const int m0 = blockIdx.x * 128;

    const int lane = tid & 31, wid = tid >> 5;
    const int grp = lane >> 2, qd = lane & 3;
    const int wm = (wid >> 1) * 32, wn = (wid & 1) * 64;

    g.stage_A(x, m0, tid);

    float c[2][8][4];
#pragma unroll 1
    for (int w = 0; w < 3; ++w) {
        if (w > 0) __syncthreads();         // prior run's B reads done
        g.stage_B(w*64, tid);
        __syncthreads();
#pragma unroll
        for (int mi = 0; mi < 2; ++mi)
#pragma unroll
            for (int ni = 0; ni < 8; ++ni)
#pragma unroll
                for (int e = 0; e < 4; ++e) c[mi][ni][e] = 0.f;
        g.run(c, tid);

        float* outp = (w == 0) ? g_q : (w == 1) ? g_k : g_v;
#pragma unroll
        for (int mi = 0; mi < 2; ++mi)
#pragma unroll
            for (int ni = 0; ni < 8; ++ni) {
                size_t r0 = (size_t)(m0 + wm + mi*16 + grp);
                int col = wn + ni*8 + 2*qd;
                *(float2*)(outp + r0*DIM + col)     = make_float2(c[mi][ni][0], c[mi][ni][1]);
                *(float2*)(outp + (r0+8)*DIM + col) = make_float2(c[mi][ni][2], c[mi][ni][3]);
            }
    }

    // ---- V column partial sums (c still holds the V tile) ----
    __syncthreads();                         // all smem reads of Ah/Al/Bh done
    float* Ys = (float*)smu;                 // [128][132]
#pragma unroll
    for (int mi = 0; mi < 2; ++mi)
#pragma unroll
        for (int ni = 0; ni < 8; ++ni) {
            int r0 = wm + mi*16 + grp;
            int col = wn + ni*8 + 2*qd;
            Ys[r0*132 + col]         = c[mi][ni][0];
            Ys[r0*132 + col + 1]     = c[mi][ni][1];
            Ys[(r0+8)*132 + col]     = c[mi][ni][2];
            Ys[(r0+8)*132 + col + 1] = c[mi][ni][3];
        }
    __syncthreads();
    {
        int col = tid & 127, half = tid >> 7;
        float s = 0.f;
#pragma unroll
        for (int r = 0; r < 64; r += 4) {
            s += Ys[(half*64 + r+0)*132 + col];
            s += Ys[(half*64 + r+1)*132 + col];
            s += Ys[(half*64 + r+2)*132 + col];
            s += Ys[(half*64 + r+3)*132 + col];
        }
        float* ps2 = Ys + 128*132;
        ps2[half*128 + col] = s;
        __syncthreads();
        if (tid < 128) {
            int b = m0 >> 12;
            int t = (m0 >> 7) & 31;
            g_vsum_p[(b*32 + t)*128 + tid] = ps2[tid] + ps2[128 + tid];
        }
    }
}

// ---------------------------------------------------------------------------
__global__ __launch_bounds__(512)
void vsum_red()
{
    __shared__ float ps[4][128];
    const int b = blockIdx.x;
    const int c = threadIdx.x >> 7, d = threadIdx.x & 127;
    float s = 0.f;
#pragma unroll
    for (int k = 0; k < 8; ++k) s += g_vsum_p[(b*32 + c*8 + k)*DIM + d];
    ps[c][d] = s;
    __syncthreads();
    if (threadIdx.x < 128)
        g_vsum[b*DIM + threadIdx.x] =
            (ps[0][threadIdx.x] + ps[1][threadIdx.x]) +
            (ps[2][threadIdx.x] + ps[3][threadIdx.x]);
}

// ---------------------------------------------------------------------------
// Attention: fp16 2-term QK^T; softmax writes P as packed fp16 (overlaying Q);
// PV single-term. 64-query tile, 192-key window in 2x96 chunks.
// ---------------------------------------------------------------------------
#define AQ_STR 68
#define AK_STR 68
#define AV_STR 136
#define AP_STR 196
#define PH_STR 100
#define Q_WORDS  (QT*AQ_STR)        // 4352 per array (Ph needs 6400 <= 2*4352)
#define KV_WORDS (CKA*AK_STR)       // 6528
#define P_WORDS  (QT*AP_STR)        // 12544
#define ATTN_SMEM ((2*Q_WORDS + KV_WORDS + P_WORDS)*4 + (KT+QT)*4)

__global__ __launch_bounds__(256, 2)
void attn_mma(const int* __restrict__ mask)
{
    extern __shared__ uint32_t smu[];
    uint32_t* Qh = smu;
    uint32_t* Ql = Qh + Q_WORDS;
    uint32_t* KV = Ql + Q_WORDS;
    float*    Ps = (float*)(KV + KV_WORDS);
    int*     msk = (int*)(Ps + P_WORDS);
    int*     qmk = msk + KT;

    uint32_t* Ks = KV;
    uint32_t* Vs = KV;
    uint32_t* Ph = Qh;                  // packed fp16 P, [64][100], overlays Q

    const int tid = threadIdx.x;
    const int b  = blockIdx.y;
    const int q0 = blockIdx.x * QT;
    const int kbase = q0 - 64;

    if (tid < KT) {
        int j = kbase + tid;
        msk[tid] = (j >= 0 && j < SEQ) ? mask[b*SEQ + j] : 0;
    }
    if (tid < QT) qmk[tid] = mask[b*SEQ + q0 + tid];

    // stage Q (split hi/lo)
#pragma unroll
    for (int t = 0; t < 16; ++t) {
        int idx = tid + t*256;
        int row = idx >> 6, kp = idx & 63;
        float2 v = *(const float2*)(g_q + ((size_t)b*SEQ + q0 + row)*DIM + 2*kp);
        uint32_t h, l; hsplit2(v.x, v.y, h, l);
        Qh[row*AQ_STR + kp] = h; Ql[row*AQ_STR + kp] = l;
    }
    // stage K chunk 0
#pragma unroll
    for (int t = 0; t < 24; ++t) {
        int idx = tid + t*256;
        int row = idx >> 6, kp = idx & 63;
        int j = kbase + row;
        uint32_t h = 0;
        if (j >= 0 && j < SEQ) {
            float2 v = *(const float2*)(g_k + ((size_t)b*SEQ + j)*DIM + 2*kp);
            h = hpack(v.x, v.y);
        }
        Ks[row*AK_STR + kp] = h;
    }
    __syncthreads();

    const int lane = tid & 31, wid = tid >> 5;
    const int grp = lane >> 2, qd = lane & 3;
    const float scale = 0.08838834764831845f;

    // ---- S = Q K^T, 2 chunks of 96 keys; warps 4(m) x 2(n) ----
    {
        const int wm = (wid & 3) * 16;
        const int wn = (wid >> 2) * 48;
#pragma unroll 1
        for (int c = 0; c < 2; ++c) {
            float cs[6][4];
#pragma unroll
            for (int ni = 0; ni < 6; ++ni)
#pragma unroll
                for (int e = 0; e < 4; ++e) cs[ni][e] = 0.f;

            int cb = c*CKA + wn;
            bool skip = (cb + 47 < wm) || (cb > wm + 143);
            if (!skip) {
#pragma unroll
                for (int t = 0; t < 8; ++t) {
                    int kp0 = 8*t;
                    uint32_t ah[4], al[4];
                    int r = (wm + grp)*AQ_STR;
                    ah[0] = Qh[r + kp0+qd];   ah[1] = Qh[r + 8*AQ_STR + kp0+qd];
                    ah[2] = Qh[r + kp0+qd+4]; ah[3] = Qh[r + 8*AQ_STR + kp0+qd+4];
                    al[0] = Ql[r + kp0+qd];   al[1] = Ql[r + 8*AQ_STR + kp0+qd];
                    al[2] = Ql[r + kp0+qd+4]; al[3] = Ql[r + 8*AQ_STR + kp0+qd+4];
#pragma unroll
                    for (int ni = 0; ni < 6; ++ni) {
                        int col = (wn + ni*8 + grp)*AK_STR;
                        uint32_t bh0 = Ks[col + kp0+qd];
                        uint32_t bh1 = Ks[col + kp0+qd+4];
                        mma_f16(cs[ni], ah, bh0, bh1);
                        mma_f16(cs[ni], al, bh0, bh1);
                    }
                }
            }
#pragma unroll
            for (int ni = 0; ni < 6; ++ni) {
#pragma unroll
                for (int e = 0; e < 4; ++e) {
                    int qi = wm + grp + (e >> 1)*8;
                    int jg = cb + ni*8 + 2*qd + (e & 1);
                    bool valid = msk[jg] && (jg >= qi) && (jg <= qi + 128);
                    Ps[qi*AP_STR + jg] = valid ? cs[ni][e]*scale : -1e9f;
                }
            }
            __syncthreads();
            if (c == 0) {
#pragma unroll
                for (int t = 0; t < 24; ++t) {
                    int idx = tid + t*256;
                    int row = idx >> 6, kp = idx & 63;
                    int j = kbase + CKA + row;
                    uint32_t h = 0;
                    if (j >= 0 && j < SEQ) {
                        float2 v = *(const float2*)(g_k + ((size_t)b*SEQ + j)*DIM + 2*kp);
                        h = hpack(v.x, v.y);
                    }
                    Ks[row*AK_STR + kp] = h;
                }
                __syncthreads();
            }
        }
    }

    // stage V chunk 0 (48 key-pairs, single fp16)
#pragma unroll
    for (int t = 0; t < 6; ++t) {
        int idx = tid + t*256;
        int kp = idx >> 5, c4 = (idx & 31)*4;
        int j0 = kbase + 2*kp, j1 = j0 + 1;
        float4 v0 = make_float4(0,0,0,0), v1 = make_float4(0,0,0,0);
        if (j0 >= 0 && j0 < SEQ) v0 = *(const float4*)(g_v + ((size_t)b*SEQ + j0)*DIM + c4);
        if (j1 >= 0 && j1 < SEQ) v1 = *(const float4*)(g_v + ((size_t)b*SEQ + j1)*DIM + c4);
        *(uint4*)&Vs[kp*AV_STR + c4] = make_uint4(
            hpack(v0.x, v1.x), hpack(v0.y, v1.y), hpack(v0.z, v1.z), hpack(v0.w, v1.w));
    }

    // softmax: 4 threads per row; final pass packs P into fp16 Ph
    {
        int qi = tid >> 2, lg = tid & 3;
        float mx = -3.4e38f;
        for (int j = lg; j < KT; j += 4) mx = fmaxf(mx, Ps[qi*AP_STR + j]);
        mx = fmaxf(mx, __shfl_xor_sync(0xffffffffu, mx, 1));
        mx = fmaxf(mx, __shfl_xor_sync(0xffffffffu, mx, 2));
        float s = 0.f;
        for (int j = lg; j < KT; j += 4) {
            float e = __expf(Ps[qi*AP_STR + j] - mx);
            Ps[qi*AP_STR + j] = e;
            s += e;
        }
        s += __shfl_xor_sync(0xffffffffu, s, 1);
        s += __shfl_xor_sync(0xffffffffu, s, 2);
        float inv = 1.f / s;
        for (int kp = lg; kp < CKA; kp += 4) {
            float e0 = Ps[qi*AP_STR + 2*kp];
            float e1 = Ps[qi*AP_STR + 2*kp + 1];
            Ph[qi*PH_STR + kp] = hpack(e0*inv, e1*inv);
        }
    }
    __syncthreads();

    // ---- agg = P V (single-term), 2 chunks of 48 key-pairs; warps 2m x 4n ----
    {
        const int wm = (wid & 1) * 32;
        const int wn = (wid >> 1) * 32;
        float co[2][4][4];
#pragma unroll
        for (int mi = 0; mi < 2; ++mi)
#pragma unroll
            for (int ni = 0; ni < 4; ++ni)
#pragma unroll
                for (int e = 0; e < 4; ++e) co[mi][ni][e] = 0.f;

#pragma unroll 1
        for (int c = 0; c < 2; ++c) {
#pragma unroll
            for (int t = 0; t < 6; ++t) {
                int ck = c*48 + t*8;
                uint32_t ah[2][4];
#pragma unroll
                for (int mi = 0; mi < 2; ++mi) {
                    int r = (wm + mi*16 + grp)*PH_STR + ck + qd;
                    ah[mi][0] = Ph[r];
                    ah[mi][1] = Ph[r + 8*PH_STR];
                    ah[mi][2] = Ph[r + 4];
                    ah[mi][3] = Ph[r + 8*PH_STR + 4];
                }
#pragma unroll
                for (int ni = 0; ni < 4; ++ni) {
                    int col = wn + ni*8 + grp;
                    uint32_t bh0 = Vs[(t*8+qd)*AV_STR + col];
                    uint32_t bh1 = Vs[(t*8+qd+4)*AV_STR + col];
#pragma unroll
                    for (int mi = 0; mi < 2; ++mi)
                        mma_f16(co[mi][ni], ah[mi], bh0, bh1);
                }
            }
            if (c == 0) {
                __syncthreads();
#pragma unroll
                for (int t = 0; t < 6; ++t) {
                    int idx = tid + t*256;
                    int kp = idx >> 5, c4 = (idx & 31)*4;
                    int j0 = kbase + CKA + 2*kp, j1 = j0 + 1;
                    float4 v0 = make_float4(0,0,0,0), v1 = make_float4(0,0,0,0);
                    if (j0 >= 0 && j0 < SEQ) v0 = *(const float4*)(g_v + ((size_t)b*SEQ + j0)*DIM + c4);
                    if (j1 >= 0 && j1 < SEQ) v1 = *(const float4*)(g_v + ((size_t)b*SEQ + j1)*DIM + c4);
                    *(uint4*)&Vs[kp*AV_STR + c4] = make_uint4(
                        hpack(v0.x, v1.x), hpack(v0.y, v1.y), hpack(v0.z, v1.z), hpack(v0.w, v1.w));
                }
                __syncthreads();
            }
        }

        // epilogue: write agg; masked query rows get uniform mean of v
#pragma unroll
        for (int mi = 0; mi < 2; ++mi)
#pragma unroll
            for (int ni = 0; ni < 4; ++ni) {
                int r0 = wm + mi*16 + grp;
                int col = wn + ni*8 + 2*qd;
#pragma unroll
                for (int half = 0; half < 2; ++half) {
                    int qi = r0 + half*8;
                    float v0 = co[mi][ni][half*2], v1 = co[mi][ni][half*2+1];
                    if (!qmk[qi]) {
                        v0 = g_vsum[b*DIM + col]     * (1.f/(float)SEQ);
                        v1 = g_vsum[b*DIM + col + 1] * (1.f/(float)SEQ);
                    }
                    size_t row = (size_t)b*SEQ + q0 + qi;
                    *(float2*)(g_agg + row*DIM + col) = make_float2(v0, v1);
                }
            }
    }
}

// ---------------------------------------------------------------------------
// MLP (K=256 via 2 full-128 phases) + fused bias/ReLU/residual/LN.
// ---------------------------------------------------------------------------
__global__ __launch_bounds__(256, 2)
void mlp_mma(const float* __restrict__ x, const float* __restrict__ bu,
             const float* __restrict__ gamma, const float* __restrict__ beta,
             float* __restrict__ out)
{
    extern __shared__ uint32_t smu[];
    GemmH g;
    g.Ah = smu;               g.Al = g.Ah + 128*GA_STR;
    g.Bh = g.Al + 128*GA_STR;

    const int tid = threadIdx.x;
    const int m0 = blockIdx.x * 128;

    float c[2][8][4];
#pragma unroll
    for (int mi = 0; mi < 2; ++mi)
#pragma unroll
        for (int ni = 0; ni < 8; ++ni)
#pragma unroll
            for (int e = 0; e < 4; ++e) c[mi][ni][e] = 0.f;

#pragma unroll 1
    for (int ph = 0; ph < 2; ++ph) {
        const float* Asrc = (ph == 0) ? x : (const float*)g_agg;
        g.stage_A(Asrc, m0, tid);
        g.stage_B(192 + ph*64, tid);
        __syncthreads();
        g.run(c, tid);
        __syncthreads();
    }

    float* Ys = (float*)smu;  // [128][132]
    const int lane = tid & 31, wid = tid >> 5;
    const int grp = lane >> 2, qd = lane & 3;
    const int wm = (wid >> 1) * 32, wn = (wid & 1) * 64;
#pragma unroll
    for (int mi = 0; mi < 2; ++mi)
#pragma unroll
        for (int ni = 0; ni < 8; ++ni) {
            int r0 = wm + mi*16 + grp;
            int col = wn + ni*8 + 2*qd;
            float b0 = __ldg(bu + col), b1 = __ldg(bu + col + 1);
            Ys[r0*132 + col]         = fmaxf(c[mi][ni][0] + b0, 0.f);
            Ys[r0*132 + col + 1]     = fmaxf(c[mi][ni][1] + b1, 0.f);
            Ys[(r0+8)*132 + col]     = fmaxf(c[mi][ni][2] + b0, 0.f);
            Ys[(r0+8)*132 + col + 1] = fmaxf(c[mi][ni][3] + b1, 0.f);
        }
    __syncthreads();

#pragma unroll
    for (int pass = 0; pass < 2; ++pass) {
        int row = (tid >> 2) + pass*64;
        int part = tid & 3;
        const float* xr = x + (size_t)(m0 + row)*DIM + part*32;
        const float* yr = Ys + row*132 + part*32;
        float vals[32];
        float sum = 0.f, sq = 0.f;
#pragma unroll
        for (int j = 0; j < 8; ++j) {
            float4 xv = *(const float4*)(xr + j*4);
            float4 yv = *(const float4*)(yr + j*4);
            float v0 = yv.x+xv.x, v1 = yv.y+xv.y, v2 = yv.z+xv.z, v3 = yv.w+xv.w;
            vals[j*4+0]=v0; vals[j*4+1]=v1; vals[j*4+2]=v2; vals[j*4+3]=v3;
            sum += (v0+v1)+(v2+v3);
            sq  += (v0*v0+v1*v1)+(v2*v2+v3*v3);
        }
        sum += __shfl_xor_sync(0xffffffffu, sum, 1);
        sq  += __shfl_xor_sync(0xffffffffu, sq, 1);
        sum += __shfl_xor_sync(0xffffffffu, sum, 2);
        sq  += __shfl_xor_sync(0xffffffffu, sq, 2);
        float mu   = sum * (1.f/128.f);
        float var  = sq * (1.f/128.f) - mu*mu;
        float rstd = rsqrtf(var + 1e-5f);
        float* op = out + (size_t)(m0 + row)*DIM + part*32;
        const float* gp = gamma + part*32;
        const float* bp = beta + part*32;
#pragma unroll
        for (int j = 0; j < 8; ++j) {
            float4 gv = *(const float4*)(gp + j*4);
            float4 bv = *(const float4*)(bp + j*4);
            float4 o;
            o.x = gv.x*((vals[j*4+0]-mu)*rstd) + bv.x;
            o.y = gv.y*((vals[j*4+1]-mu)*rstd) + bv.y;
            o.z = gv.z*((vals[j*4+2]-mu)*rstd) + bv.z;
            o.w = gv.w*((vals[j*4+3]-mu)*rstd) + bv.w;
            *(float4*)(op + j*4) = o;
        }
    }
}

// ---------------------------------------------------------------------------
extern "C" void kernel_launch(void* const* d_in, const int* in_sizes, int n_in,
                              void* d_out, int out_size)
{
    const float* x    = (const float*)d_in[0];
    const int*   mask = (const int*)d_in[2];
    const float* Wq   = (const float*)d_in[3];
    const float* Wk   = (const float*)d_in[4];
    const float* Wv   = (const float*)d_in[5];
    const float* Wu   = (const float*)d_in[6];
    const float* bu   = (const float*)d_in[7];
    const float* gm   = (const float*)d_in[8];
    const float* bt   = (const float*)d_in[9];
    float* out = (float*)d_out;

    cudaFuncSetAttribute(qkv3_mma, cudaFuncAttributeMaxDynamicSharedMemorySize, GEMM_SMEM);
    cudaFuncSetAttribute(mlp_mma,  cudaFuncAttributeMaxDynamicSharedMemorySize, GEMM_SMEM);
    cudaFuncSetAttribute(attn_mma, cudaFuncAttributeMaxDynamicSharedMemorySize, ATTN_SMEM);

    prep_w<<<160, 256>>>(Wq, Wk, Wv, Wu);
    qkv3_mma<<<MTOT/128, 256, GEMM_SMEM>>>(x);
    vsum_red<<<NBATCH, 512>>>();
    attn_mma<<<dim3(SEQ/QT, NBATCH), 256, ATTN_SMEM>>>(mask);
    mlp_mma<<<MTOT/128, 256, GEMM_SMEM>>>(x, bu, gm, bt, out);
}

// round 12
// speedup vs baseline: 1.8650x; 1.0047x over previous
#include <cuda_runtime.h>
#include <cstdint>

#define NBATCH 4
#define SEQ    4096
#define DIM    128
#define MTOT   (NBATCH*SEQ)
#define QT     64
#define KT     192
#define CKA    96

__device__ float g_q[MTOT*DIM];
__device__ float g_k[MTOT*DIM];
__device__ float g_v[MTOT*DIM];
__device__ float g_agg[MTOT*DIM];
__device__ float g_vsum[NBATCH*DIM];
__device__ float g_vsum_p[NBATCH*64*DIM];
__device__ uint32_t g_wh[(3*64+128)*DIM];   // Wq|Wk|Wv|Wu, B-layout [kp][n], fp16x2

// ---------------------------------------------------------------------------
__device__ __forceinline__ uint32_t hpack(float x0, float x1) {
    uint32_t r;
    asm("cvt.rn.f16x2.f32 %0, %1, %2;" : "=r"(r) : "f"(x1), "f"(x0));
    return r;
}
__device__ __forceinline__ float2 hunpack(uint32_t h) {
    float f0, f1;
    asm("{.reg .b16 lo,hi; mov.b32 {lo,hi}, %2; cvt.f32.f16 %0, lo; cvt.f32.f16 %1, hi;}"
        : "=f"(f0), "=f"(f1) : "r"(h));
    return make_float2(f0, f1);
}
__device__ __forceinline__ void hsplit2(float x0, float x1, uint32_t& h, uint32_t& l) {
    h = hpack(x0, x1);
    float2 hf = hunpack(h);
    l = hpack(x0 - hf.x, x1 - hf.y);
}
__device__ __forceinline__ void mma_f16(float* c, const uint32_t* a,
                                        uint32_t b0, uint32_t b1) {
    asm volatile(
        "mma.sync.aligned.m16n8k16.row.col.f32.f16.f16.f32 "
        "{%0,%1,%2,%3}, {%4,%5,%6,%7}, {%8,%9}, {%0,%1,%2,%3};"
        : "+f"(c[0]), "+f"(c[1]), "+f"(c[2]), "+f"(c[3])
        : "r"(a[0]), "r"(a[1]), "r"(a[2]), "r"(a[3]), "r"(b0), "r"(b1));
}

// ---------------------------------------------------------------------------
__global__ __launch_bounds__(256)
void prep_w(const float* __restrict__ Wq, const float* __restrict__ Wk,
            const float* __restrict__ Wv, const float* __restrict__ Wu)
{
    int o = blockIdx.x*256 + threadIdx.x;
    const float* W; int ofs, oo;
    if (o < 8192)        { W = Wq; ofs = 0;        oo = o; }
    else if (o < 16384)  { W = Wk; ofs = 64*128;   oo = o - 8192; }
    else if (o < 24576)  { W = Wv; ofs = 128*128;  oo = o - 16384; }
    else                 { W = Wu; ofs = 192*128;  oo = o - 24576; }
    int kp = oo >> 7, n = oo & 127;
    g_wh[ofs + kp*128 + n] = hpack(W[(size_t)(2*kp)*DIM + n], W[(size_t)(2*kp+1)*DIM + n]);
}

// ---------------------------------------------------------------------------
// GEMM core (BM=64): 64x128 tile, full K=128; A split hi/lo fp16, B fp16.
// 8 warps as 4(m) x 2(n); per warp 1 m-frag x 8 n-frags.
// smem: 2*64*68 + 64*136 = 17408 words = 69632 B -> up to 3 CTAs/SM.
// ---------------------------------------------------------------------------
#define GA_STR 68
#define GB_STR 136
#define GEMM_SMEM ((2*64*GA_STR + 64*GB_STR)*4)   // 69632 B

struct GemmH64 {
    uint32_t *Ah, *Al, *Bh;

    __device__ void stage_A(const float* __restrict__ src, int m0, int tid) {
#pragma unroll
        for (int t = 0; t < 16; ++t) {
            int idx = tid + t*256;
            int row = idx >> 6, kp = idx & 63;
            float2 v = *(const float2*)(src + (size_t)(m0+row)*DIM + 2*kp);
            uint32_t h, l; hsplit2(v.x, v.y, h, l);
            Ah[row*GA_STR + kp] = h; Al[row*GA_STR + kp] = l;
        }
    }
    __device__ void stage_B(int kpo, int tid) {
#pragma unroll
        for (int t = 0; t < 8; ++t) {
            int idx = tid + t*256;
            int kp = idx >> 5, c4 = (idx & 31)*4;
            *(uint4*)&Bh[kp*GB_STR + c4] = *(const uint4*)&g_wh[(size_t)(kpo+kp)*128 + c4];
        }
    }
    __device__ void run(float c[8][4], int tid) {
        const int lane = tid & 31, wid = tid >> 5;
        const int grp = lane >> 2, qd = lane & 3;
        const int wm = (wid & 3) * 16, wn = (wid >> 2) * 64;
#pragma unroll
        for (int t = 0; t < 8; ++t) {
            int kp0 = 8*t;
            uint32_t ah[4], al[4];
            int r = (wm + grp)*GA_STR;
            ah[0] = Ah[r + kp0+qd];   ah[1] = Ah[r + 8*GA_STR + kp0+qd];
            ah[2] = Ah[r + kp0+qd+4]; ah[3] = Ah[r + 8*GA_STR + kp0+qd+4];
            al[0] = Al[r + kp0+qd];   al[1] = Al[r + 8*GA_STR + kp0+qd];
            al[2] = Al[r + kp0+qd+4]; al[3] = Al[r + 8*GA_STR + kp0+qd+4];
#pragma unroll
            for (int ni = 0; ni < 8; ++ni) {
                int col = wn + ni*8 + grp;
                uint32_t bh0 = Bh[(kp0+qd)*GB_STR + col];
                uint32_t bh1 = Bh[(kp0+qd+4)*GB_STR + col];
                mma_f16(c[ni], ah, bh0, bh1);
                mma_f16(c[ni], al, bh0, bh1);
            }
        }
    }
};

// ---------------------------------------------------------------------------
// QKV fused (BM=64): one CTA stages x once, loops over Wq/Wk/Wv; V phase
// also emits per-tile column sums.
// ---------------------------------------------------------------------------
__global__ __launch_bounds__(256, 3)
void qkv3_mma(const float* __restrict__ x)
{
    extern __shared__ uint32_t smu[];
    GemmH64 g;
    g.Ah = smu;               g.Al = g.Ah + 64*GA_STR;
    g.Bh = g.Al + 64*GA_STR;

    const int tid = threadIdx.x;
    const int m0 = blockIdx.x * 64;

    const int lane = tid & 31, wid = tid >> 5;
    const int grp = lane >> 2, qd = lane & 3;
    const int wm = (wid & 3) * 16, wn = (wid >> 2) * 64;

    g.stage_A(x, m0, tid);

    float c[8][4];
#pragma unroll 1
    for (int w = 0; w < 3; ++w) {
        if (w > 0) __syncthreads();
        g.stage_B(w*64, tid);
        __syncthreads();
#pragma unroll
        for (int ni = 0; ni < 8; ++ni)
#pragma unroll
            for (int e = 0; e < 4; ++e) c[ni][e] = 0.f;
        g.run(c, tid);

        float* outp = (w == 0) ? g_q : (w == 1) ? g_k : g_v;
#pragma unroll
        for (int ni = 0; ni < 8; ++ni) {
            size_t r0 = (size_t)(m0 + wm + grp);
            int col = wn + ni*8 + 2*qd;
            *(float2*)(outp + r0*DIM + col)     = make_float2(c[ni][0], c[ni][1]);
            *(float2*)(outp + (r0+8)*DIM + col) = make_float2(c[ni][2], c[ni][3]);
        }
    }

    // ---- V column partial sums (c still holds the V tile) ----
    __syncthreads();
    float* Ys = (float*)smu;                 // [64][132]
#pragma unroll
    for (int ni = 0; ni < 8; ++ni) {
        int r0 = wm + grp;
        int col = wn + ni*8 + 2*qd;
        Ys[r0*132 + col]         = c[ni][0];
        Ys[r0*132 + col + 1]     = c[ni][1];
        Ys[(r0+8)*132 + col]     = c[ni][2];
        Ys[(r0+8)*132 + col + 1] = c[ni][3];
    }
    __syncthreads();
    {
        int col = tid & 127, half = tid >> 7;
        float s = 0.f;
#pragma unroll
        for (int r = 0; r < 32; r += 4) {
            s += Ys[(half*32 + r+0)*132 + col];
            s += Ys[(half*32 + r+1)*132 + col];
            s += Ys[(half*32 + r+2)*132 + col];
            s += Ys[(half*32 + r+3)*132 + col];
        }
        float* ps2 = Ys + 64*132;
        ps2[half*128 + col] = s;
        __syncthreads();
        if (tid < 128) {
            int b = m0 >> 12;
            int t = (m0 >> 6) & 63;
            g_vsum_p[(b*64 + t)*128 + tid] = ps2[tid] + ps2[128 + tid];
        }
    }
}

// ---------------------------------------------------------------------------
__global__ __launch_bounds__(512)
void vsum_red()
{
    __shared__ float ps[4][128];
    const int b = blockIdx.x;
    const int c = threadIdx.x >> 7, d = threadIdx.x & 127;
    float s = 0.f;
#pragma unroll
    for (int k = 0; k < 16; ++k) s += g_vsum_p[(b*64 + c*16 + k)*DIM + d];
    ps[c][d] = s;
    __syncthreads();
    if (threadIdx.x < 128)
        g_vsum[b*DIM + threadIdx.x] =
            (ps[0][threadIdx.x] + ps[1][threadIdx.x]) +
            (ps[2][threadIdx.x] + ps[3][threadIdx.x]);
}

// ---------------------------------------------------------------------------
// Attention (unchanged from round 11): fp16 2-term QK^T, P packed fp16,
// PV single-term. 64-query tile, 192-key window in 2x96 chunks.
// ---------------------------------------------------------------------------
#define AQ_STR 68
#define AK_STR 68
#define AV_STR 136
#define AP_STR 196
#define PH_STR 100
#define Q_WORDS  (QT*AQ_STR)
#define KV_WORDS (CKA*AK_STR)
#define P_WORDS  (QT*AP_STR)
#define ATTN_SMEM ((2*Q_WORDS + KV_WORDS + P_WORDS)*4 + (KT+QT)*4)

__global__ __launch_bounds__(256, 2)
void attn_mma(const int* __restrict__ mask)
{
    extern __shared__ uint32_t smu[];
    uint32_t* Qh = smu;
    uint32_t* Ql = Qh + Q_WORDS;
    uint32_t* KV = Ql + Q_WORDS;
    float*    Ps = (float*)(KV + KV_WORDS);
    int*     msk = (int*)(Ps + P_WORDS);
    int*     qmk = msk + KT;

    uint32_t* Ks = KV;
    uint32_t* Vs = KV;
    uint32_t* Ph = Qh;

    const int tid = threadIdx.x;
    const int b  = blockIdx.y;
    const int q0 = blockIdx.x * QT;
    const int kbase = q0 - 64;

    if (tid < KT) {
        int j = kbase + tid;
        msk[tid] = (j >= 0 && j < SEQ) ? mask[b*SEQ + j] : 0;
    }
    if (tid < QT) qmk[tid] = mask[b*SEQ + q0 + tid];

#pragma unroll
    for (int t = 0; t < 16; ++t) {
        int idx = tid + t*256;
        int row = idx >> 6, kp = idx & 63;
        float2 v = *(const float2*)(g_q + ((size_t)b*SEQ + q0 + row)*DIM + 2*kp);
        uint32_t h, l; hsplit2(v.x, v.y, h, l);
        Qh[row*AQ_STR + kp] = h; Ql[row*AQ_STR + kp] = l;
    }
#pragma unroll
    for (int t = 0; t < 24; ++t) {
        int idx = tid + t*256;
        int row = idx >> 6, kp = idx & 63;
        int j = kbase + row;
        uint32_t h = 0;
        if (j >= 0 && j < SEQ) {
            float2 v = *(const float2*)(g_k + ((size_t)b*SEQ + j)*DIM + 2*kp);
            h = hpack(v.x, v.y);
        }
        Ks[row*AK_STR + kp] = h;
    }
    __syncthreads();

    const int lane = tid & 31, wid = tid >> 5;
    const int grp = lane >> 2, qd = lane & 3;
    const float scale = 0.08838834764831845f;

    {
        const int wm = (wid & 3) * 16;
        const int wn = (wid >> 2) * 48;
#pragma unroll 1
        for (int c = 0; c < 2; ++c) {
            float cs[6][4];
#pragma unroll
            for (int ni = 0; ni < 6; ++ni)
#pragma unroll
                for (int e = 0; e < 4; ++e) cs[ni][e] = 0.f;

            int cb = c*CKA + wn;
            bool skip = (cb + 47 < wm) || (cb > wm + 143);
            if (!skip) {
#pragma unroll
                for (int t = 0; t < 8; ++t) {
                    int kp0 = 8*t;
                    uint32_t ah[4], al[4];
                    int r = (wm + grp)*AQ_STR;
                    ah[0] = Qh[r + kp0+qd];   ah[1] = Qh[r + 8*AQ_STR + kp0+qd];
                    ah[2] = Qh[r + kp0+qd+4]; ah[3] = Qh[r + 8*AQ_STR + kp0+qd+4];
                    al[0] = Ql[r + kp0+qd];   al[1] = Ql[r + 8*AQ_STR + kp0+qd];
                    al[2] = Ql[r + kp0+qd+4]; al[3] = Ql[r + 8*AQ_STR + kp0+qd+4];
#pragma unroll
                    for (int ni = 0; ni < 6; ++ni) {
                        int col = (wn + ni*8 + grp)*AK_STR;
                        uint32_t bh0 = Ks[col + kp0+qd];
                        uint32_t bh1 = Ks[col + kp0+qd+4];
                        mma_f16(cs[ni], ah, bh0, bh1);
                        mma_f16(cs[ni], al, bh0, bh1);
                    }
                }
            }
#pragma unroll
            for (int ni = 0; ni < 6; ++ni) {
#pragma unroll
                for (int e = 0; e < 4; ++e) {
                    int qi = wm + grp + (e >> 1)*8;
                    int jg = cb + ni*8 + 2*qd + (e & 1);
                    bool valid = msk[jg] && (jg >= qi) && (jg <= qi + 128);
                    Ps[qi*AP_STR + jg] = valid ? cs[ni][e]*scale : -1e9f;
                }
            }
            __syncthreads();
            if (c == 0) {
#pragma unroll
                for (int t = 0; t < 24; ++t) {
                    int idx = tid + t*256;
                    int row = idx >> 6, kp = idx & 63;
                    int j = kbase + CKA + row;
                    uint32_t h = 0;
                    if (j >= 0 && j < SEQ) {
                        float2 v = *(const float2*)(g_k + ((size_t)b*SEQ + j)*DIM + 2*kp);
                        h = hpack(v.x, v.y);
                    }
                    Ks[row*AK_STR + kp] = h;
                }
                __syncthreads();
            }
        }
    }

#pragma unroll
    for (int t = 0; t < 6; ++t) {
        int idx = tid + t*256;
        int kp = idx >> 5, c4 = (idx & 31)*4;
        int j0 = kbase + 2*kp, j1 = j0 + 1;
        float4 v0 = make_float4(0,0,0,0), v1 = make_float4(0,0,0,0);
        if (j0 >= 0 && j0 < SEQ) v0 = *(const float4*)(g_v + ((size_t)b*SEQ + j0)*DIM + c4);
        if (j1 >= 0 && j1 < SEQ) v1 = *(const float4*)(g_v + ((size_t)b*SEQ + j1)*DIM + c4);
        *(uint4*)&Vs[kp*AV_STR + c4] = make_uint4(
            hpack(v0.x, v1.x), hpack(v0.y, v1.y), hpack(v0.z, v1.z), hpack(v0.w, v1.w));
    }

    {
        int qi = tid >> 2, lg = tid & 3;
        float mx = -3.4e38f;
        for (int j = lg; j < KT; j += 4) mx = fmaxf(mx, Ps[qi*AP_STR + j]);
        mx = fmaxf(mx, __shfl_xor_sync(0xffffffffu, mx, 1));
        mx = fmaxf(mx, __shfl_xor_sync(0xffffffffu, mx, 2));
        float s = 0.f;
        for (int j = lg; j < KT; j += 4) {
            float e = __expf(Ps[qi*AP_STR + j] - mx);
            Ps[qi*AP_STR + j] = e;
            s += e;
        }
        s += __shfl_xor_sync(0xffffffffu, s, 1);
        s += __shfl_xor_sync(0xffffffffu, s, 2);
        float inv = 1.f / s;
        for (int kp = lg; kp < CKA; kp += 4) {
            float e0 = Ps[qi*AP_STR + 2*kp];
            float e1 = Ps[qi*AP_STR + 2*kp + 1];
            Ph[qi*PH_STR + kp] = hpack(e0*inv, e1*inv);
        }
    }
    __syncthreads();

    {
        const int wm = (wid & 1) * 32;
        const int wn = (wid >> 1) * 32;
        float co[2][4][4];
#pragma unroll
        for (int mi = 0; mi < 2; ++mi)
#pragma unroll
            for (int ni = 0; ni < 4; ++ni)
#pragma unroll
                for (int e = 0; e < 4; ++e) co[mi][ni][e] = 0.f;

#pragma unroll 1
        for (int c = 0; c < 2; ++c) {
#pragma unroll
            for (int t = 0; t < 6; ++t) {
                int ck = c*48 + t*8;
                uint32_t ah[2][4];
#pragma unroll
                for (int mi = 0; mi < 2; ++mi) {
                    int r = (wm + mi*16 + grp)*PH_STR + ck + qd;
                    ah[mi][0] = Ph[r];
                    ah[mi][1] = Ph[r + 8*PH_STR];
                    ah[mi][2] = Ph[r + 4];
                    ah[mi][3] = Ph[r + 8*PH_STR + 4];
                }
#pragma unroll
                for (int ni = 0; ni < 4; ++ni) {
                    int col = wn + ni*8 + grp;
                    uint32_t bh0 = Vs[(t*8+qd)*AV_STR + col];
                    uint32_t bh1 = Vs[(t*8+qd+4)*AV_STR + col];
#pragma unroll
                    for (int mi = 0; mi < 2; ++mi)
                        mma_f16(co[mi][ni], ah[mi], bh0, bh1);
                }
            }
            if (c == 0) {
                __syncthreads();
#pragma unroll
                for (int t = 0; t < 6; ++t) {
                    int idx = tid + t*256;
                    int kp = idx >> 5, c4 = (idx & 31)*4;
                    int j0 = kbase + CKA + 2*kp, j1 = j0 + 1;
                    float4 v0 = make_float4(0,0,0,0), v1 = make_float4(0,0,0,0);
                    if (j0 >= 0 && j0 < SEQ) v0 = *(const float4*)(g_v + ((size_t)b*SEQ + j0)*DIM + c4);
                    if (j1 >= 0 && j1 < SEQ) v1 = *(const float4*)(g_v + ((size_t)b*SEQ + j1)*DIM + c4);
                    *(uint4*)&Vs[kp*AV_STR + c4] = make_uint4(
                        hpack(v0.x, v1.x), hpack(v0.y, v1.y), hpack(v0.z, v1.z), hpack(v0.w, v1.w));
                }
                __syncthreads();
            }
        }

#pragma unroll
        for (int mi = 0; mi < 2; ++mi)
#pragma unroll
            for (int ni = 0; ni < 4; ++ni) {
                int r0 = wm + mi*16 + grp;
                int col = wn + ni*8 + 2*qd;
#pragma unroll
                for (int half = 0; half < 2; ++half) {
                    int qi = r0 + half*8;
                    float v0 = co[mi][ni][half*2], v1 = co[mi][ni][half*2+1];
                    if (!qmk[qi]) {
                        v0 = g_vsum[b*DIM + col]     * (1.f/(float)SEQ);
                        v1 = g_vsum[b*DIM + col + 1] * (1.f/(float)SEQ);
                    }
                    size_t row = (size_t)b*SEQ + q0 + qi;
                    *(float2*)(g_agg + row*DIM + col) = make_float2(v0, v1);
                }
            }
    }
}

// ---------------------------------------------------------------------------
// MLP (BM=64, K=256 via 2 full-128 phases) + fused bias/ReLU/residual/LN.
// ---------------------------------------------------------------------------
__global__ __launch_bounds__(256, 3)
void mlp_mma(const float* __restrict__ x, const float* __restrict__ bu,
             const float* __restrict__ gamma, const float* __restrict__ beta,
             float* __restrict__ out)
{
    extern __shared__ uint32_t smu[];
    GemmH64 g;
    g.Ah = smu;               g.Al = g.Ah + 64*GA_STR;
    g.Bh = g.Al + 64*GA_STR;

    const int tid = threadIdx.x;
    const int m0 = blockIdx.x * 64;

    float c[8][4];
#pragma unroll
    for (int ni = 0; ni < 8; ++ni)
#pragma unroll
        for (int e = 0; e < 4; ++e) c[ni][e] = 0.f;

#pragma unroll 1
    for (int ph = 0; ph < 2; ++ph) {
        const float* Asrc = (ph == 0) ? x : (const float*)g_agg;
        g.stage_A(Asrc, m0, tid);
        g.stage_B(192 + ph*64, tid);
        __syncthreads();
        g.run(c, tid);
        __syncthreads();
    }

    float* Ys = (float*)smu;  // [64][132]
    const int lane = tid & 31, wid = tid >> 5;
    const int grp = lane >> 2, qd = lane & 3;
    const int wm = (wid & 3) * 16, wn = (wid >> 2) * 64;
#pragma unroll
    for (int ni = 0; ni < 8; ++ni) {
        int r0 = wm + grp;
        int col = wn + ni*8 + 2*qd;
        float b0 = __ldg(bu + col), b1 = __ldg(bu + col + 1);
        Ys[r0*132 + col]         = fmaxf(c[ni][0] + b0, 0.f);
        Ys[r0*132 + col + 1]     = fmaxf(c[ni][1] + b1, 0.f);
        Ys[(r0+8)*132 + col]     = fmaxf(c[ni][2] + b0, 0.f);
        Ys[(r0+8)*132 + col + 1] = fmaxf(c[ni][3] + b1, 0.f);
    }
    __syncthreads();

    {
        int row = tid >> 2;
        int part = tid & 3;
        const float* xr = x + (size_t)(m0 + row)*DIM + part*32;
        const float* yr = Ys + row*132 + part*32;
        float vals[32];
        float sum = 0.f, sq = 0.f;
#pragma unroll
        for (int j = 0; j < 8; ++j) {
            float4 xv = *(const float4*)(xr + j*4);
            float4 yv = *(const float4*)(yr + j*4);
            float v0 = yv.x+xv.x, v1 = yv.y+xv.y, v2 = yv.z+xv.z, v3 = yv.w+xv.w;
            vals[j*4+0]=v0; vals[j*4+1]=v1; vals[j*4+2]=v2; vals[j*4+3]=v3;
            sum += (v0+v1)+(v2+v3);
            sq  += (v0*v0+v1*v1)+(v2*v2+v3*v3);
        }
        sum += __shfl_xor_sync(0xffffffffu, sum, 1);
        sq  += __shfl_xor_sync(0xffffffffu, sq, 1);
        sum += __shfl_xor_sync(0xffffffffu, sum, 2);
        sq  += __shfl_xor_sync(0xffffffffu, sq, 2);
        float mu   = sum * (1.f/128.f);
        float var  = sq * (1.f/128.f) - mu*mu;
        float rstd = rsqrtf(var + 1e-5f);
        float* op = out + (size_t)(m0 + row)*DIM + part*32;
        const float* gp = gamma + part*32;
        const float* bp = beta + part*32;
#pragma unroll
        for (int j = 0; j < 8; ++j) {
            float4 gv = *(const float4*)(gp + j*4);
            float4 bv = *(const float4*)(bp + j*4);
            float4 o;
            o.x = gv.x*((vals[j*4+0]-mu)*rstd) + bv.x;
            o.y = gv.y*((vals[j*4+1]-mu)*rstd) + bv.y;
            o.z = gv.z*((vals[j*4+2]-mu)*rstd) + bv.z;
            o.w = gv.w*((vals[j*4+3]-mu)*rstd) + bv.w;
            *(float4*)(op + j*4) = o;
        }
    }
}

// ---------------------------------------------------------------------------
extern "C" void kernel_launch(void* const* d_in, const int* in_sizes, int n_in,
                              void* d_out, int out_size)
{
    const float* x    = (const float*)d_in[0];
    const int*   mask = (const int*)d_in[2];
    const float* Wq   = (const float*)d_in[3];
    const float* Wk   = (const float*)d_in[4];
    const float* Wv   = (const float*)d_in[5];
    const float* Wu   = (const float*)d_in[6];
    const float* bu   = (const float*)d_in[7];
    const float* gm   = (const float*)d_in[8];
    const float* bt   = (const float*)d_in[9];
    float* out = (float*)d_out;

    cudaFuncSetAttribute(qkv3_mma, cudaFuncAttributeMaxDynamicSharedMemorySize, GEMM_SMEM);
    cudaFuncSetAttribute(mlp_mma,  cudaFuncAttributeMaxDynamicSharedMemorySize, GEMM_SMEM);
    cudaFuncSetAttribute(attn_mma, cudaFuncAttributeMaxDynamicSharedMemorySize, ATTN_SMEM);

    prep_w<<<160, 256>>>(Wq, Wk, Wv, Wu);
    qkv3_mma<<<MTOT/64, 256, GEMM_SMEM>>>(x);
    vsum_red<<<NBATCH, 512>>>();
    attn_mma<<<dim3(SEQ/QT, NBATCH), 256, ATTN_SMEM>>>(mask);
    mlp_mma<<<MTOT/64, 256, GEMM_SMEM>>>(x, bu, gm, bt, out);
}

// round 13
// speedup vs baseline: 1.9382x; 1.0392x over previous
#include <cuda_runtime.h>
#include <cstdint>

#define NBATCH 4
#define SEQ    4096
#define DIM    128
#define MTOT   (NBATCH*SEQ)
#define QT     64
#define KT     192
#define CKA    96

__device__ float g_q[MTOT*DIM];
__device__ float g_k[MTOT*DIM];
__device__ float g_v[MTOT*DIM];
__device__ float g_agg[MTOT*DIM];
__device__ float g_vsum_p[NBATCH*64*DIM];
__device__ uint32_t g_wh[(3*64+128)*DIM];   // Wq|Wk|Wv|Wu, B-layout [kp][n], fp16x2

// ---------------------------------------------------------------------------
__device__ __forceinline__ uint32_t hpack(float x0, float x1) {
    uint32_t r;
    asm("cvt.rn.f16x2.f32 %0, %1, %2;" : "=r"(r) : "f"(x1), "f"(x0));
    return r;
}
__device__ __forceinline__ float2 hunpack(uint32_t h) {
    float f0, f1;
    asm("{.reg .b16 lo,hi; mov.b32 {lo,hi}, %2; cvt.f32.f16 %0, lo; cvt.f32.f16 %1, hi;}"
        : "=f"(f0), "=f"(f1) : "r"(h));
    return make_float2(f0, f1);
}
__device__ __forceinline__ void hsplit2(float x0, float x1, uint32_t& h, uint32_t& l) {
    h = hpack(x0, x1);
    float2 hf = hunpack(h);
    l = hpack(x0 - hf.x, x1 - hf.y);
}
__device__ __forceinline__ void mma_f16(float* c, const uint32_t* a,
                                        uint32_t b0, uint32_t b1) {
    asm volatile(
        "mma.sync.aligned.m16n8k16.row.col.f32.f16.f16.f32 "
        "{%0,%1,%2,%3}, {%4,%5,%6,%7}, {%8,%9}, {%0,%1,%2,%3};"
        : "+f"(c[0]), "+f"(c[1]), "+f"(c[2]), "+f"(c[3])
        : "r"(a[0]), "r"(a[1]), "r"(a[2]), "r"(a[3]), "r"(b0), "r"(b1));
}

// ---------------------------------------------------------------------------
__global__ __launch_bounds__(256)
void prep_w(const float* __restrict__ Wq, const float* __restrict__ Wk,
            const float* __restrict__ Wv, const float* __restrict__ Wu)
{
    int o = blockIdx.x*256 + threadIdx.x;
    const float* W; int ofs, oo;
    if (o < 8192)        { W = Wq; ofs = 0;        oo = o; }
    else if (o < 16384)  { W = Wk; ofs = 64*128;   oo = o - 8192; }
    else if (o < 24576)  { W = Wv; ofs = 128*128;  oo = o - 16384; }
    else                 { W = Wu; ofs = 192*128;  oo = o - 24576; }
    int kp = oo >> 7, n = oo & 127;
    g_wh[ofs + kp*128 + n] = hpack(W[(size_t)(2*kp)*DIM + n], W[(size_t)(2*kp+1)*DIM + n]);
}

// ---------------------------------------------------------------------------
// GEMM core (BM=64): 64x128 tile, full K=128; A split hi/lo fp16, B fp16.
// ---------------------------------------------------------------------------
#define GA_STR 68
#define GB_STR 136
#define GEMM_SMEM ((2*64*GA_STR + 64*GB_STR)*4)   // 69632 B

struct GemmH64 {
    uint32_t *Ah, *Al, *Bh;

    __device__ void stage_A(const float* __restrict__ src, int m0, int tid) {
#pragma unroll
        for (int t = 0; t < 16; ++t) {
            int idx = tid + t*256;
            int row = idx >> 6, kp = idx & 63;
            float2 v = *(const float2*)(src + (size_t)(m0+row)*DIM + 2*kp);
            uint32_t h, l; hsplit2(v.x, v.y, h, l);
            Ah[row*GA_STR + kp] = h; Al[row*GA_STR + kp] = l;
        }
    }
    __device__ void stage_B(int kpo, int tid) {
#pragma unroll
        for (int t = 0; t < 8; ++t) {
            int idx = tid + t*256;
            int kp = idx >> 5, c4 = (idx & 31)*4;
            *(uint4*)&Bh[kp*GB_STR + c4] = *(const uint4*)&g_wh[(size_t)(kpo+kp)*128 + c4];
        }
    }
    // lo_term: include the A-residual MMA pass (2-term) or not (1-term)
    __device__ void run(float c[8][4], int tid, bool lo_term) {
        const int lane = tid & 31, wid = tid >> 5;
        const int grp = lane >> 2, qd = lane & 3;
        const int wm = (wid & 3) * 16, wn = (wid >> 2) * 64;
#pragma unroll
        for (int t = 0; t < 8; ++t) {
            int kp0 = 8*t;
            uint32_t ah[4], al[4];
            int r = (wm + grp)*GA_STR;
            ah[0] = Ah[r + kp0+qd];   ah[1] = Ah[r + 8*GA_STR + kp0+qd];
            ah[2] = Ah[r + kp0+qd+4]; ah[3] = Ah[r + 8*GA_STR + kp0+qd+4];
            al[0] = Al[r + kp0+qd];   al[1] = Al[r + 8*GA_STR + kp0+qd];
            al[2] = Al[r + kp0+qd+4]; al[3] = Al[r + 8*GA_STR + kp0+qd+4];
#pragma unroll
            for (int ni = 0; ni < 8; ++ni) {
                int col = wn + ni*8 + grp;
                uint32_t bh0 = Bh[(kp0+qd)*GB_STR + col];
                uint32_t bh1 = Bh[(kp0+qd+4)*GB_STR + col];
                mma_f16(c[ni], ah, bh0, bh1);
                if (lo_term) mma_f16(c[ni], al, bh0, bh1);
            }
        }
    }
};

// ---------------------------------------------------------------------------
// QKV fused (BM=64): stage x once, loop Wq/Wk/Wv; V phase single-term and
// also emits per-tile column sums.
// ---------------------------------------------------------------------------
__global__ __launch_bounds__(256, 3)
void qkv3_mma(const float* __restrict__ x)
{
    extern __shared__ uint32_t smu[];
    GemmH64 g;
    g.Ah = smu;               g.Al = g.Ah + 64*GA_STR;
    g.Bh = g.Al + 64*GA_STR;

    const int tid = threadIdx.x;
    const int m0 = blockIdx.x * 64;

    const int lane = tid & 31, wid = tid >> 5;
    const int grp = lane >> 2, qd = lane & 3;
    const int wm = (wid & 3) * 16, wn = (wid >> 2) * 64;

    g.stage_A(x, m0, tid);

    float c[8][4];
#pragma unroll 1
    for (int w = 0; w < 3; ++w) {
        if (w > 0) __syncthreads();
        g.stage_B(w*64, tid);
        __syncthreads();
#pragma unroll
        for (int ni = 0; ni < 8; ++ni)
#pragma unroll
            for (int e = 0; e < 4; ++e) c[ni][e] = 0.f;
        g.run(c, tid, w < 2);     // V projection single-term

        float* outp = (w == 0) ? g_q : (w == 1) ? g_k : g_v;
#pragma unroll
        for (int ni = 0; ni < 8; ++ni) {
            size_t r0 = (size_t)(m0 + wm + grp);
            int col = wn + ni*8 + 2*qd;
            *(float2*)(outp + r0*DIM + col)     = make_float2(c[ni][0], c[ni][1]);
            *(float2*)(outp + (r0+8)*DIM + col) = make_float2(c[ni][2], c[ni][3]);
        }
    }

    // ---- V column partial sums ----
    __syncthreads();
    float* Ys = (float*)smu;                 // [64][132]
#pragma unroll
    for (int ni = 0; ni < 8; ++ni) {
        int r0 = wm + grp;
        int col = wn + ni*8 + 2*qd;
        Ys[r0*132 + col]         = c[ni][0];
        Ys[r0*132 + col + 1]     = c[ni][1];
        Ys[(r0+8)*132 + col]     = c[ni][2];
        Ys[(r0+8)*132 + col + 1] = c[ni][3];
    }
    __syncthreads();
    {
        int col = tid & 127, half = tid >> 7;
        float s = 0.f;
#pragma unroll
        for (int r = 0; r < 32; r += 4) {
            s += Ys[(half*32 + r+0)*132 + col];
            s += Ys[(half*32 + r+1)*132 + col];
            s += Ys[(half*32 + r+2)*132 + col];
            s += Ys[(half*32 + r+3)*132 + col];
        }
        float* ps2 = Ys + 64*132;
        ps2[half*128 + col] = s;
        __syncthreads();
        if (tid < 128) {
            int b = m0 >> 12;
            int t = (m0 >> 6) & 63;
            g_vsum_p[(b*64 + t)*128 + tid] = ps2[tid] + ps2[128 + tid];
        }
    }
}

// ---------------------------------------------------------------------------
// Attention: fp16 2-term QK^T, P packed fp16, PV single-term; inline vsum
// (computed from g_vsum_p only in CTAs that contain masked query rows).
// ---------------------------------------------------------------------------
#define AQ_STR 68
#define AK_STR 68
#define AV_STR 136
#define AP_STR 196
#define PH_STR 100
#define Q_WORDS  (QT*AQ_STR)
#define KV_WORDS (CKA*AK_STR)
#define P_WORDS  (QT*AP_STR)
#define ATTN_SMEM ((2*Q_WORDS + KV_WORDS + P_WORDS)*4 + (KT+QT)*4 + 128*4)

__global__ __launch_bounds__(256, 2)
void attn_mma(const int* __restrict__ mask)
{
    extern __shared__ uint32_t smu[];
    uint32_t* Qh = smu;
    uint32_t* Ql = Qh + Q_WORDS;
    uint32_t* KV = Ql + Q_WORDS;
    float*    Ps = (float*)(KV + KV_WORDS);
    int*     msk = (int*)(Ps + P_WORDS);
    int*     qmk = msk + KT;
    float* vsum_s = (float*)(qmk + QT);   // [128]

    uint32_t* Ks = KV;
    uint32_t* Vs = KV;
    uint32_t* Ph = Qh;

    const int tid = threadIdx.x;
    const int b  = blockIdx.y;
    const int q0 = blockIdx.x * QT;
    const int kbase = q0 - 64;

    if (tid < KT) {
        int j = kbase + tid;
        msk[tid] = (j >= 0 && j < SEQ) ? mask[b*SEQ + j] : 0;
    }
    if (tid < QT) qmk[tid] = mask[b*SEQ + q0 + tid];

#pragma unroll
    for (int t = 0; t < 16; ++t) {
        int idx = tid + t*256;
        int row = idx >> 6, kp = idx & 63;
        float2 v = *(const float2*)(g_q + ((size_t)b*SEQ + q0 + row)*DIM + 2*kp);
        uint32_t h, l; hsplit2(v.x, v.y, h, l);
        Qh[row*AQ_STR + kp] = h; Ql[row*AQ_STR + kp] = l;
    }
#pragma unroll
    for (int t = 0; t < 24; ++t) {
        int idx = tid + t*256;
        int row = idx >> 6, kp = idx & 63;
        int j = kbase + row;
        uint32_t h = 0;
        if (j >= 0 && j < SEQ) {
            float2 v = *(const float2*)(g_k + ((size_t)b*SEQ + j)*DIM + 2*kp);
            h = hpack(v.x, v.y);
        }
        Ks[row*AK_STR + kp] = h;
    }
    __syncthreads();

    // does this tile contain masked query rows?
    int need_vsum = __syncthreads_or((tid < QT) ? (qmk[tid] == 0) : 0);
    if (need_vsum && tid < 128) {
        float s = 0.f;
#pragma unroll 4
        for (int t = 0; t < 64; ++t) s += g_vsum_p[(b*64 + t)*128 + tid];
        vsum_s[tid] = s * (1.f/(float)SEQ);
    }

    const int lane = tid & 31, wid = tid >> 5;
    const int grp = lane >> 2, qd = lane & 3;
    const float scale = 0.08838834764831845f;

    // ---- S = Q K^T, 2 chunks of 96 keys; warps 4(m) x 2(n), band skip ----
    {
        const int wm = (wid & 3) * 16;
        const int wn = (wid >> 2) * 48;
#pragma unroll 1
        for (int c = 0; c < 2; ++c) {
            float cs[6][4];
#pragma unroll
            for (int ni = 0; ni < 6; ++ni)
#pragma unroll
                for (int e = 0; e < 4; ++e) cs[ni][e] = 0.f;

            int cb = c*CKA + wn;
            bool skip = (cb + 47 < wm) || (cb > wm + 143);
            if (!skip) {
#pragma unroll
                for (int t = 0; t < 8; ++t) {
                    int kp0 = 8*t;
                    uint32_t ah[4], al[4];
                    int r = (wm + grp)*AQ_STR;
                    ah[0] = Qh[r + kp0+qd];   ah[1] = Qh[r + 8*AQ_STR + kp0+qd];
                    ah[2] = Qh[r + kp0+qd+4]; ah[3] = Qh[r + 8*AQ_STR + kp0+qd+4];
                    al[0] = Ql[r + kp0+qd];   al[1] = Ql[r + 8*AQ_STR + kp0+qd];
                    al[2] = Ql[r + kp0+qd+4]; al[3] = Ql[r + 8*AQ_STR + kp0+qd+4];
#pragma unroll
                    for (int ni = 0; ni < 6; ++ni) {
                        int col = (wn + ni*8 + grp)*AK_STR;
                        uint32_t bh0 = Ks[col + kp0+qd];
                        uint32_t bh1 = Ks[col + kp0+qd+4];
                        mma_f16(cs[ni], ah, bh0, bh1);
                        mma_f16(cs[ni], al, bh0, bh1);
                    }
                }
            }
#pragma unroll
            for (int ni = 0; ni < 6; ++ni) {
#pragma unroll
                for (int e = 0; e < 4; ++e) {
                    int qi = wm + grp + (e >> 1)*8;
                    int jg = cb + ni*8 + 2*qd + (e & 1);
                    bool valid = msk[jg] && (jg >= qi) && (jg <= qi + 128);
                    Ps[qi*AP_STR + jg] = valid ? cs[ni][e]*scale : -1e9f;
                }
            }
            __syncthreads();
            if (c == 0) {
#pragma unroll
                for (int t = 0; t < 24; ++t) {
                    int idx = tid + t*256;
                    int row = idx >> 6, kp = idx & 63;
                    int j = kbase + CKA + row;
                    uint32_t h = 0;
                    if (j >= 0 && j < SEQ) {
                        float2 v = *(const float2*)(g_k + ((size_t)b*SEQ + j)*DIM + 2*kp);
                        h = hpack(v.x, v.y);
                    }
                    Ks[row*AK_STR + kp] = h;
                }
                __syncthreads();
            }
        }
    }

    // stage V chunk 0
#pragma unroll
    for (int t = 0; t < 6; ++t) {
        int idx = tid + t*256;
        int kp = idx >> 5, c4 = (idx & 31)*4;
        int j0 = kbase + 2*kp, j1 = j0 + 1;
        float4 v0 = make_float4(0,0,0,0), v1 = make_float4(0,0,0,0);
        if (j0 >= 0 && j0 < SEQ) v0 = *(const float4*)(g_v + ((size_t)b*SEQ + j0)*DIM + c4);
        if (j1 >= 0 && j1 < SEQ) v1 = *(const float4*)(g_v + ((size_t)b*SEQ + j1)*DIM + c4);
        *(uint4*)&Vs[kp*AV_STR + c4] = make_uint4(
            hpack(v0.x, v1.x), hpack(v0.y, v1.y), hpack(v0.z, v1.z), hpack(v0.w, v1.w));
    }

    // softmax: 4 threads per row; pack normalized P into fp16 Ph
    {
        int qi = tid >> 2, lg = tid & 3;
        float mx = -3.4e38f;
        for (int j = lg; j < KT; j += 4) mx = fmaxf(mx, Ps[qi*AP_STR + j]);
        mx = fmaxf(mx, __shfl_xor_sync(0xffffffffu, mx, 1));
        mx = fmaxf(mx, __shfl_xor_sync(0xffffffffu, mx, 2));
        float s = 0.f;
        for (int j = lg; j < KT; j += 4) {
            float e = __expf(Ps[qi*AP_STR + j] - mx);
            Ps[qi*AP_STR + j] = e;
            s += e;
        }
        s += __shfl_xor_sync(0xffffffffu, s, 1);
        s += __shfl_xor_sync(0xffffffffu, s, 2);
        float inv = 1.f / s;
        for (int kp = lg; kp < CKA; kp += 4) {
            float e0 = Ps[qi*AP_STR + 2*kp];
            float e1 = Ps[qi*AP_STR + 2*kp + 1];
            Ph[qi*PH_STR + kp] = hpack(e0*inv, e1*inv);
        }
    }
    __syncthreads();

    // ---- agg = P V (single-term), 2 chunks of 48 key-pairs; warps 2m x 4n ----
    {
        const int wm = (wid & 1) * 32;
        const int wn = (wid >> 1) * 32;
        float co[2][4][4];
#pragma unroll
        for (int mi = 0; mi < 2; ++mi)
#pragma unroll
            for (int ni = 0; ni < 4; ++ni)
#pragma unroll
                for (int e = 0; e < 4; ++e) co[mi][ni][e] = 0.f;

#pragma unroll 1
        for (int c = 0; c < 2; ++c) {
#pragma unroll
            for (int t = 0; t < 6; ++t) {
                int ck = c*48 + t*8;
                uint32_t ah[2][4];
#pragma unroll
                for (int mi = 0; mi < 2; ++mi) {
                    int r = (wm + mi*16 + grp)*PH_STR + ck + qd;
                    ah[mi][0] = Ph[r];
                    ah[mi][1] = Ph[r + 8*PH_STR];
                    ah[mi][2] = Ph[r + 4];
                    ah[mi][3] = Ph[r + 8*PH_STR + 4];
                }
#pragma unroll
                for (int ni = 0; ni < 4; ++ni) {
                    int col = wn + ni*8 + grp;
                    uint32_t bh0 = Vs[(t*8+qd)*AV_STR + col];
                    uint32_t bh1 = Vs[(t*8+qd+4)*AV_STR + col];
#pragma unroll
                    for (int mi = 0; mi < 2; ++mi)
                        mma_f16(co[mi][ni], ah[mi], bh0, bh1);
                }
            }
            if (c == 0) {
                __syncthreads();
#pragma unroll
                for (int t = 0; t < 6; ++t) {
                    int idx = tid + t*256;
                    int kp = idx >> 5, c4 = (idx & 31)*4;
                    int j0 = kbase + CKA + 2*kp, j1 = j0 + 1;
                    float4 v0 = make_float4(0,0,0,0), v1 = make_float4(0,0,0,0);
                    if (j0 >= 0 && j0 < SEQ) v0 = *(const float4*)(g_v + ((size_t)b*SEQ + j0)*DIM + c4);
                    if (j1 >= 0 && j1 < SEQ) v1 = *(const float4*)(g_v + ((size_t)b*SEQ + j1)*DIM + c4);
                    *(uint4*)&Vs[kp*AV_STR + c4] = make_uint4(
                        hpack(v0.x, v1.x), hpack(v0.y, v1.y), hpack(v0.z, v1.z), hpack(v0.w, v1.w));
                }
                __syncthreads();
            }
        }

        // epilogue: write agg; masked query rows -> vsum_s
#pragma unroll
        for (int mi = 0; mi < 2; ++mi)
#pragma unroll
            for (int ni = 0; ni < 4; ++ni) {
                int r0 = wm + mi*16 + grp;
                int col = wn + ni*8 + 2*qd;
#pragma unroll
                for (int half = 0; half < 2; ++half) {
                    int qi = r0 + half*8;
                    float v0 = co[mi][ni][half*2], v1 = co[mi][ni][half*2+1];
                    if (!qmk[qi]) {
                        v0 = vsum_s[col];
                        v1 = vsum_s[col + 1];
                    }
                    size_t row = (size_t)b*SEQ + q0 + qi;
                    *(float2*)(g_agg + row*DIM + col) = make_float2(v0, v1);
                }
            }
    }
}

// ---------------------------------------------------------------------------
// MLP (BM=64, K=256 via 2 phases) + fused bias/ReLU/residual/LN.
// ---------------------------------------------------------------------------
__global__ __launch_bounds__(256, 3)
void mlp_mma(const float* __restrict__ x, const float* __restrict__ bu,
             const float* __restrict__ gamma, const float* __restrict__ beta,
             float* __restrict__ out)
{
    extern __shared__ uint32_t smu[];
    GemmH64 g;
    g.Ah = smu;               g.Al = g.Ah + 64*GA_STR;
    g.Bh = g.Al + 64*GA_STR;

    const int tid = threadIdx.x;
    const int m0 = blockIdx.x * 64;

    float c[8][4];
#pragma unroll
    for (int ni = 0; ni < 8; ++ni)
#pragma unroll
        for (int e = 0; e < 4; ++e) c[ni][e] = 0.f;

#pragma unroll 1
    for (int ph = 0; ph < 2; ++ph) {
        const float* Asrc = (ph == 0) ? x : (const float*)g_agg;
        g.stage_A(Asrc, m0, tid);
        g.stage_B(192 + ph*64, tid);
        __syncthreads();
        g.run(c, tid, true);
        __syncthreads();
    }

    float* Ys = (float*)smu;  // [64][132]
    const int lane = tid & 31, wid = tid >> 5;
    const int grp = lane >> 2, qd = lane & 3;
    const int wm = (wid & 3) * 16, wn = (wid >> 2) * 64;
#pragma unroll
    for (int ni = 0; ni < 8; ++ni) {
        int r0 = wm + grp;
        int col = wn + ni*8 + 2*qd;
        float b0 = __ldg(bu + col), b1 = __ldg(bu + col + 1);
        Ys[r0*132 + col]         = fmaxf(c[ni][0] + b0, 0.f);
        Ys[r0*132 + col + 1]     = fmaxf(c[ni][1] + b1, 0.f);
        Ys[(r0+8)*132 + col]     = fmaxf(c[ni][2] + b0, 0.f);
        Ys[(r0+8)*132 + col + 1] = fmaxf(c[ni][3] + b1, 0.f);
    }
    __syncthreads();

    {
        int row = tid >> 2;
        int part = tid & 3;
        const float* xr = x + (size_t)(m0 + row)*DIM + part*32;
        const float* yr = Ys + row*132 + part*32;
        float vals[32];
        float sum = 0.f, sq = 0.f;
#pragma unroll
        for (int j = 0; j < 8; ++j) {
            float4 xv = *(const float4*)(xr + j*4);
            float4 yv = *(const float4*)(yr + j*4);
            float v0 = yv.x+xv.x, v1 = yv.y+xv.y, v2 = yv.z+xv.z, v3 = yv.w+xv.w;
            vals[j*4+0]=v0; vals[j*4+1]=v1; vals[j*4+2]=v2; vals[j*4+3]=v3;
            sum += (v0+v1)+(v2+v3);
            sq  += (v0*v0+v1*v1)+(v2*v2+v3*v3);
        }
        sum += __shfl_xor_sync(0xffffffffu, sum, 1);
        sq  += __shfl_xor_sync(0xffffffffu, sq, 1);
        sum += __shfl_xor_sync(0xffffffffu, sum, 2);
        sq  += __shfl_xor_sync(0xffffffffu, sq, 2);
        float mu   = sum * (1.f/128.f);
        float var  = sq * (1.f/128.f) - mu*mu;
        float rstd = rsqrtf(var + 1e-5f);
        float* op = out + (size_t)(m0 + row)*DIM + part*32;
        const float* gp = gamma + part*32;
        const float* bp = beta + part*32;
#pragma unroll
        for (int j = 0; j < 8; ++j) {
            float4 gv = *(const float4*)(gp + j*4);
            float4 bv = *(const float4*)(bp + j*4);
            float4 o;
            o.x = gv.x*((vals[j*4+0]-mu)*rstd) + bv.x;
            o.y = gv.y*((vals[j*4+1]-mu)*rstd) + bv.y;
            o.z = gv.z*((vals[j*4+2]-mu)*rstd) + bv.z;
            o.w = gv.w*((vals[j*4+3]-mu)*rstd) + bv.w;
            *(float4*)(op + j*4) = o;
        }
    }
}

// ---------------------------------------------------------------------------
extern "C" void kernel_launch(void* const* d_in, const int* in_sizes, int n_in,
                              void* d_out, int out_size)
{
    const float* x    = (const float*)d_in[0];
    const int*   mask = (const int*)d_in[2];
    const float* Wq   = (const float*)d_in[3];
    const float* Wk   = (const float*)d_in[4];
    const float* Wv   = (const float*)d_in[5];
    const float* Wu   = (const float*)d_in[6];
    const float* bu   = (const float*)d_in[7];
    const float* gm   = (const float*)d_in[8];
    const float* bt   = (const float*)d_in[9];
    float* out = (float*)d_out;

    cudaFuncSetAttribute(qkv3_mma, cudaFuncAttributeMaxDynamicSharedMemorySize, GEMM_SMEM);
    cudaFuncSetAttribute(mlp_mma,  cudaFuncAttributeMaxDynamicSharedMemorySize, GEMM_SMEM);
    cudaFuncSetAttribute(attn_mma, cudaFuncAttributeMaxDynamicSharedMemorySize, ATTN_SMEM);

    prep_w<<<160, 256>>>(Wq, Wk, Wv, Wu);
    qkv3_mma<<<MTOT/64, 256, GEMM_SMEM>>>(x);
    attn_mma<<<dim3(SEQ/QT, NBATCH), 256, ATTN_SMEM>>>(mask);
    mlp_mma<<<MTOT/64, 256, GEMM_SMEM>>>(x, bu, gm, bt, out);
}

// round 14
// speedup vs baseline: 1.9961x; 1.0299x over previous
#include <cuda_runtime.h>
#include <cstdint>

#define NBATCH 4
#define SEQ    4096
#define DIM    128
#define MTOT   (NBATCH*SEQ)
#define QT     64
#define KT     192
#define CKA    96

__device__ float g_q[MTOT*DIM];
__device__ float g_k[MTOT*DIM];
__device__ float g_v[MTOT*DIM];
__device__ float g_agg[MTOT*DIM];
__device__ float g_vsum_p[NBATCH*64*DIM];
__device__ uint32_t g_wh[(3*64+128)*DIM];   // Wq|Wk|Wv|Wu, B-layout [kp][n], fp16x2

// ---------------------------------------------------------------------------
__device__ __forceinline__ uint32_t hpack(float x0, float x1) {
    uint32_t r;
    asm("cvt.rn.f16x2.f32 %0, %1, %2;" : "=r"(r) : "f"(x1), "f"(x0));
    return r;
}
__device__ __forceinline__ float2 hunpack(uint32_t h) {
    float f0, f1;
    asm("{.reg .b16 lo,hi; mov.b32 {lo,hi}, %2; cvt.f32.f16 %0, lo; cvt.f32.f16 %1, hi;}"
        : "=f"(f0), "=f"(f1) : "r"(h));
    return make_float2(f0, f1);
}
__device__ __forceinline__ void hsplit2(float x0, float x1, uint32_t& h, uint32_t& l) {
    h = hpack(x0, x1);
    float2 hf = hunpack(h);
    l = hpack(x0 - hf.x, x1 - hf.y);
}
__device__ __forceinline__ void mma_f16(float* c, const uint32_t* a,
                                        uint32_t b0, uint32_t b1) {
    asm volatile(
        "mma.sync.aligned.m16n8k16.row.col.f32.f16.f16.f32 "
        "{%0,%1,%2,%3}, {%4,%5,%6,%7}, {%8,%9}, {%0,%1,%2,%3};"
        : "+f"(c[0]), "+f"(c[1]), "+f"(c[2]), "+f"(c[3])
        : "r"(a[0]), "r"(a[1]), "r"(a[2]), "r"(a[3]), "r"(b0), "r"(b1));
}

// ---------------------------------------------------------------------------
__global__ __launch_bounds__(256)
void prep_w(const float* __restrict__ Wq, const float* __restrict__ Wk,
            const float* __restrict__ Wv, const float* __restrict__ Wu)
{
    int o = blockIdx.x*256 + threadIdx.x;
    const float* W; int ofs, oo;
    if (o < 8192)        { W = Wq; ofs = 0;        oo = o; }
    else if (o < 16384)  { W = Wk; ofs = 64*128;   oo = o - 8192; }
    else if (o < 24576)  { W = Wv; ofs = 128*128;  oo = o - 16384; }
    else                 { W = Wu; ofs = 192*128;  oo = o - 24576; }
    int kp = oo >> 7, n = oo & 127;
    g_wh[ofs + kp*128 + n] = hpack(W[(size_t)(2*kp)*DIM + n], W[(size_t)(2*kp+1)*DIM + n]);
}

// ---------------------------------------------------------------------------
// GEMM core (BM=64, 512 threads): 64x128 tile, full K=128.
// 16 warps as 4(m) x 4(n); per warp 1 m-frag x 4 n-frags.
// ---------------------------------------------------------------------------
#define GA_STR 68
#define GB_STR 136
#define GEMM_SMEM ((2*64*GA_STR + 64*GB_STR)*4)   // 69632 B

struct GemmH512 {
    uint32_t *Ah, *Al, *Bh;

    __device__ void stage_A(const float* __restrict__ src, int m0, int tid) {
#pragma unroll
        for (int t = 0; t < 8; ++t) {
            int idx = tid + t*512;
            int row = idx >> 6, kp = idx & 63;
            float2 v = *(const float2*)(src + (size_t)(m0+row)*DIM + 2*kp);
            uint32_t h, l; hsplit2(v.x, v.y, h, l);
            Ah[row*GA_STR + kp] = h; Al[row*GA_STR + kp] = l;
        }
    }
    __device__ void stage_A1(const float* __restrict__ src, int m0, int tid) {
#pragma unroll
        for (int t = 0; t < 8; ++t) {
            int idx = tid + t*512;
            int row = idx >> 6, kp = idx & 63;
            float2 v = *(const float2*)(src + (size_t)(m0+row)*DIM + 2*kp);
            Ah[row*GA_STR + kp] = hpack(v.x, v.y);
        }
    }
    __device__ void stage_B(int kpo, int tid) {
#pragma unroll
        for (int t = 0; t < 4; ++t) {
            int idx = tid + t*512;
            int kp = idx >> 5, c4 = (idx & 31)*4;
            *(uint4*)&Bh[kp*GB_STR + c4] = *(const uint4*)&g_wh[(size_t)(kpo+kp)*128 + c4];
        }
    }
    __device__ void run(float c[4][4], int tid, bool lo_term) {
        const int lane = tid & 31, wid = tid >> 5;
        const int grp = lane >> 2, qd = lane & 3;
        const int wm = (wid & 3) * 16, wn = (wid >> 2) * 32;
#pragma unroll
        for (int t = 0; t < 8; ++t) {
            int kp0 = 8*t;
            uint32_t ah[4], al[4];
            int r = (wm + grp)*GA_STR;
            ah[0] = Ah[r + kp0+qd];   ah[1] = Ah[r + 8*GA_STR + kp0+qd];
            ah[2] = Ah[r + kp0+qd+4]; ah[3] = Ah[r + 8*GA_STR + kp0+qd+4];
            if (lo_term) {
                al[0] = Al[r + kp0+qd];   al[1] = Al[r + 8*GA_STR + kp0+qd];
                al[2] = Al[r + kp0+qd+4]; al[3] = Al[r + 8*GA_STR + kp0+qd+4];
            }
#pragma unroll
            for (int ni = 0; ni < 4; ++ni) {
                int col = wn + ni*8 + grp;
                uint32_t bh0 = Bh[(kp0+qd)*GB_STR + col];
                uint32_t bh1 = Bh[(kp0+qd+4)*GB_STR + col];
                mma_f16(c[ni], ah, bh0, bh1);
                if (lo_term) mma_f16(c[ni], al, bh0, bh1);
            }
        }
    }
};

// ---------------------------------------------------------------------------
// QKV fused (BM=64, 512 thr): stage x once, loop Wq/Wk/Wv; V single-term,
// V phase also emits per-tile column sums.
// ---------------------------------------------------------------------------
__global__ __launch_bounds__(512, 2)
void qkv3_mma(const float* __restrict__ x)
{
    extern __shared__ uint32_t smu[];
    GemmH512 g;
    g.Ah = smu;               g.Al = g.Ah + 64*GA_STR;
    g.Bh = g.Al + 64*GA_STR;

    const int tid = threadIdx.x;
    const int m0 = blockIdx.x * 64;

    const int lane = tid & 31, wid = tid >> 5;
    const int grp = lane >> 2, qd = lane & 3;
    const int wm = (wid & 3) * 16, wn = (wid >> 2) * 32;

    g.stage_A(x, m0, tid);

    float c[4][4];
#pragma unroll 1
    for (int w = 0; w < 3; ++w) {
        if (w > 0) __syncthreads();
        g.stage_B(w*64, tid);
        __syncthreads();
#pragma unroll
        for (int ni = 0; ni < 4; ++ni)
#pragma unroll
            for (int e = 0; e < 4; ++e) c[ni][e] = 0.f;
        g.run(c, tid, w < 2);     // V projection single-term

        float* outp = (w == 0) ? g_q : (w == 1) ? g_k : g_v;
#pragma unroll
        for (int ni = 0; ni < 4; ++ni) {
            size_t r0 = (size_t)(m0 + wm + grp);
            int col = wn + ni*8 + 2*qd;
            *(float2*)(outp + r0*DIM + col)     = make_float2(c[ni][0], c[ni][1]);
            *(float2*)(outp + (r0+8)*DIM + col) = make_float2(c[ni][2], c[ni][3]);
        }
    }

    // ---- V column partial sums (c holds the V tile) ----
    __syncthreads();
    float* Ys = (float*)smu;                 // [64][132]
#pragma unroll
    for (int ni = 0; ni < 4; ++ni) {
        int r0 = wm + grp;
        int col = wn + ni*8 + 2*qd;
        Ys[r0*132 + col]         = c[ni][0];
        Ys[r0*132 + col + 1]     = c[ni][1];
        Ys[(r0+8)*132 + col]     = c[ni][2];
        Ys[(r0+8)*132 + col + 1] = c[ni][3];
    }
    __syncthreads();
    {
        int col = tid & 127, q = tid >> 7;   // q: 0..3
        float s = 0.f;
#pragma unroll
        for (int r = 0; r < 16; r += 4) {
            s += Ys[(q*16 + r+0)*132 + col];
            s += Ys[(q*16 + r+1)*132 + col];
            s += Ys[(q*16 + r+2)*132 + col];
            s += Ys[(q*16 + r+3)*132 + col];
        }
        float* ps2 = Ys + 64*132;
        ps2[q*128 + col] = s;
        __syncthreads();
        if (tid < 128) {
            int b = m0 >> 12;
            int t = (m0 >> 6) & 63;
            g_vsum_p[(b*64 + t)*128 + tid] =
                (ps2[tid] + ps2[128 + tid]) + (ps2[256 + tid] + ps2[384 + tid]);
        }
    }
}

// ---------------------------------------------------------------------------
// Attention (unchanged from round 13).
// ---------------------------------------------------------------------------
#define AQ_STR 68
#define AK_STR 68
#define AV_STR 136
#define AP_STR 196
#define PH_STR 100
#define Q_WORDS  (QT*AQ_STR)
#define KV_WORDS (CKA*AK_STR)
#define P_WORDS  (QT*AP_STR)
#define ATTN_SMEM ((2*Q_WORDS + KV_WORDS + P_WORDS)*4 + (KT+QT)*4 + 128*4)

__global__ __launch_bounds__(256, 2)
void attn_mma(const int* __restrict__ mask)
{
    extern __shared__ uint32_t smu[];
    uint32_t* Qh = smu;
    uint32_t* Ql = Qh + Q_WORDS;
    uint32_t* KV = Ql + Q_WORDS;
    float*    Ps = (float*)(KV + KV_WORDS);
    int*     msk = (int*)(Ps + P_WORDS);
    int*     qmk = msk + KT;
    float* vsum_s = (float*)(qmk + QT);   // [128]

    uint32_t* Ks = KV;
    uint32_t* Vs = KV;
    uint32_t* Ph = Qh;

    const int tid = threadIdx.x;
    const int b  = blockIdx.y;
    const int q0 = blockIdx.x * QT;
    const int kbase = q0 - 64;

    if (tid < KT) {
        int j = kbase + tid;
        msk[tid] = (j >= 0 && j < SEQ) ? mask[b*SEQ + j] : 0;
    }
    if (tid < QT) qmk[tid] = mask[b*SEQ + q0 + tid];

#pragma unroll
    for (int t = 0; t < 16; ++t) {
        int idx = tid + t*256;
        int row = idx >> 6, kp = idx & 63;
        float2 v = *(const float2*)(g_q + ((size_t)b*SEQ + q0 + row)*DIM + 2*kp);
        uint32_t h, l; hsplit2(v.x, v.y, h, l);
        Qh[row*AQ_STR + kp] = h; Ql[row*AQ_STR + kp] = l;
    }
#pragma unroll
    for (int t = 0; t < 24; ++t) {
        int idx = tid + t*256;
        int row = idx >> 6, kp = idx & 63;
        int j = kbase + row;
        uint32_t h = 0;
        if (j >= 0 && j < SEQ) {
            float2 v = *(const float2*)(g_k + ((size_t)b*SEQ + j)*DIM + 2*kp);
            h = hpack(v.x, v.y);
        }
        Ks[row*AK_STR + kp] = h;
    }
    __syncthreads();

    int need_vsum = __syncthreads_or((tid < QT) ? (qmk[tid] == 0) : 0);
    if (need_vsum && tid < 128) {
        float s = 0.f;
#pragma unroll 4
        for (int t = 0; t < 64; ++t) s += g_vsum_p[(b*64 + t)*128 + tid];
        vsum_s[tid] = s * (1.f/(float)SEQ);
    }

    const int lane = tid & 31, wid = tid >> 5;
    const int grp = lane >> 2, qd = lane & 3;
    const float scale = 0.08838834764831845f;

    {
        const int wm = (wid & 3) * 16;
        const int wn = (wid >> 2) * 48;
#pragma unroll 1
        for (int c = 0; c < 2; ++c) {
            float cs[6][4];
#pragma unroll
            for (int ni = 0; ni < 6; ++ni)
#pragma unroll
                for (int e = 0; e < 4; ++e) cs[ni][e] = 0.f;

            int cb = c*CKA + wn;
            bool skip = (cb + 47 < wm) || (cb > wm + 143);
            if (!skip) {
#pragma unroll
                for (int t = 0; t < 8; ++t) {
                    int kp0 = 8*t;
                    uint32_t ah[4], al[4];
                    int r = (wm + grp)*AQ_STR;
                    ah[0] = Qh[r + kp0+qd];   ah[1] = Qh[r + 8*AQ_STR + kp0+qd];
                    ah[2] = Qh[r + kp0+qd+4]; ah[3] = Qh[r + 8*AQ_STR + kp0+qd+4];
                    al[0] = Ql[r + kp0+qd];   al[1] = Ql[r + 8*AQ_STR + kp0+qd];
                    al[2] = Ql[r + kp0+qd+4]; al[3] = Ql[r + 8*AQ_STR + kp0+qd+4];
#pragma unroll
                    for (int ni = 0; ni < 6; ++ni) {
                        int col = (wn + ni*8 + grp)*AK_STR;
                        uint32_t bh0 = Ks[col + kp0+qd];
                        uint32_t bh1 = Ks[col + kp0+qd+4];
                        mma_f16(cs[ni], ah, bh0, bh1);
                        mma_f16(cs[ni], al, bh0, bh1);
                    }
                }
            }
#pragma unroll
            for (int ni = 0; ni < 6; ++ni) {
#pragma unroll
                for (int e = 0; e < 4; ++e) {
                    int qi = wm + grp + (e >> 1)*8;
                    int jg = cb + ni*8 + 2*qd + (e & 1);
                    bool valid = msk[jg] && (jg >= qi) && (jg <= qi + 128);
                    Ps[qi*AP_STR + jg] = valid ? cs[ni][e]*scale : -1e9f;
                }
            }
            __syncthreads();
            if (c == 0) {
#pragma unroll
                for (int t = 0; t < 24; ++t) {
                    int idx = tid + t*256;
                    int row = idx >> 6, kp = idx & 63;
                    int j = kbase + CKA + row;
                    uint32_t h = 0;
                    if (j >= 0 && j < SEQ) {
                        float2 v = *(const float2*)(g_k + ((size_t)b*SEQ + j)*DIM + 2*kp);
                        h = hpack(v.x, v.y);
                    }
                    Ks[row*AK_STR + kp] = h;
                }
                __syncthreads();
            }
        }
    }

#pragma unroll
    for (int t = 0; t < 6; ++t) {
        int idx = tid + t*256;
        int kp = idx >> 5, c4 = (idx & 31)*4;
        int j0 = kbase + 2*kp, j1 = j0 + 1;
        float4 v0 = make_float4(0,0,0,0), v1 = make_float4(0,0,0,0);
        if (j0 >= 0 && j0 < SEQ) v0 = *(const float4*)(g_v + ((size_t)b*SEQ + j0)*DIM + c4);
        if (j1 >= 0 && j1 < SEQ) v1 = *(const float4*)(g_v + ((size_t)b*SEQ + j1)*DIM + c4);
        *(uint4*)&Vs[kp*AV_STR + c4] = make_uint4(
            hpack(v0.x, v1.x), hpack(v0.y, v1.y), hpack(v0.z, v1.z), hpack(v0.w, v1.w));
    }

    {
        int qi = tid >> 2, lg = tid & 3;
        float mx = -3.4e38f;
        for (int j = lg; j < KT; j += 4) mx = fmaxf(mx, Ps[qi*AP_STR + j]);
        mx = fmaxf(mx, __shfl_xor_sync(0xffffffffu, mx, 1));
        mx = fmaxf(mx, __shfl_xor_sync(0xffffffffu, mx, 2));
        float s = 0.f;
        for (int j = lg; j < KT; j += 4) {
            float e = __expf(Ps[qi*AP_STR + j] - mx);
            Ps[qi*AP_STR + j] = e;
            s += e;
        }
        s += __shfl_xor_sync(0xffffffffu, s, 1);
        s += __shfl_xor_sync(0xffffffffu, s, 2);
        float inv = 1.f / s;
        for (int kp = lg; kp < CKA; kp += 4) {
            float e0 = Ps[qi*AP_STR + 2*kp];
            float e1 = Ps[qi*AP_STR + 2*kp + 1];
            Ph[qi*PH_STR + kp] = hpack(e0*inv, e1*inv);
        }
    }
    __syncthreads();

    {
        const int wm = (wid & 1) * 32;
        const int wn = (wid >> 1) * 32;
        float co[2][4][4];
#pragma unroll
        for (int mi = 0; mi < 2; ++mi)
#pragma unroll
            for (int ni = 0; ni < 4; ++ni)
#pragma unroll
                for (int e = 0; e < 4; ++e) co[mi][ni][e] = 0.f;

#pragma unroll 1
        for (int c = 0; c < 2; ++c) {
#pragma unroll
            for (int t = 0; t < 6; ++t) {
                int ck = c*48 + t*8;
                uint32_t ah[2][4];
#pragma unroll
                for (int mi = 0; mi < 2; ++mi) {
                    int r = (wm + mi*16 + grp)*PH_STR + ck + qd;
                    ah[mi][0] = Ph[r];
                    ah[mi][1] = Ph[r + 8*PH_STR];
                    ah[mi][2] = Ph[r + 4];
                    ah[mi][3] = Ph[r + 8*PH_STR + 4];
                }
#pragma unroll
                for (int ni = 0; ni < 4; ++ni) {
                    int col = wn + ni*8 + grp;
                    uint32_t bh0 = Vs[(t*8+qd)*AV_STR + col];
                    uint32_t bh1 = Vs[(t*8+qd+4)*AV_STR + col];
#pragma unroll
                    for (int mi = 0; mi < 2; ++mi)
                        mma_f16(co[mi][ni], ah[mi], bh0, bh1);
                }
            }
            if (c == 0) {
                __syncthreads();
#pragma unroll
                for (int t = 0; t < 6; ++t) {
                    int idx = tid + t*256;
                    int kp = idx >> 5, c4 = (idx & 31)*4;
                    int j0 = kbase + CKA + 2*kp, j1 = j0 + 1;
                    float4 v0 = make_float4(0,0,0,0), v1 = make_float4(0,0,0,0);
                    if (j0 >= 0 && j0 < SEQ) v0 = *(const float4*)(g_v + ((size_t)b*SEQ + j0)*DIM + c4);
                    if (j1 >= 0 && j1 < SEQ) v1 = *(const float4*)(g_v + ((size_t)b*SEQ + j1)*DIM + c4);
                    *(uint4*)&Vs[kp*AV_STR + c4] = make_uint4(
                        hpack(v0.x, v1.x), hpack(v0.y, v1.y), hpack(v0.z, v1.z), hpack(v0.w, v1.w));
                }
                __syncthreads();
            }
        }

#pragma unroll
        for (int mi = 0; mi < 2; ++mi)
#pragma unroll
            for (int ni = 0; ni < 4; ++ni) {
                int r0 = wm + mi*16 + grp;
                int col = wn + ni*8 + 2*qd;
#pragma unroll
                for (int half = 0; half < 2; ++half) {
                    int qi = r0 + half*8;
                    float v0 = co[mi][ni][half*2], v1 = co[mi][ni][half*2+1];
                    if (!qmk[qi]) {
                        v0 = vsum_s[col];
                        v1 = vsum_s[col + 1];
                    }
                    size_t row = (size_t)b*SEQ + q0 + qi;
                    *(float2*)(g_agg + row*DIM + col) = make_float2(v0, v1);
                }
            }
    }
}

// ---------------------------------------------------------------------------
// MLP (BM=64, 512 thr, K=256 via 2 phases; x 2-term, agg 1-term)
// + fused bias/ReLU/residual/LN.
// ---------------------------------------------------------------------------
__global__ __launch_bounds__(512, 2)
void mlp_mma(const float* __restrict__ x, const float* __restrict__ bu,
             const float* __restrict__ gamma, const float* __restrict__ beta,
             float* __restrict__ out)
{
    extern __shared__ uint32_t smu[];
    GemmH512 g;
    g.Ah = smu;               g.Al = g.Ah + 64*GA_STR;
    g.Bh = g.Al + 64*GA_STR;

    const int tid = threadIdx.x;
    const int m0 = blockIdx.x * 64;

    float c[4][4];
#pragma unroll
    for (int ni = 0; ni < 4; ++ni)
#pragma unroll
        for (int e = 0; e < 4; ++e) c[ni][e] = 0.f;

#pragma unroll 1
    for (int ph = 0; ph < 2; ++ph) {
        if (ph == 0) g.stage_A(x, m0, tid);
        else         g.stage_A1((const float*)g_agg, m0, tid);
        g.stage_B(192 + ph*64, tid);
        __syncthreads();
        g.run(c, tid, ph == 0);
        __syncthreads();
    }

    float* Ys = (float*)smu;  // [64][132]
    const int lane = tid & 31, wid = tid >> 5;
    const int grp = lane >> 2, qd = lane & 3;
    const int wm = (wid & 3) * 16, wn = (wid >> 2) * 32;
#pragma unroll
    for (int ni = 0; ni < 4; ++ni) {
        int r0 = wm + grp;
        int col = wn + ni*8 + 2*qd;
        float b0 = __ldg(bu + col), b1 = __ldg(bu + col + 1);
        Ys[r0*132 + col]         = fmaxf(c[ni][0] + b0, 0.f);
        Ys[r0*132 + col + 1]     = fmaxf(c[ni][1] + b1, 0.f);
        Ys[(r0+8)*132 + col]     = fmaxf(c[ni][2] + b0, 0.f);
        Ys[(r0+8)*132 + col + 1] = fmaxf(c[ni][3] + b1, 0.f);
    }
    __syncthreads();

    // LN: 8 threads per row, 16 cols each
    {
        int row = tid >> 3;
        int part = tid & 7;
        const float* xr = x + (size_t)(m0 + row)*DIM + part*16;
        const float* yr = Ys + row*132 + part*16;
        float vals[16];
        float sum = 0.f, sq = 0.f;
#pragma unroll
        for (int j = 0; j < 4; ++j) {
            float4 xv = *(const float4*)(xr + j*4);
            float4 yv = *(const float4*)(yr + j*4);
            float v0 = yv.x+xv.x, v1 = yv.y+xv.y, v2 = yv.z+xv.z, v3 = yv.w+xv.w;
            vals[j*4+0]=v0; vals[j*4+1]=v1; vals[j*4+2]=v2; vals[j*4+3]=v3;
            sum += (v0+v1)+(v2+v3);
            sq  += (v0*v0+v1*v1)+(v2*v2+v3*v3);
        }
        sum += __shfl_xor_sync(0xffffffffu, sum, 1);
        sq  += __shfl_xor_sync(0xffffffffu, sq, 1);
        sum += __shfl_xor_sync(0xffffffffu, sum, 2);
        sq  += __shfl_xor_sync(0xffffffffu, sq, 2);
        sum += __shfl_xor_sync(0xffffffffu, sum, 4);
        sq  += __shfl_xor_sync(0xffffffffu, sq, 4);
        float mu   = sum * (1.f/128.f);
        float var  = sq * (1.f/128.f) - mu*mu;
        float rstd = rsqrtf(var + 1e-5f);
        float* op = out + (size_t)(m0 + row)*DIM + part*16;
        const float* gp = gamma + part*16;
        const float* bp = beta + part*16;
#pragma unroll
        for (int j = 0; j < 4; ++j) {
            float4 gv = *(const float4*)(gp + j*4);
            float4 bv = *(const float4*)(bp + j*4);
            float4 o;
            o.x = gv.x*((vals[j*4+0]-mu)*rstd) + bv.x;
            o.y = gv.y*((vals[j*4+1]-mu)*rstd) + bv.y;
            o.z = gv.z*((vals[j*4+2]-mu)*rstd) + bv.z;
            o.w = gv.w*((vals[j*4+3]-mu)*rstd) + bv.w;
            *(float4*)(op + j*4) = o;
        }
    }
}

// ---------------------------------------------------------------------------
extern "C" void kernel_launch(void* const* d_in, const int* in_sizes, int n_in,
                              void* d_out, int out_size)
{
    const float* x    = (const float*)d_in[0];
    const int*   mask = (const int*)d_in[2];
    const float* Wq   = (const float*)d_in[3];
    const float* Wk   = (const float*)d_in[4];
    const float* Wv   = (const float*)d_in[5];
    const float* Wu   = (const float*)d_in[6];
    const float* bu   = (const float*)d_in[7];
    const float* gm   = (const float*)d_in[8];
    const float* bt   = (const float*)d_in[9];
    float* out = (float*)d_out;

    cudaFuncSetAttribute(qkv3_mma, cudaFuncAttributeMaxDynamicSharedMemorySize, GEMM_SMEM);
    cudaFuncSetAttribute(mlp_mma,  cudaFuncAttributeMaxDynamicSharedMemorySize, GEMM_SMEM);
    cudaFuncSetAttribute(attn_mma, cudaFuncAttributeMaxDynamicSharedMemorySize, ATTN_SMEM);

    prep_w<<<160, 256>>>(Wq, Wk, Wv, Wu);
    qkv3_mma<<<MTOT/64, 512, GEMM_SMEM>>>(x);
    attn_mma<<<dim3(SEQ/QT, NBATCH), 256, ATTN_SMEM>>>(mask);
    mlp_mma<<<MTOT/64, 512, GEMM_SMEM>>>(x, bu, gm, bt, out);
}

// round 15
// speedup vs baseline: 1.9972x; 1.0006x over previous
#include <cuda_runtime.h>
#include <cstdint>

#define NBATCH 4
#define SEQ    4096
#define DIM    128
#define MTOT   (NBATCH*SEQ)
#define QT     64
#define KT     192
#define CKA    96

__device__ float g_q[MTOT*DIM];
__device__ float g_k[MTOT*DIM];
__device__ float g_v[MTOT*DIM];
__device__ float g_agg[MTOT*DIM];
__device__ float g_mlpp[MTOT*DIM];          // x @ Wu[0:128] partial
__device__ float g_vsum_p[NBATCH*64*DIM];
__device__ uint32_t g_wh[(3*64+128)*DIM];   // Wq|Wk|Wv|Wu, B-layout [kp][n], fp16x2

// ---------------------------------------------------------------------------
__device__ __forceinline__ uint32_t hpack(float x0, float x1) {
    uint32_t r;
    asm("cvt.rn.f16x2.f32 %0, %1, %2;" : "=r"(r) : "f"(x1), "f"(x0));
    return r;
}
__device__ __forceinline__ float2 hunpack(uint32_t h) {
    float f0, f1;
    asm("{.reg .b16 lo,hi; mov.b32 {lo,hi}, %2; cvt.f32.f16 %0, lo; cvt.f32.f16 %1, hi;}"
        : "=f"(f0), "=f"(f1) : "r"(h));
    return make_float2(f0, f1);
}
__device__ __forceinline__ void hsplit2(float x0, float x1, uint32_t& h, uint32_t& l) {
    h = hpack(x0, x1);
    float2 hf = hunpack(h);
    l = hpack(x0 - hf.x, x1 - hf.y);
}
__device__ __forceinline__ void mma_f16(float* c, const uint32_t* a,
                                        uint32_t b0, uint32_t b1) {
    asm volatile(
        "mma.sync.aligned.m16n8k16.row.col.f32.f16.f16.f32 "
        "{%0,%1,%2,%3}, {%4,%5,%6,%7}, {%8,%9}, {%0,%1,%2,%3};"
        : "+f"(c[0]), "+f"(c[1]), "+f"(c[2]), "+f"(c[3])
        : "r"(a[0]), "r"(a[1]), "r"(a[2]), "r"(a[3]), "r"(b0), "r"(b1));
}

// ---------------------------------------------------------------------------
__global__ __launch_bounds__(256)
void prep_w(const float* __restrict__ Wq, const float* __restrict__ Wk,
            const float* __restrict__ Wv, const float* __restrict__ Wu)
{
    int o = blockIdx.x*256 + threadIdx.x;
    const float* W; int ofs, oo;
    if (o < 8192)        { W = Wq; ofs = 0;        oo = o; }
    else if (o < 16384)  { W = Wk; ofs = 64*128;   oo = o - 8192; }
    else if (o < 24576)  { W = Wv; ofs = 128*128;  oo = o - 16384; }
    else                 { W = Wu; ofs = 192*128;  oo = o - 24576; }
    int kp = oo >> 7, n = oo & 127;
    g_wh[ofs + kp*128 + n] = hpack(W[(size_t)(2*kp)*DIM + n], W[(size_t)(2*kp+1)*DIM + n]);
}

// ---------------------------------------------------------------------------
// GEMM core (BM=64, 512 threads): 64x128 tile, full K=128.
// 16 warps as 4(m) x 4(n); per warp 1 m-frag x 4 n-frags.
// ---------------------------------------------------------------------------
#define GA_STR 68
#define GB_STR 136
#define GEMM_SMEM ((2*64*GA_STR + 64*GB_STR)*4)   // 69632 B

struct GemmH512 {
    uint32_t *Ah, *Al, *Bh;

    __device__ void stage_A(const float* __restrict__ src, int m0, int tid) {
#pragma unroll
        for (int t = 0; t < 8; ++t) {
            int idx = tid + t*512;
            int row = idx >> 6, kp = idx & 63;
            float2 v = *(const float2*)(src + (size_t)(m0+row)*DIM + 2*kp);
            uint32_t h, l; hsplit2(v.x, v.y, h, l);
            Ah[row*GA_STR + kp] = h; Al[row*GA_STR + kp] = l;
        }
    }
    __device__ void stage_A1(const float* __restrict__ src, int m0, int tid) {
#pragma unroll
        for (int t = 0; t < 8; ++t) {
            int idx = tid + t*512;
            int row = idx >> 6, kp = idx & 63;
            float2 v = *(const float2*)(src + (size_t)(m0+row)*DIM + 2*kp);
            Ah[row*GA_STR + kp] = hpack(v.x, v.y);
        }
    }
    __device__ void stage_B(int kpo, int tid) {
#pragma unroll
        for (int t = 0; t < 4; ++t) {
            int idx = tid + t*512;
            int kp = idx >> 5, c4 = (idx & 31)*4;
            *(uint4*)&Bh[kp*GB_STR + c4] = *(const uint4*)&g_wh[(size_t)(kpo+kp)*128 + c4];
        }
    }
    __device__ void run(float c[4][4], int tid, bool lo_term) {
        const int lane = tid & 31, wid = tid >> 5;
        const int grp = lane >> 2, qd = lane & 3;
        const int wm = (wid & 3) * 16, wn = (wid >> 2) * 32;
#pragma unroll
        for (int t = 0; t < 8; ++t) {
            int kp0 = 8*t;
            uint32_t ah[4], al[4];
            int r = (wm + grp)*GA_STR;
            ah[0] = Ah[r + kp0+qd];   ah[1] = Ah[r + 8*GA_STR + kp0+qd];
            ah[2] = Ah[r + kp0+qd+4]; ah[3] = Ah[r + 8*GA_STR + kp0+qd+4];
            if (lo_term) {
                al[0] = Al[r + kp0+qd];   al[1] = Al[r + 8*GA_STR + kp0+qd];
                al[2] = Al[r + kp0+qd+4]; al[3] = Al[r + 8*GA_STR + kp0+qd+4];
            }
#pragma unroll
            for (int ni = 0; ni < 4; ++ni) {
                int col = wn + ni*8 + grp;
                uint32_t bh0 = Bh[(kp0+qd)*GB_STR + col];
                uint32_t bh1 = Bh[(kp0+qd+4)*GB_STR + col];
                mma_f16(c[ni], ah, bh0, bh1);
                if (lo_term) mma_f16(c[ni], al, bh0, bh1);
            }
        }
    }
};

// ---------------------------------------------------------------------------
// QKV+MLPx fused (BM=64, 512 thr): stage x once, loop Wq/Wk/Wu0/Wv.
// Q,K,MLPx 2-term; V single-term; V phase also emits column sums.
// ---------------------------------------------------------------------------
__global__ __launch_bounds__(512, 2)
void qkv4_mma(const float* __restrict__ x)
{
    extern __shared__ uint32_t smu[];
    GemmH512 g;
    g.Ah = smu;               g.Al = g.Ah + 64*GA_STR;
    g.Bh = g.Al + 64*GA_STR;

    const int tid = threadIdx.x;
    const int m0 = blockIdx.x * 64;

    const int lane = tid & 31, wid = tid >> 5;
    const int grp = lane >> 2, qd = lane & 3;
    const int wm = (wid & 3) * 16, wn = (wid >> 2) * 32;

    g.stage_A(x, m0, tid);

    const int kpo_tab[4] = {0, 64, 192, 128};   // Wq, Wk, Wu0, Wv (V last)
    float c[4][4];
#pragma unroll 1
    for (int w = 0; w < 4; ++w) {
        if (w > 0) __syncthreads();
        g.stage_B(kpo_tab[w], tid);
        __syncthreads();
#pragma unroll
        for (int ni = 0; ni < 4; ++ni)
#pragma unroll
            for (int e = 0; e < 4; ++e) c[ni][e] = 0.f;
        g.run(c, tid, w < 3);     // V projection single-term

        float* outp = (w == 0) ? g_q : (w == 1) ? g_k : (w == 2) ? g_mlpp : g_v;
#pragma unroll
        for (int ni = 0; ni < 4; ++ni) {
            size_t r0 = (size_t)(m0 + wm + grp);
            int col = wn + ni*8 + 2*qd;
            *(float2*)(outp + r0*DIM + col)     = make_float2(c[ni][0], c[ni][1]);
            *(float2*)(outp + (r0+8)*DIM + col) = make_float2(c[ni][2], c[ni][3]);
        }
    }

    // ---- V column partial sums (c holds the V tile) ----
    __syncthreads();
    float* Ys = (float*)smu;                 // [64][132]
#pragma unroll
    for (int ni = 0; ni < 4; ++ni) {
        int r0 = wm + grp;
        int col = wn + ni*8 + 2*qd;
        Ys[r0*132 + col]         = c[ni][0];
        Ys[r0*132 + col + 1]     = c[ni][1];
        Ys[(r0+8)*132 + col]     = c[ni][2];
        Ys[(r0+8)*132 + col + 1] = c[ni][3];
    }
    __syncthreads();
    {
        int col = tid & 127, q = tid >> 7;   // q: 0..3
        float s = 0.f;
#pragma unroll
        for (int r = 0; r < 16; r += 4) {
            s += Ys[(q*16 + r+0)*132 + col];
            s += Ys[(q*16 + r+1)*132 + col];
            s += Ys[(q*16 + r+2)*132 + col];
            s += Ys[(q*16 + r+3)*132 + col];
        }
        float* ps2 = Ys + 64*132;
        ps2[q*128 + col] = s;
        __syncthreads();
        if (tid < 128) {
            int b = m0 >> 12;
            int t = (m0 >> 6) & 63;
            g_vsum_p[(b*64 + t)*128 + tid] =
                (ps2[tid] + ps2[128 + tid]) + (ps2[256 + tid] + ps2[384 + tid]);
        }
    }
}

// ---------------------------------------------------------------------------
// Attention (unchanged from round 14).
// ---------------------------------------------------------------------------
#define AQ_STR 68
#define AK_STR 68
#define AV_STR 136
#define AP_STR 196
#define PH_STR 100
#define Q_WORDS  (QT*AQ_STR)
#define KV_WORDS (CKA*AK_STR)
#define P_WORDS  (QT*AP_STR)
#define ATTN_SMEM ((2*Q_WORDS + KV_WORDS + P_WORDS)*4 + (KT+QT)*4 + 128*4)

__global__ __launch_bounds__(256, 2)
void attn_mma(const int* __restrict__ mask)
{
    extern __shared__ uint32_t smu[];
    uint32_t* Qh = smu;
    uint32_t* Ql = Qh + Q_WORDS;
    uint32_t* KV = Ql + Q_WORDS;
    float*    Ps = (float*)(KV + KV_WORDS);
    int*     msk = (int*)(Ps + P_WORDS);
    int*     qmk = msk + KT;
    float* vsum_s = (float*)(qmk + QT);   // [128]

    uint32_t* Ks = KV;
    uint32_t* Vs = KV;
    uint32_t* Ph = Qh;

    const int tid = threadIdx.x;
    const int b  = blockIdx.y;
    const int q0 = blockIdx.x * QT;
    const int kbase = q0 - 64;

    if (tid < KT) {
        int j = kbase + tid;
        msk[tid] = (j >= 0 && j < SEQ) ? mask[b*SEQ + j] : 0;
    }
    if (tid < QT) qmk[tid] = mask[b*SEQ + q0 + tid];

#pragma unroll
    for (int t = 0; t < 16; ++t) {
        int idx = tid + t*256;
        int row = idx >> 6, kp = idx & 63;
        float2 v = *(const float2*)(g_q + ((size_t)b*SEQ + q0 + row)*DIM + 2*kp);
        uint32_t h, l; hsplit2(v.x, v.y, h, l);
        Qh[row*AQ_STR + kp] = h; Ql[row*AQ_STR + kp] = l;
    }
#pragma unroll
    for (int t = 0; t < 24; ++t) {
        int idx = tid + t*256;
        int row = idx >> 6, kp = idx & 63;
        int j = kbase + row;
        uint32_t h = 0;
        if (j >= 0 && j < SEQ) {
            float2 v = *(const float2*)(g_k + ((size_t)b*SEQ + j)*DIM + 2*kp);
            h = hpack(v.x, v.y);
        }
        Ks[row*AK_STR + kp] = h;
    }
    __syncthreads();

    int need_vsum = __syncthreads_or((tid < QT) ? (qmk[tid] == 0) : 0);
    if (need_vsum && tid < 128) {
        float s = 0.f;
#pragma unroll 4
        for (int t = 0; t < 64; ++t) s += g_vsum_p[(b*64 + t)*128 + tid];
        vsum_s[tid] = s * (1.f/(float)SEQ);
    }

    const int lane = tid & 31, wid = tid >> 5;
    const int grp = lane >> 2, qd = lane & 3;
    const float scale = 0.08838834764831845f;

    {
        const int wm = (wid & 3) * 16;
        const int wn = (wid >> 2) * 48;
#pragma unroll 1
        for (int c = 0; c < 2; ++c) {
            float cs[6][4];
#pragma unroll
            for (int ni = 0; ni < 6; ++ni)
#pragma unroll
                for (int e = 0; e < 4; ++e) cs[ni][e] = 0.f;

            int cb = c*CKA + wn;
            bool skip = (cb + 47 < wm) || (cb > wm + 143);
            if (!skip) {
#pragma unroll
                for (int t = 0; t < 8; ++t) {
                    int kp0 = 8*t;
                    uint32_t ah[4], al[4];
                    int r = (wm + grp)*AQ_STR;
                    ah[0] = Qh[r + kp0+qd];   ah[1] = Qh[r + 8*AQ_STR + kp0+qd];
                    ah[2] = Qh[r + kp0+qd+4]; ah[3] = Qh[r + 8*AQ_STR + kp0+qd+4];
                    al[0] = Ql[r + kp0+qd];   al[1] = Ql[r + 8*AQ_STR + kp0+qd];
                    al[2] = Ql[r + kp0+qd+4]; al[3] = Ql[r + 8*AQ_STR + kp0+qd+4];
#pragma unroll
                    for (int ni = 0; ni < 6; ++ni) {
                        int col = (wn + ni*8 + grp)*AK_STR;
                        uint32_t bh0 = Ks[col + kp0+qd];
                        uint32_t bh1 = Ks[col + kp0+qd+4];
                        mma_f16(cs[ni], ah, bh0, bh1);
                        mma_f16(cs[ni], al, bh0, bh1);
                    }
                }
            }
#pragma unroll
            for (int ni = 0; ni < 6; ++ni) {
#pragma unroll
                for (int e = 0; e < 4; ++e) {
                    int qi = wm + grp + (e >> 1)*8;
                    int jg = cb + ni*8 + 2*qd + (e & 1);
                    bool valid = msk[jg] && (jg >= qi) && (jg <= qi + 128);
                    Ps[qi*AP_STR + jg] = valid ? cs[ni][e]*scale : -1e9f;
                }
            }
            __syncthreads();
            if (c == 0) {
#pragma unroll
                for (int t = 0; t < 24; ++t) {
                    int idx = tid + t*256;
                    int row = idx >> 6, kp = idx & 63;
                    int j = kbase + CKA + row;
                    uint32_t h = 0;
                    if (j >= 0 && j < SEQ) {
                        float2 v = *(const float2*)(g_k + ((size_t)b*SEQ + j)*DIM + 2*kp);
                        h = hpack(v.x, v.y);
                    }
                    Ks[row*AK_STR + kp] = h;
                }
                __syncthreads();
            }
        }
    }

#pragma unroll
    for (int t = 0; t < 6; ++t) {
        int idx = tid + t*256;
        int kp = idx >> 5, c4 = (idx & 31)*4;
        int j0 = kbase + 2*kp, j1 = j0 + 1;
        float4 v0 = make_float4(0,0,0,0), v1 = make_float4(0,0,0,0);
        if (j0 >= 0 && j0 < SEQ) v0 = *(const float4*)(g_v + ((size_t)b*SEQ + j0)*DIM + c4);
        if (j1 >= 0 && j1 < SEQ) v1 = *(const float4*)(g_v + ((size_t)b*SEQ + j1)*DIM + c4);
        *(uint4*)&Vs[kp*AV_STR + c4] = make_uint4(
            hpack(v0.x, v1.x), hpack(v0.y, v1.y), hpack(v0.z, v1.z), hpack(v0.w, v1.w));
    }

    {
        int qi = tid >> 2, lg = tid & 3;
        float mx = -3.4e38f;
        for (int j = lg; j < KT; j += 4) mx = fmaxf(mx, Ps[qi*AP_STR + j]);
        mx = fmaxf(mx, __shfl_xor_sync(0xffffffffu, mx, 1));
        mx = fmaxf(mx, __shfl_xor_sync(0xffffffffu, mx, 2));
        float s = 0.f;
        for (int j = lg; j < KT; j += 4) {
            float e = __expf(Ps[qi*AP_STR + j] - mx);
            Ps[qi*AP_STR + j] = e;
            s += e;
        }
        s += __shfl_xor_sync(0xffffffffu, s, 1);
        s += __shfl_xor_sync(0xffffffffu, s, 2);
        float inv = 1.f / s;
        for (int kp = lg; kp < CKA; kp += 4) {
            float e0 = Ps[qi*AP_STR + 2*kp];
            float e1 = Ps[qi*AP_STR + 2*kp + 1];
            Ph[qi*PH_STR + kp] = hpack(e0*inv, e1*inv);
        }
    }
    __syncthreads();

    {
        const int wm = (wid & 1) * 32;
        const int wn = (wid >> 1) * 32;
        float co[2][4][4];
#pragma unroll
        for (int mi = 0; mi < 2; ++mi)
#pragma unroll
            for (int ni = 0; ni < 4; ++ni)
#pragma unroll
                for (int e = 0; e < 4; ++e) co[mi][ni][e] = 0.f;

#pragma unroll 1
        for (int c = 0; c < 2; ++c) {
#pragma unroll
            for (int t = 0; t < 6; ++t) {
                int ck = c*48 + t*8;
                uint32_t ah[2][4];
#pragma unroll
                for (int mi = 0; mi < 2; ++mi) {
                    int r = (wm + mi*16 + grp)*PH_STR + ck + qd;
                    ah[mi][0] = Ph[r];
                    ah[mi][1] = Ph[r + 8*PH_STR];
                    ah[mi][2] = Ph[r + 4];
                    ah[mi][3] = Ph[r + 8*PH_STR + 4];
                }
#pragma unroll
                for (int ni = 0; ni < 4; ++ni) {
                    int col = wn + ni*8 + grp;
                    uint32_t bh0 = Vs[(t*8+qd)*AV_STR + col];
                    uint32_t bh1 = Vs[(t*8+qd+4)*AV_STR + col];
#pragma unroll
                    for (int mi = 0; mi < 2; ++mi)
                        mma_f16(co[mi][ni], ah[mi], bh0, bh1);
                }
            }
            if (c == 0) {
                __syncthreads();
#pragma unroll
                for (int t = 0; t < 6; ++t) {
                    int idx = tid + t*256;
                    int kp = idx >> 5, c4 = (idx & 31)*4;
                    int j0 = kbase + CKA + 2*kp, j1 = j0 + 1;
                    float4 v0 = make_float4(0,0,0,0), v1 = make_float4(0,0,0,0);
                    if (j0 >= 0 && j0 < SEQ) v0 = *(const float4*)(g_v + ((size_t)b*SEQ + j0)*DIM + c4);
                    if (j1 >= 0 && j1 < SEQ) v1 = *(const float4*)(g_v + ((size_t)b*SEQ + j1)*DIM + c4);
                    *(uint4*)&Vs[kp*AV_STR + c4] = make_uint4(
                        hpack(v0.x, v1.x), hpack(v0.y, v1.y), hpack(v0.z, v1.z), hpack(v0.w, v1.w));
                }
                __syncthreads();
            }
        }

#pragma unroll
        for (int mi = 0; mi < 2; ++mi)
#pragma unroll
            for (int ni = 0; ni < 4; ++ni) {
                int r0 = wm + mi*16 + grp;
                int col = wn + ni*8 + 2*qd;
#pragma unroll
                for (int half = 0; half < 2; ++half) {
                    int qi = r0 + half*8;
                    float v0 = co[mi][ni][half*2], v1 = co[mi][ni][half*2+1];
                    if (!qmk[qi]) {
                        v0 = vsum_s[col];
                        v1 = vsum_s[col + 1];
                    }
                    size_t row = (size_t)b*SEQ + q0 + qi;
                    *(float2*)(g_agg + row*DIM + col) = make_float2(v0, v1);
                }
            }
    }
}

// ---------------------------------------------------------------------------
// MLP tail: single phase (agg @ Wu1, 1-term) + mlpp partial + bias/ReLU/
// residual/LN.
// ---------------------------------------------------------------------------
__global__ __launch_bounds__(512, 2)
void mlp_mma(const float* __restrict__ x, const float* __restrict__ bu,
             const float* __restrict__ gamma, const float* __restrict__ beta,
             float* __restrict__ out)
{
    extern __shared__ uint32_t smu[];
    GemmH512 g;
    g.Ah = smu;               g.Al = g.Ah + 64*GA_STR;
    g.Bh = g.Al + 64*GA_STR;

    const int tid = threadIdx.x;
    const int m0 = blockIdx.x * 64;

    float c[4][4];
#pragma unroll
    for (int ni = 0; ni < 4; ++ni)
#pragma unroll
        for (int e = 0; e < 4; ++e) c[ni][e] = 0.f;

    g.stage_A1((const float*)g_agg, m0, tid);
    g.stage_B(256, tid);                 // Wu second half (agg)
    __syncthreads();
    g.run(c, tid, false);
    __syncthreads();

    float* Ys = (float*)smu;  // [64][132]
    const int lane = tid & 31, wid = tid >> 5;
    const int grp = lane >> 2, qd = lane & 3;
    const int wm = (wid & 3) * 16, wn = (wid >> 2) * 32;
#pragma unroll
    for (int ni = 0; ni < 4; ++ni) {
        int r0 = wm + grp;
        int col = wn + ni*8 + 2*qd;
        float b0 = __ldg(bu + col), b1 = __ldg(bu + col + 1);
        float2 p0 = *(const float2*)(g_mlpp + (size_t)(m0 + r0)*DIM + col);
        float2 p1 = *(const float2*)(g_mlpp + (size_t)(m0 + r0 + 8)*DIM + col);
        Ys[r0*132 + col]         = fmaxf(c[ni][0] + p0.x + b0, 0.f);
        Ys[r0*132 + col + 1]     = fmaxf(c[ni][1] + p0.y + b1, 0.f);
        Ys[(r0+8)*132 + col]     = fmaxf(c[ni][2] + p1.x + b0, 0.f);
        Ys[(r0+8)*132 + col + 1] = fmaxf(c[ni][3] + p1.y + b1, 0.f);
    }
    __syncthreads();

    // LN: 8 threads per row, 16 cols each
    {
        int row = tid >> 3;
        int part = tid & 7;
        const float* xr = x + (size_t)(m0 + row)*DIM + part*16;
        const float* yr = Ys + row*132 + part*16;
        float vals[16];
        float sum = 0.f, sq = 0.f;
#pragma unroll
        for (int j = 0; j < 4; ++j) {
            float4 xv = *(const float4*)(xr + j*4);
            float4 yv = *(const float4*)(yr + j*4);
            float v0 = yv.x+xv.x, v1 = yv.y+xv.y, v2 = yv.z+xv.z, v3 = yv.w+xv.w;
            vals[j*4+0]=v0; vals[j*4+1]=v1; vals[j*4+2]=v2; vals[j*4+3]=v3;
            sum += (v0+v1)+(v2+v3);
            sq  += (v0*v0+v1*v1)+(v2*v2+v3*v3);
        }
        sum += __shfl_xor_sync(0xffffffffu, sum, 1);
        sq  += __shfl_xor_sync(0xffffffffu, sq, 1);
        sum += __shfl_xor_sync(0xffffffffu, sum, 2);
        sq  += __shfl_xor_sync(0xffffffffu, sq, 2);
        sum += __shfl_xor_sync(0xffffffffu, sum, 4);
        sq  += __shfl_xor_sync(0xffffffffu, sq, 4);
        float mu   = sum * (1.f/128.f);
        float var  = sq * (1.f/128.f) - mu*mu;
        float rstd = rsqrtf(var + 1e-5f);
        float* op = out + (size_t)(m0 + row)*DIM + part*16;
        const float* gp = gamma + part*16;
        const float* bp = beta + part*16;
#pragma unroll
        for (int j = 0; j < 4; ++j) {
            float4 gv = *(const float4*)(gp + j*4);
            float4 bv = *(const float4*)(bp + j*4);
            float4 o;
            o.x = gv.x*((vals[j*4+0]-mu)*rstd) + bv.x;
            o.y = gv.y*((vals[j*4+1]-mu)*rstd) + bv.y;
            o.z = gv.z*((vals[j*4+2]-mu)*rstd) + bv.z;
            o.w = gv.w*((vals[j*4+3]-mu)*rstd) + bv.w;
            *(float4*)(op + j*4) = o;
        }
    }
}

// ---------------------------------------------------------------------------
extern "C" void kernel_launch(void* const* d_in, const int* in_sizes, int n_in,
                              void* d_out, int out_size)
{
    const float* x    = (const float*)d_in[0];
    const int*   mask = (const int*)d_in[2];
    const float* Wq   = (const float*)d_in[3];
    const float* Wk   = (const float*)d_in[4];
    const float* Wv   = (const float*)d_in[5];
    const float* Wu   = (const float*)d_in[6];
    const float* bu   = (const float*)d_in[7];
    const float* gm   = (const float*)d_in[8];
    const float* bt   = (const float*)d_in[9];
    float* out = (float*)d_out;

    cudaFuncSetAttribute(qkv4_mma, cudaFuncAttributeMaxDynamicSharedMemorySize, GEMM_SMEM);
    cudaFuncSetAttribute(mlp_mma,  cudaFuncAttributeMaxDynamicSharedMemorySize, GEMM_SMEM);
    cudaFuncSetAttribute(attn_mma, cudaFuncAttributeMaxDynamicSharedMemorySize, ATTN_SMEM);

    prep_w<<<160, 256>>>(Wq, Wk, Wv, Wu);
    qkv4_mma<<<MTOT/64, 512, GEMM_SMEM>>>(x);
    attn_mma<<<dim3(SEQ/QT, NBATCH), 256, ATTN_SMEM>>>(mask);
    mlp_mma<<<MTOT/64, 512, GEMM_SMEM>>>(x, bu, gm, bt, out);
}

// round 16
// speedup vs baseline: 2.0072x; 1.0050x over previous
#include <cuda_runtime.h>
#include <cstdint>

#define NBATCH 4
#define SEQ    4096
#define DIM    128
#define MTOT   (NBATCH*SEQ)
#define QT     64
#define KT     192
#define CKA    96

__device__ float g_q[MTOT*DIM];
__device__ float g_k[MTOT*DIM];
__device__ float g_v[MTOT*DIM];
__device__ float g_mlpp[MTOT*DIM];          // x @ Wu[0:128] partial
__device__ float g_vsum_p[NBATCH*64*DIM];
__device__ uint32_t g_wh[(3*64+128)*DIM];   // Wq|Wk|Wv|Wu, B-layout [kp][n], fp16x2

// ---------------------------------------------------------------------------
__device__ __forceinline__ uint32_t hpack(float x0, float x1) {
    uint32_t r;
    asm("cvt.rn.f16x2.f32 %0, %1, %2;" : "=r"(r) : "f"(x1), "f"(x0));
    return r;
}
__device__ __forceinline__ float2 hunpack(uint32_t h) {
    float f0, f1;
    asm("{.reg .b16 lo,hi; mov.b32 {lo,hi}, %2; cvt.f32.f16 %0, lo; cvt.f32.f16 %1, hi;}"
        : "=f"(f0), "=f"(f1) : "r"(h));
    return make_float2(f0, f1);
}
__device__ __forceinline__ void hsplit2(float x0, float x1, uint32_t& h, uint32_t& l) {
    h = hpack(x0, x1);
    float2 hf = hunpack(h);
    l = hpack(x0 - hf.x, x1 - hf.y);
}
__device__ __forceinline__ void mma_f16(float* c, const uint32_t* a,
                                        uint32_t b0, uint32_t b1) {
    asm volatile(
        "mma.sync.aligned.m16n8k16.row.col.f32.f16.f16.f32 "
        "{%0,%1,%2,%3}, {%4,%5,%6,%7}, {%8,%9}, {%0,%1,%2,%3};"
        : "+f"(c[0]), "+f"(c[1]), "+f"(c[2]), "+f"(c[3])
        : "r"(a[0]), "r"(a[1]), "r"(a[2]), "r"(a[3]), "r"(b0), "r"(b1));
}

// ---------------------------------------------------------------------------
__global__ __launch_bounds__(256)
void prep_w(const float* __restrict__ Wq, const float* __restrict__ Wk,
            const float* __restrict__ Wv, const float* __restrict__ Wu)
{
    int o = blockIdx.x*256 + threadIdx.x;
    const float* W; int ofs, oo;
    if (o < 8192)        { W = Wq; ofs = 0;        oo = o; }
    else if (o < 16384)  { W = Wk; ofs = 64*128;   oo = o - 8192; }
    else if (o < 24576)  { W = Wv; ofs = 128*128;  oo = o - 16384; }
    else                 { W = Wu; ofs = 192*128;  oo = o - 24576; }
    int kp = oo >> 7, n = oo & 127;
    g_wh[ofs + kp*128 + n] = hpack(W[(size_t)(2*kp)*DIM + n], W[(size_t)(2*kp+1)*DIM + n]);
}

// ---------------------------------------------------------------------------
// GEMM core (BM=64, 512 threads): 64x128 tile, full K=128.
// ---------------------------------------------------------------------------
#define GA_STR 68
#define GB_STR 136
#define GEMM_SMEM ((2*64*GA_STR + 64*GB_STR)*4)   // 69632 B

struct GemmH512 {
    uint32_t *Ah, *Al, *Bh;

    __device__ void stage_A(const float* __restrict__ src, int m0, int tid) {
#pragma unroll
        for (int t = 0; t < 8; ++t) {
            int idx = tid + t*512;
            int row = idx >> 6, kp = idx & 63;
            float2 v = *(const float2*)(src + (size_t)(m0+row)*DIM + 2*kp);
            uint32_t h, l; hsplit2(v.x, v.y, h, l);
            Ah[row*GA_STR + kp] = h; Al[row*GA_STR + kp] = l;
        }
    }
    __device__ void stage_B(int kpo, int tid) {
#pragma unroll
        for (int t = 0; t < 4; ++t) {
            int idx = tid + t*512;
            int kp = idx >> 5, c4 = (idx & 31)*4;
            *(uint4*)&Bh[kp*GB_STR + c4] = *(const uint4*)&g_wh[(size_t)(kpo+kp)*128 + c4];
        }
    }
    __device__ void run(float c[4][4], int tid, bool lo_term) {
        const int lane = tid & 31, wid = tid >> 5;
        const int grp = lane >> 2, qd = lane & 3;
        const int wm = (wid & 3) * 16, wn = (wid >> 2) * 32;
#pragma unroll
        for (int t = 0; t < 8; ++t) {
            int kp0 = 8*t;
            uint32_t ah[4], al[4];
            int r = (wm + grp)*GA_STR;
            ah[0] = Ah[r + kp0+qd];   ah[1] = Ah[r + 8*GA_STR + kp0+qd];
            ah[2] = Ah[r + kp0+qd+4]; ah[3] = Ah[r + 8*GA_STR + kp0+qd+4];
            if (lo_term) {
                al[0] = Al[r + kp0+qd];   al[1] = Al[r + 8*GA_STR + kp0+qd];
                al[2] = Al[r + kp0+qd+4]; al[3] = Al[r + 8*GA_STR + kp0+qd+4];
            }
#pragma unroll
            for (int ni = 0; ni < 4; ++ni) {
                int col = wn + ni*8 + grp;
                uint32_t bh0 = Bh[(kp0+qd)*GB_STR + col];
                uint32_t bh1 = Bh[(kp0+qd+4)*GB_STR + col];
                mma_f16(c[ni], ah, bh0, bh1);
                if (lo_term) mma_f16(c[ni], al, bh0, bh1);
            }
        }
    }
};

// ---------------------------------------------------------------------------
// QKV+MLPx fused (BM=64, 512 thr): stage x once, loop Wq/Wk/Wu0/Wv.
// ---------------------------------------------------------------------------
__global__ __launch_bounds__(512, 2)
void qkv4_mma(const float* __restrict__ x)
{
    extern __shared__ uint32_t smu[];
    GemmH512 g;
    g.Ah = smu;               g.Al = g.Ah + 64*GA_STR;
    g.Bh = g.Al + 64*GA_STR;

    const int tid = threadIdx.x;
    const int m0 = blockIdx.x * 64;

    const int lane = tid & 31, wid = tid >> 5;
    const int grp = lane >> 2, qd = lane & 3;
    const int wm = (wid & 3) * 16, wn = (wid >> 2) * 32;

    g.stage_A(x, m0, tid);

    const int kpo_tab[4] = {0, 64, 192, 128};   // Wq, Wk, Wu0, Wv (V last)
    float c[4][4];
#pragma unroll 1
    for (int w = 0; w < 4; ++w) {
        if (w > 0) __syncthreads();
        g.stage_B(kpo_tab[w], tid);
        __syncthreads();
#pragma unroll
        for (int ni = 0; ni < 4; ++ni)
#pragma unroll
            for (int e = 0; e < 4; ++e) c[ni][e] = 0.f;
        g.run(c, tid, w < 3);     // V projection single-term

        float* outp = (w == 0) ? g_q : (w == 1) ? g_k : (w == 2) ? g_mlpp : g_v;
#pragma unroll
        for (int ni = 0; ni < 4; ++ni) {
            size_t r0 = (size_t)(m0 + wm + grp);
            int col = wn + ni*8 + 2*qd;
            *(float2*)(outp + r0*DIM + col)     = make_float2(c[ni][0], c[ni][1]);
            *(float2*)(outp + (r0+8)*DIM + col) = make_float2(c[ni][2], c[ni][3]);
        }
    }

    // ---- V column partial sums (c holds the V tile) ----
    __syncthreads();
    float* Ys = (float*)smu;                 // [64][132]
#pragma unroll
    for (int ni = 0; ni < 4; ++ni) {
        int r0 = wm + grp;
        int col = wn + ni*8 + 2*qd;
        Ys[r0*132 + col]         = c[ni][0];
        Ys[r0*132 + col + 1]     = c[ni][1];
        Ys[(r0+8)*132 + col]     = c[ni][2];
        Ys[(r0+8)*132 + col + 1] = c[ni][3];
    }
    __syncthreads();
    {
        int col = tid & 127, q = tid >> 7;   // q: 0..3
        float s = 0.f;
#pragma unroll
        for (int r = 0; r < 16; r += 4) {
            s += Ys[(q*16 + r+0)*132 + col];
            s += Ys[(q*16 + r+1)*132 + col];
            s += Ys[(q*16 + r+2)*132 + col];
            s += Ys[(q*16 + r+3)*132 + col];
        }
        float* ps2 = Ys + 64*132;
        ps2[q*128 + col] = s;
        __syncthreads();
        if (tid < 128) {
            int b = m0 >> 12;
            int t = (m0 >> 6) & 63;
            g_vsum_p[(b*64 + t)*128 + tid] =
                (ps2[tid] + ps2[128 + tid]) + (ps2[256 + tid] + ps2[384 + tid]);
        }
    }
}

// ---------------------------------------------------------------------------
// Attention + fused MLP tail + LN. 64-query tile, 256 threads.
// ---------------------------------------------------------------------------
#define AQ_STR 68
#define AK_STR 68
#define AV_STR 136
#define AP_STR 196
#define PH_STR 100
#define Q_WORDS  (QT*AQ_STR)        // 4352 per array
#define KV_WORDS (CKA*AK_STR)       // 6528
#define P_WORDS  (QT*AP_STR)        // 12544
#define ATTN_SMEM ((2*Q_WORDS + KV_WORDS + P_WORDS)*4 + (KT+QT)*4 + 128*4)

__global__ __launch_bounds__(256, 2)
void attn_mma(const int* __restrict__ mask, const float* __restrict__ x,
              const float* __restrict__ bu, const float* __restrict__ gamma,
              const float* __restrict__ beta, float* __restrict__ out)
{
    extern __shared__ uint32_t smu[];
    uint32_t* Qh = smu;
    uint32_t* Ql = Qh + Q_WORDS;
    uint32_t* KV = Ql + Q_WORDS;
    float*    Ps = (float*)(KV + KV_WORDS);
    int*     msk = (int*)(Ps + P_WORDS);
    int*     qmk = msk + KT;
    float* vsum_s = (float*)(qmk + QT);   // [128]

    uint32_t* Ks = KV;
    uint32_t* Vs = KV;
    uint32_t* Ph = Qh;                    // packed fp16 P, overlays Q
    uint32_t* Ag = KV;                    // packed fp16 agg [64][68], overlays K/V
    uint32_t* Wu1 = (uint32_t*)Ps;        // Wu second half [64][136], overlays Ps
    float*    Yf = (float*)Qh;            // fused Y [64][132], overlays Q/P

    const int tid = threadIdx.x;
    const int b  = blockIdx.y;
    const int q0 = blockIdx.x * QT;
    const int kbase = q0 - 64;

    if (tid < KT) {
        int j = kbase + tid;
        msk[tid] = (j >= 0 && j < SEQ) ? mask[b*SEQ + j] : 0;
    }
    if (tid < QT) qmk[tid] = mask[b*SEQ + q0 + tid];

#pragma unroll
    for (int t = 0; t < 16; ++t) {
        int idx = tid + t*256;
        int row = idx >> 6, kp = idx & 63;
        float2 v = *(const float2*)(g_q + ((size_t)b*SEQ + q0 + row)*DIM + 2*kp);
        uint32_t h, l; hsplit2(v.x, v.y, h, l);
        Qh[row*AQ_STR + kp] = h; Ql[row*AQ_STR + kp] = l;
    }
#pragma unroll
    for (int t = 0; t < 24; ++t) {
        int idx = tid + t*256;
        int row = idx >> 6, kp = idx & 63;
        int j = kbase + row;
        uint32_t h = 0;
        if (j >= 0 && j < SEQ) {
            float2 v = *(const float2*)(g_k + ((size_t)b*SEQ + j)*DIM + 2*kp);
            h = hpack(v.x, v.y);
        }
        Ks[row*AK_STR + kp] = h;
    }
    __syncthreads();

    int need_vsum = __syncthreads_or((tid < QT) ? (qmk[tid] == 0) : 0);
    if (need_vsum && tid < 128) {
        float s = 0.f;
#pragma unroll 4
        for (int t = 0; t < 64; ++t) s += g_vsum_p[(b*64 + t)*128 + tid];
        vsum_s[tid] = s * (1.f/(float)SEQ);
    }

    const int lane = tid & 31, wid = tid >> 5;
    const int grp = lane >> 2, qd = lane & 3;
    const float scale = 0.08838834764831845f;

    // ---- S = Q K^T, 2 chunks of 96 keys; warps 4(m) x 2(n), band skip ----
    {
        const int wm = (wid & 3) * 16;
        const int wn = (wid >> 2) * 48;
#pragma unroll 1
        for (int c = 0; c < 2; ++c) {
            float cs[6][4];
#pragma unroll
            for (int ni = 0; ni < 6; ++ni)
#pragma unroll
                for (int e = 0; e < 4; ++e) cs[ni][e] = 0.f;

            int cb = c*CKA + wn;
            bool skip = (cb + 47 < wm) || (cb > wm + 143);
            if (!skip) {
#pragma unroll
                for (int t = 0; t < 8; ++t) {
                    int kp0 = 8*t;
                    uint32_t ah[4], al[4];
                    int r = (wm + grp)*AQ_STR;
                    ah[0] = Qh[r + kp0+qd];   ah[1] = Qh[r + 8*AQ_STR + kp0+qd];
                    ah[2] = Qh[r + kp0+qd+4]; ah[3] = Qh[r + 8*AQ_STR + kp0+qd+4];
                    al[0] = Ql[r + kp0+qd];   al[1] = Ql[r + 8*AQ_STR + kp0+qd];
                    al[2] = Ql[r + kp0+qd+4]; al[3] = Ql[r + 8*AQ_STR + kp0+qd+4];
#pragma unroll
                    for (int ni = 0; ni < 6; ++ni) {
                        int col = (wn + ni*8 + grp)*AK_STR;
                        uint32_t bh0 = Ks[col + kp0+qd];
                        uint32_t bh1 = Ks[col + kp0+qd+4];
                        mma_f16(cs[ni], ah, bh0, bh1);
                        mma_f16(cs[ni], al, bh0, bh1);
                    }
                }
            }
#pragma unroll
            for (int ni = 0; ni < 6; ++ni) {
#pragma unroll
                for (int e = 0; e < 4; ++e) {
                    int qi = wm + grp + (e >> 1)*8;
                    int jg = cb + ni*8 + 2*qd + (e & 1);
                    bool valid = msk[jg] && (jg >= qi) && (jg <= qi + 128);
                    Ps[qi*AP_STR + jg] = valid ? cs[ni][e]*scale : -1e9f;
                }
            }
            __syncthreads();
            if (c == 0) {
#pragma unroll
                for (int t = 0; t < 24; ++t) {
                    int idx = tid + t*256;
                    int row = idx >> 6, kp = idx & 63;
                    int j = kbase + CKA + row;
                    uint32_t h = 0;
                    if (j >= 0 && j < SEQ) {
                        float2 v = *(const float2*)(g_k + ((size_t)b*SEQ + j)*DIM + 2*kp);
                        h = hpack(v.x, v.y);
                    }
                    Ks[row*AK_STR + kp] = h;
                }
                __syncthreads();
            }
        }
    }

    // stage V chunk 0
#pragma unroll
    for (int t = 0; t < 6; ++t) {
        int idx = tid + t*256;
        int kp = idx >> 5, c4 = (idx & 31)*4;
        int j0 = kbase + 2*kp, j1 = j0 + 1;
        float4 v0 = make_float4(0,0,0,0), v1 = make_float4(0,0,0,0);
        if (j0 >= 0 && j0 < SEQ) v0 = *(const float4*)(g_v + ((size_t)b*SEQ + j0)*DIM + c4);
        if (j1 >= 0 && j1 < SEQ) v1 = *(const float4*)(g_v + ((size_t)b*SEQ + j1)*DIM + c4);
        *(uint4*)&Vs[kp*AV_STR + c4] = make_uint4(
            hpack(v0.x, v1.x), hpack(v0.y, v1.y), hpack(v0.z, v1.z), hpack(v0.w, v1.w));
    }

    // softmax: 4 threads per row; pack normalized P into fp16 Ph
    {
        int qi = tid >> 2, lg = tid & 3;
        float mx = -3.4e38f;
        for (int j = lg; j < KT; j += 4) mx = fmaxf(mx, Ps[qi*AP_STR + j]);
        mx = fmaxf(mx, __shfl_xor_sync(0xffffffffu, mx, 1));
        mx = fmaxf(mx, __shfl_xor_sync(0xffffffffu, mx, 2));
        float s = 0.f;
        for (int j = lg; j < KT; j += 4) {
            float e = __expf(Ps[qi*AP_STR + j] - mx);
            Ps[qi*AP_STR + j] = e;
            s += e;
        }
        s += __shfl_xor_sync(0xffffffffu, s, 1);
        s += __shfl_xor_sync(0xffffffffu, s, 2);
        float inv = 1.f / s;
        for (int kp = lg; kp < CKA; kp += 4) {
            float e0 = Ps[qi*AP_STR + 2*kp];
            float e1 = Ps[qi*AP_STR + 2*kp + 1];
            Ph[qi*PH_STR + kp] = hpack(e0*inv, e1*inv);
        }
    }
    __syncthreads();

    // ---- agg = P V (single-term), 2 chunks of 48 key-pairs; warps 2m x 4n ----
    const int wm2 = (wid & 1) * 32;
    const int wn2 = (wid >> 1) * 32;
    float co[2][4][4];
#pragma unroll
    for (int mi = 0; mi < 2; ++mi)
#pragma unroll
        for (int ni = 0; ni < 4; ++ni)
#pragma unroll
            for (int e = 0; e < 4; ++e) co[mi][ni][e] = 0.f;

#pragma unroll 1
    for (int c = 0; c < 2; ++c) {
#pragma unroll
        for (int t = 0; t < 6; ++t) {
            int ck = c*48 + t*8;
            uint32_t ah[2][4];
#pragma unroll
            for (int mi = 0; mi < 2; ++mi) {
                int r = (wm2 + mi*16 + grp)*PH_STR + ck + qd;
                ah[mi][0] = Ph[r];
                ah[mi][1] = Ph[r + 8*PH_STR];
                ah[mi][2] = Ph[r + 4];
                ah[mi][3] = Ph[r + 8*PH_STR + 4];
            }
#pragma unroll
            for (int ni = 0; ni < 4; ++ni) {
                int col = wn2 + ni*8 + grp;
                uint32_t bh0 = Vs[(t*8+qd)*AV_STR + col];
                uint32_t bh1 = Vs[(t*8+qd+4)*AV_STR + col];
#pragma unroll
                for (int mi = 0; mi < 2; ++mi)
                    mma_f16(co[mi][ni], ah[mi], bh0, bh1);
            }
        }
        if (c == 0) {
            __syncthreads();
#pragma unroll
            for (int t = 0; t < 6; ++t) {
                int idx = tid + t*256;
                int kp = idx >> 5, c4 = (idx & 31)*4;
                int j0 = kbase + CKA + 2*kp, j1 = j0 + 1;
                float4 v0 = make_float4(0,0,0,0), v1 = make_float4(0,0,0,0);
                if (j0 >= 0 && j0 < SEQ) v0 = *(const float4*)(g_v + ((size_t)b*SEQ + j0)*DIM + c4);
                if (j1 >= 0 && j1 < SEQ) v1 = *(const float4*)(g_v + ((size_t)b*SEQ + j1)*DIM + c4);
                *(uint4*)&Vs[kp*AV_STR + c4] = make_uint4(
                    hpack(v0.x, v1.x), hpack(v0.y, v1.y), hpack(v0.z, v1.z), hpack(v0.w, v1.w));
            }
            __syncthreads();
        }
    }

    // ---- fused MLP tail: agg -> smem fp16, Wu1 staged, GEMM, epilogue ----
    __syncthreads();          // all PV reads of Vs/Ph done

    // pack agg into Ag [64][68] (KV region); masked rows get vsum
#pragma unroll
    for (int mi = 0; mi < 2; ++mi)
#pragma unroll
        for (int ni = 0; ni < 4; ++ni) {
            int kpc = (wn2 >> 1) + ni*4 + qd;     // col pair index
            int colc = wn2 + ni*8 + 2*qd;
#pragma unroll
            for (int half = 0; half < 2; ++half) {
                int qi = wm2 + mi*16 + grp + half*8;
                float v0 = co[mi][ni][half*2], v1 = co[mi][ni][half*2+1];
                if (!qmk[qi]) { v0 = vsum_s[colc]; v1 = vsum_s[colc + 1]; }
                Ag[qi*AQ_STR + kpc] = hpack(v0, v1);
            }
        }
    // stage Wu1 (kp 256..319) into Ps region [64][136]
#pragma unroll
    for (int t = 0; t < 8; ++t) {
        int idx = tid + t*256;
        int kp = idx >> 5, c4 = (idx & 31)*4;
        *(uint4*)&Wu1[kp*GB_STR + c4] = *(const uint4*)&g_wh[(size_t)(256+kp)*128 + c4];
    }
    __syncthreads();

    // GEMM: Y2 = Ag @ Wu1 (single-term), warps 2m x 4n
    float c2[2][4][4];
#pragma unroll
    for (int mi = 0; mi < 2; ++mi)
#pragma unroll
        for (int ni = 0; ni < 4; ++ni)
#pragma unroll
            for (int e = 0; e < 4; ++e) c2[mi][ni][e] = 0.f;
#pragma unroll
    for (int t = 0; t < 8; ++t) {
        int kp0 = 8*t;
        uint32_t ah[2][4];
#pragma unroll
        for (int mi = 0; mi < 2; ++mi) {
            int r = (wm2 + mi*16 + grp)*AQ_STR + kp0 + qd;
            ah[mi][0] = Ag[r];
            ah[mi][1] = Ag[r + 8*AQ_STR];
            ah[mi][2] = Ag[r + 4];
            ah[mi][3] = Ag[r + 8*AQ_STR + 4];
        }
#pragma unroll
        for (int ni = 0; ni < 4; ++ni) {
            int col = wn2 + ni*8 + grp;
            uint32_t bh0 = Wu1[(kp0+qd)*GB_STR + col];
            uint32_t bh1 = Wu1[(kp0+qd+4)*GB_STR + col];
#pragma unroll
            for (int mi = 0; mi < 2; ++mi)
                mma_f16(c2[mi][ni], ah[mi], bh0, bh1);
        }
    }
    __syncthreads();          // Ph/Q region reads long done; now safe to write Yf

    // epilogue: Y = relu(c2 + mlpp + bias), into Yf [64][132]
#pragma unroll
    for (int mi = 0; mi < 2; ++mi)
#pragma unroll
        for (int ni = 0; ni < 4; ++ni) {
            int r0 = wm2 + mi*16 + grp;
            int col = wn2 + ni*8 + 2*qd;
            float b0 = __ldg(bu + col), b1 = __ldg(bu + col + 1);
            size_t gr = (size_t)b*SEQ + q0 + r0;
            float2 p0 = *(const float2*)(g_mlpp + gr*DIM + col);
            float2 p1 = *(const float2*)(g_mlpp + (gr+8)*DIM + col);
            Yf[r0*132 + col]         = fmaxf(c2[mi][ni][0] + p0.x + b0, 0.f);
            Yf[r0*132 + col + 1]     = fmaxf(c2[mi][ni][1] + p0.y + b1, 0.f);
            Yf[(r0+8)*132 + col]     = fmaxf(c2[mi][ni][2] + p1.x + b0, 0.f);
            Yf[(r0+8)*132 + col + 1] = fmaxf(c2[mi][ni][3] + p1.y + b1, 0.f);
        }
    __syncthreads();

    // LN: 4 threads per row, 32 cols each
    {
        int row = tid >> 2;
        int part = tid & 3;
        size_t gr = (size_t)b*SEQ + q0 + row;
        const float* xr = x + gr*DIM + part*32;
        const float* yr = Yf + row*132 + part*32;
        float vals[32];
        float sum = 0.f, sq = 0.f;
#pragma unroll
        for (int j = 0; j < 8; ++j) {
            float4 xv = *(const float4*)(xr + j*4);
            float4 yv = *(const float4*)(yr + j*4);
            float v0 = yv.x+xv.x, v1 = yv.y+xv.y, v2 = yv.z+xv.z, v3 = yv.w+xv.w;
            vals[j*4+0]=v0; vals[j*4+1]=v1; vals[j*4+2]=v2; vals[j*4+3]=v3;
            sum += (v0+v1)+(v2+v3);
            sq  += (v0*v0+v1*v1)+(v2*v2+v3*v3);
        }
        sum += __shfl_xor_sync(0xffffffffu, sum, 1);
        sq  += __shfl_xor_sync(0xffffffffu, sq, 1);
        sum += __shfl_xor_sync(0xffffffffu, sum, 2);
        sq  += __shfl_xor_sync(0xffffffffu, sq, 2);
        float mu   = sum * (1.f/128.f);
        float var  = sq * (1.f/128.f) - mu*mu;
        float rstd = rsqrtf(var + 1e-5f);
        float* op = out + gr*DIM + part*32;
        const float* gp = gamma + part*32;
        const float* bp = beta + part*32;
#pragma unroll
        for (int j = 0; j < 8; ++j) {
            float4 gv = *(const float4*)(gp + j*4);
            float4 bv = *(const float4*)(bp + j*4);
            float4 o;
            o.x = gv.x*((vals[j*4+0]-mu)*rstd) + bv.x;
            o.y = gv.y*((vals[j*4+1]-mu)*rstd) + bv.y;
            o.z = gv.z*((vals[j*4+2]-mu)*rstd) + bv.z;
            o.w = gv.w*((vals[j*4+3]-mu)*rstd) + bv.w;
            *(float4*)(op + j*4) = o;
        }
    }
}

// ---------------------------------------------------------------------------
extern "C" void kernel_launch(void* const* d_in, const int* in_sizes, int n_in,
                              void* d_out, int out_size)
{
    const float* x    = (const float*)d_in[0];
    const int*   mask = (const int*)d_in[2];
    const float* Wq   = (const float*)d_in[3];
    const float* Wk   = (const float*)d_in[4];
    const float* Wv   = (const float*)d_in[5];
    const float* Wu   = (const float*)d_in[6];
    const float* bu   = (const float*)d_in[7];
    const float* gm   = (const float*)d_in[8];
    const float* bt   = (const float*)d_in[9];
    float* out = (float*)d_out;

    cudaFuncSetAttribute(qkv4_mma, cudaFuncAttributeMaxDynamicSharedMemorySize, GEMM_SMEM);
    cudaFuncSetAttribute(attn_mma, cudaFuncAttributeMaxDynamicSharedMemorySize, ATTN_SMEM);

    prep_w<<<160, 256>>>(Wq, Wk, Wv, Wu);
    qkv4_mma<<<MTOT/64, 512, GEMM_SMEM>>>(x);
    attn_mma<<<dim3(SEQ/QT, NBATCH), 256, ATTN_SMEM>>>(mask, x, bu, gm, bt, out);
}